// round 8
// baseline (speedup 1.0000x reference)
#include <cuda_runtime.h>
#include <cuda_fp16.h>
#include <math.h>
#include <stdint.h>

// ---------------- problem constants ----------------
#define BQ 2
#define TQ 1024
#define DQ 768
#define LQ 4
#define HQ 12
#define VQ 50257
#define BT (BQ*TQ)
#define HD 64
#define NT_LM 393   // ceil(VQ/128)

// ---------------- scratch ----------------
__device__ float  g_x   [BT*DQ];          // residual stream (fp32)
__device__ __half g_h   [BT*DQ];          // LN output (fp16)
__device__ __half g_qkv [BT*3*DQ];
__device__ __half g_attn[BT*DQ];
__device__ __half g_ffn [BT*4*DQ];
__device__ float  g_nll [BT];
__device__ float  g_pm  [BT*NT_LM];
__device__ float  g_ps  [BT*NT_LM];
__device__ float  g_logits_fb[102926336];
// fp16, TRANSPOSED ([N][K]) weight copies
__device__ __half g_wqkv[LQ*DQ*3*DQ];
__device__ __half g_wap [LQ*DQ*DQ];
__device__ __half g_wfc [LQ*DQ*4*DQ];
__device__ __half g_wpr [LQ*4*DQ*DQ];
__device__ __half g_tokt[(size_t)VQ*DQ];  // fp16 (already [V][K])

__device__ __forceinline__ void lse_merge(float& m, float& s, float m2, float s2) {
    float M = fmaxf(m, m2);
    s = s * __expf(m - M) + s2 * __expf(m2 - M);
    m = M;
}

// ---------------- fp16 pre-convert (tok_emb) ----------------
__global__ void cvt_kernel(const float4* __restrict__ src, __half* __restrict__ dst, int n4) {
    int i = blockIdx.x * 256 + threadIdx.x;
    if (i >= n4) return;
    float4 v = src[i];
    __half2* d = (__half2*)(dst + (size_t)i * 4);
    d[0] = __floats2half2_rn(v.x, v.y);
    d[1] = __floats2half2_rn(v.z, v.w);
}

// ---------------- fp16 convert + transpose: [L][K][N] -> [L][N][K] ----------------
__global__ __launch_bounds__(256)
void cvtT_kernel(const float* __restrict__ src, __half* __restrict__ dst, int K, int N) {
    __shared__ float t[32][33];
    int l = blockIdx.z;
    int k0 = blockIdx.x * 32, n0 = blockIdx.y * 32;
    const float* S = src + (size_t)l * K * N;
    __half* D = dst + (size_t)l * K * N;
    int tid = threadIdx.x;
    int r = tid >> 3, c4 = (tid & 7) << 2;
    float4 v = *(const float4*)(S + (size_t)(k0 + r) * N + n0 + c4);
    t[r][c4 + 0] = v.x; t[r][c4 + 1] = v.y; t[r][c4 + 2] = v.z; t[r][c4 + 3] = v.w;
    __syncthreads();
    __half2* d = (__half2*)(D + (size_t)(n0 + r) * K + k0 + c4);
    d[0] = __floats2half2_rn(t[c4 + 0][r], t[c4 + 1][r]);
    d[1] = __floats2half2_rn(t[c4 + 2][r], t[c4 + 3][r]);
}

// ---------------- embedding ----------------
__global__ void embed_kernel(const int* __restrict__ ids, const float* __restrict__ tok,
                             const float* __restrict__ pos, float* __restrict__ x) {
    int i = blockIdx.x * 256 + threadIdx.x;
    if (i >= BT * DQ) return;
    int r = i / DQ, d = i - r * DQ;
    x[i] = tok[(size_t)ids[r] * DQ + d] + pos[(r % TQ) * DQ + d];
}

// ---------------- layernorm: fp32 in, fp16 out ----------------
__global__ void ln_kernel(const float* __restrict__ x, const float* __restrict__ w,
                          const float* __restrict__ b, __half* __restrict__ y) {
    int row = blockIdx.x;
    const float* xr = x + (size_t)row * DQ;
    float s = 0.f, q = 0.f;
    for (int i = threadIdx.x; i < DQ; i += 256) { float v = xr[i]; s += v; q += v * v; }
    __shared__ float ss[256], sq[256];
    ss[threadIdx.x] = s; sq[threadIdx.x] = q; __syncthreads();
    for (int o = 128; o > 0; o >>= 1) {
        if (threadIdx.x < o) { ss[threadIdx.x] += ss[threadIdx.x + o]; sq[threadIdx.x] += sq[threadIdx.x + o]; }
        __syncthreads();
    }
    float mean = ss[0] * (1.f / DQ);
    float var  = sq[0] * (1.f / DQ) - mean * mean;
    float inv  = rsqrtf(var + 1e-5f);
    __half* yr = y + (size_t)row * DQ;
    for (int i = threadIdx.x; i < DQ; i += 256)
        yr[i] = __float2half((xr[i] - mean) * inv * w[i] + b[i]);
}

// ---------------- fp16 mma / cp.async / ldmatrix helpers ----------------
__device__ __forceinline__ void mma16(float* c, const uint32_t* a, const uint32_t* b) {
    asm volatile("mma.sync.aligned.m16n8k16.row.col.f32.f16.f16.f32 "
                 "{%0,%1,%2,%3}, {%4,%5,%6,%7}, {%8,%9}, {%0,%1,%2,%3};\n"
                 : "+f"(c[0]), "+f"(c[1]), "+f"(c[2]), "+f"(c[3])
                 : "r"(a[0]), "r"(a[1]), "r"(a[2]), "r"(a[3]), "r"(b[0]), "r"(b[1]));
}
__device__ __forceinline__ void cpa16(uint32_t dst, const void* src) {
    asm volatile("cp.async.cg.shared.global [%0], [%1], 16;\n" :: "r"(dst), "l"(src));
}
__device__ __forceinline__ void cpa16z(uint32_t dst, const void* src, int bytes) {
    asm volatile("cp.async.cg.shared.global [%0], [%1], 16, %2;\n" :: "r"(dst), "l"(src), "r"(bytes));
}
__device__ __forceinline__ void ldsm4(uint32_t* r, uint32_t addr) {
    asm volatile("ldmatrix.sync.aligned.m8n8.x4.shared.b16 {%0,%1,%2,%3}, [%4];\n"
                 : "=r"(r[0]), "=r"(r[1]), "=r"(r[2]), "=r"(r[3]) : "r"(addr));
}

// BM=BN=128, BK=32 halves, 2 stages, tiles [row][k] stride 72 halves (144B).
#define SKH 72
#define STG_H (128*SKH)                   // halves per tile per stage
#define SMEM_GEMM (4*STG_H*2)             // 73728 bytes

// ---------------- layer GEMMs: C = A[M,K](fp16) * W^T (W [N][K] fp16) ----------------
template<int EPI>   // 0 bias -> half, 1 bias+res -> float, 2 bias+gelu -> half
__global__ __launch_bounds__(256, 2)
void gemm_h(const __half* __restrict__ A, const __half* __restrict__ B,
            const float* __restrict__ bias, const float* __restrict__ res,
            void* __restrict__ Cv, int M, int N, int K) {
    extern __shared__ __half smh[];
    __half* As = smh;
    __half* Bs = smh + 2 * STG_H;

    const int tid  = threadIdx.x;
    const int lane = tid & 31, wid = tid >> 5;
    const int wm = (wid & 1) * 64, wn = (wid >> 1) * 32;
    const int g = lane >> 2, tq = lane & 3;
    const int m0 = blockIdx.y * 128, n0 = blockIdx.x * 128;

    const uint32_t sAu = (uint32_t)__cvta_generic_to_shared(As);
    const uint32_t sBu = (uint32_t)__cvta_generic_to_shared(Bs);

    const int arow = tid >> 2, acol = (tid & 3) << 3;   // 8 halves = 16B

    const int mrow = lane & 15, khalf = (lane >> 4) << 3;
    int aoff[4], boff[2];
    #pragma unroll
    for (int mi = 0; mi < 4; mi++) aoff[mi] = (wm + mi * 16 + mrow) * SKH + khalf;
    #pragma unroll
    for (int p = 0; p < 2; p++)    boff[p]  = (wn + p * 16 + mrow) * SKH + khalf;

    auto load_tile = [&](int t) {
        int k0 = t * 32, st = t & 1;
        #pragma unroll
        for (int it = 0; it < 2; it++) {
            int r = arow + it * 64;
            cpa16(sAu + ((st * 128 + r) * SKH + acol) * 2, A + (size_t)(m0 + r) * K + k0 + acol);
            cpa16(sBu + ((st * 128 + r) * SKH + acol) * 2, B + (size_t)(n0 + r) * K + k0 + acol);
        }
    };

    float acc[4][4][4] = {};
    const int nt = K / 32;

    load_tile(0);
    asm volatile("cp.async.commit_group;\n");

    for (int t = 0; t < nt; t++) {
        if (t + 1 < nt) load_tile(t + 1);
        asm volatile("cp.async.commit_group;\n");
        asm volatile("cp.async.wait_group 1;\n");
        __syncthreads();

        const int stO = (t & 1) * STG_H;
        #pragma unroll
        for (int ks = 0; ks < 2; ks++) {
            uint32_t af[4][4], bq[2][4];
            #pragma unroll
            for (int mi = 0; mi < 4; mi++)
                ldsm4(af[mi], sAu + (stO + aoff[mi] + ks * 16) * 2);
            #pragma unroll
            for (int p = 0; p < 2; p++)
                ldsm4(bq[p], sBu + (stO + boff[p] + ks * 16) * 2);
            #pragma unroll
            for (int mi = 0; mi < 4; mi++) {
                #pragma unroll
                for (int ni = 0; ni < 4; ni++) {
                    uint32_t bb[2] = { bq[ni >> 1][ni & 1], bq[ni >> 1][(ni & 1) + 2] };
                    mma16(acc[mi][ni], af[mi], bb);
                }
            }
        }
        __syncthreads();
    }

    #pragma unroll
    for (int mi = 0; mi < 4; mi++) {
        #pragma unroll
        for (int ni = 0; ni < 4; ni++) {
            int m = m0 + wm + mi * 16 + g;
            int n = n0 + wn + ni * 8 + tq * 2;
            #pragma unroll
            for (int half_ = 0; half_ < 2; half_++) {
                int mm = m + half_ * 8;
                float v0 = acc[mi][ni][half_ * 2 + 0] + bias[n + 0];
                float v1 = acc[mi][ni][half_ * 2 + 1] + bias[n + 1];
                if (EPI == 1) {
                    float2 rr = *(const float2*)(res + (size_t)mm * N + n);
                    v0 += rr.x; v1 += rr.y;
                    *(float2*)((float*)Cv + (size_t)mm * N + n) = make_float2(v0, v1);
                } else {
                    if (EPI == 2) {
                        v0 = 0.5f * v0 * (1.f + erff(v0 * 0.70710678f));
                        v1 = 0.5f * v1 * (1.f + erff(v1 * 0.70710678f));
                    }
                    *(__half2*)((__half*)Cv + (size_t)mm * N + n) = __floats2half2_rn(v0, v1);
                }
            }
        }
    }
}

// ---------------- LM-head GEMM (tokt [V][K] fp16) + fused NLL partials ----------------
__global__ __launch_bounds__(256, 2)
void gemm_lm(const __half* __restrict__ A, const __half* __restrict__ B,
             float* __restrict__ C, float* __restrict__ pm, float* __restrict__ ps,
             int M, int N, int K) {
    extern __shared__ __half smh[];
    __half* As = smh;
    __half* Bs = smh + 2 * STG_H;
    float* sPm = (float*)smh;
    float* sPs = (float*)smh + 512;

    const int tid  = threadIdx.x;
    const int lane = tid & 31, wid = tid >> 5;
    const int wm = (wid & 1) * 64, wn = (wid >> 1) * 32;
    const int g = lane >> 2, tq = lane & 3;
    const int m0 = blockIdx.x * 128, n0 = blockIdx.y * 128;
    const int tileY = blockIdx.y, NTt = gridDim.y;

    const uint32_t sAu = (uint32_t)__cvta_generic_to_shared(As);
    const uint32_t sBu = (uint32_t)__cvta_generic_to_shared(Bs);

    const int arow = tid >> 2, acol = (tid & 3) << 3;
    const int mrow = lane & 15, khalf = (lane >> 4) << 3;
    int aoff[4], boff[2];
    #pragma unroll
    for (int mi = 0; mi < 4; mi++) aoff[mi] = (wm + mi * 16 + mrow) * SKH + khalf;
    #pragma unroll
    for (int p = 0; p < 2; p++)    boff[p]  = (wn + p * 16 + mrow) * SKH + khalf;

    auto load_tile = [&](int t) {
        int k0 = t * 32, st = t & 1;
        #pragma unroll
        for (int it = 0; it < 2; it++) {
            int r = arow + it * 64;
            cpa16(sAu + ((st * 128 + r) * SKH + acol) * 2, A + (size_t)(m0 + r) * K + k0 + acol);
            int n = n0 + r;
            int ok = (n < N);
            cpa16z(sBu + ((st * 128 + r) * SKH + acol) * 2,
                   B + (size_t)(ok ? n : (N - 1)) * K + k0 + acol, ok ? 16 : 0);
        }
    };

    float acc[4][4][4] = {};
    const int nt = K / 32;

    load_tile(0);
    asm volatile("cp.async.commit_group;\n");

    for (int t = 0; t < nt; t++) {
        if (t + 1 < nt) load_tile(t + 1);
        asm volatile("cp.async.commit_group;\n");
        asm volatile("cp.async.wait_group 1;\n");
        __syncthreads();

        const int stO = (t & 1) * STG_H;
        #pragma unroll
        for (int ks = 0; ks < 2; ks++) {
            uint32_t af[4][4], bq[2][4];
            #pragma unroll
            for (int mi = 0; mi < 4; mi++)
                ldsm4(af[mi], sAu + (stO + aoff[mi] + ks * 16) * 2);
            #pragma unroll
            for (int p = 0; p < 2; p++)
                ldsm4(bq[p], sBu + (stO + boff[p] + ks * 16) * 2);
            #pragma unroll
            for (int mi = 0; mi < 4; mi++) {
                #pragma unroll
                for (int ni = 0; ni < 4; ni++) {
                    uint32_t bb[2] = { bq[ni >> 1][ni & 1], bq[ni >> 1][(ni & 1) + 2] };
                    mma16(acc[mi][ni], af[mi], bb);
                }
            }
        }
        __syncthreads();
    }

    // write logits (fp32)
    #pragma unroll
    for (int mi = 0; mi < 4; mi++) {
        #pragma unroll
        for (int ni = 0; ni < 4; ni++) {
            int m = m0 + wm + mi * 16 + g;
            int n = n0 + wn + ni * 8 + tq * 2;
            #pragma unroll
            for (int half_ = 0; half_ < 2; half_++) {
                int mm = m + half_ * 8;
                #pragma unroll
                for (int e = 0; e < 2; e++) {
                    int nn = n + e;
                    if (nn >= N) continue;
                    C[(size_t)mm * N + nn] = acc[mi][ni][half_ * 2 + e];
                }
            }
        }
    }

    // fused per-tile logsumexp partials
    __syncthreads();
    #pragma unroll
    for (int mi = 0; mi < 4; mi++) {
        #pragma unroll
        for (int half_ = 0; half_ < 2; half_++) {
            float lm = -1e30f, lsum = 0.f;
            #pragma unroll
            for (int ni = 0; ni < 4; ni++) {
                #pragma unroll
                for (int e = 0; e < 2; e++) {
                    int nn = n0 + wn + ni * 8 + tq * 2 + e;
                    if (nn < N) lm = fmaxf(lm, acc[mi][ni][half_ * 2 + e]);
                }
            }
            #pragma unroll
            for (int ni = 0; ni < 4; ni++) {
                #pragma unroll
                for (int e = 0; e < 2; e++) {
                    int nn = n0 + wn + ni * 8 + tq * 2 + e;
                    if (nn < N) lsum += __expf(acc[mi][ni][half_ * 2 + e] - lm);
                }
            }
            #pragma unroll
            for (int o = 1; o <= 2; o <<= 1) {
                float m2 = __shfl_xor_sync(0xffffffffu, lm, o);
                float s2 = __shfl_xor_sync(0xffffffffu, lsum, o);
                lse_merge(lm, lsum, m2, s2);
            }
            if (tq == 0) {
                int rl = wm + mi * 16 + half_ * 8 + g;
                sPm[rl * 4 + (wid >> 1)] = lm;
                sPs[rl * 4 + (wid >> 1)] = lsum;
            }
        }
    }
    __syncthreads();
    if (tid < 128) {
        float M_ = sPm[tid * 4], S_ = sPs[tid * 4];
        #pragma unroll
        for (int gi = 1; gi < 4; gi++) lse_merge(M_, S_, sPm[tid * 4 + gi], sPs[tid * 4 + gi]);
        pm[(size_t)(m0 + tid) * NTt + tileY] = M_;
        ps[(size_t)(m0 + tid) * NTt + tileY] = S_;
    }
}

// ---------------- flash attention (fp16 mma) ----------------
#define FQH 72
#define SMEM_FL (3*64*FQH*2)   // 27648 bytes
__global__ __launch_bounds__(128)
void flash_h(const __half* __restrict__ qkv, __half* __restrict__ out) {
    extern __shared__ __half smh[];
    __half* Qs = smh;                 // [64][FQH]
    __half* Ks = smh + 64 * FQH;      // K tile, reused for P
    __half* Vt = smh + 2 * 64 * FQH;  // V transposed: [d][key]

    const int tid = threadIdx.x;
    const int lane = tid & 31, wid = tid >> 5;
    const int g = lane >> 2, tq = lane & 3;
    const int q0 = blockIdx.x * 64;
    const int h = blockIdx.y, b = blockIdx.z;
    const int r0 = wid * 16 + g;

    const __half2 sc8 = __floats2half2_rn(0.125f, 0.125f);
    #pragma unroll
    for (int i = 0; i < 4; i++) {
        int idx = tid + i * 128;
        int r = idx >> 3, c8 = (idx & 7) << 3;
        const __half* src = qkv + (size_t)(b * TQ + q0 + r) * (3 * DQ) + h * HD + c8;
        uint4 raw = *(const uint4*)src;
        __half2* hp = (__half2*)&raw;
        hp[0] = __hmul2(hp[0], sc8); hp[1] = __hmul2(hp[1], sc8);
        hp[2] = __hmul2(hp[2], sc8); hp[3] = __hmul2(hp[3], sc8);
        *(uint4*)(Qs + r * FQH + c8) = raw;
    }

    float m0r = -1e30f, m1r = -1e30f, l0 = 0.f, l1 = 0.f;
    float oc[8][4] = {};

    const int ktiles = q0 / 64 + 1;
    for (int kt = 0; kt < ktiles; kt++) {
        int k0 = kt * 64;
        __syncthreads();
        #pragma unroll
        for (int i = 0; i < 4; i++) {
            int idx = tid + i * 128;
            int r = idx >> 3, c8 = (idx & 7) << 3;
            const __half* src = qkv + (size_t)(b * TQ + k0 + r) * (3 * DQ) + h * HD + c8;
            *(uint4*)(Ks + r * FQH + c8) = *(const uint4*)(src + DQ);
            uint4 vv = *(const uint4*)(src + 2 * DQ);
            const __half* vh = (const __half*)&vv;
            #pragma unroll
            for (int j = 0; j < 8; j++) Vt[(c8 + j) * FQH + r] = vh[j];
        }
        __syncthreads();

        // S = Q K^T
        float sc[8][4] = {};
        #pragma unroll
        for (int kk = 0; kk < 4; kk++) {
            uint32_t a[4];
            a[0] = *(const uint32_t*)(Qs + r0 * FQH + kk * 16 + 2 * tq);
            a[1] = *(const uint32_t*)(Qs + (r0 + 8) * FQH + kk * 16 + 2 * tq);
            a[2] = *(const uint32_t*)(Qs + r0 * FQH + kk * 16 + 8 + 2 * tq);
            a[3] = *(const uint32_t*)(Qs + (r0 + 8) * FQH + kk * 16 + 8 + 2 * tq);
            #pragma unroll
            for (int ni = 0; ni < 8; ni++) {
                uint32_t bb[2];
                bb[0] = *(const uint32_t*)(Ks + (ni * 8 + g) * FQH + kk * 16 + 2 * tq);
                bb[1] = *(const uint32_t*)(Ks + (ni * 8 + g) * FQH + kk * 16 + 8 + 2 * tq);
                mma16(sc[ni], a, bb);
            }
        }

        if (k0 == q0) {
            #pragma unroll
            for (int ni = 0; ni < 8; ni++) {
                int c0 = ni * 8 + 2 * tq, c1 = c0 + 1;
                if (c0 > r0) sc[ni][0] = -1e30f;
                if (c1 > r0) sc[ni][1] = -1e30f;
                if (c0 > r0 + 8) sc[ni][2] = -1e30f;
                if (c1 > r0 + 8) sc[ni][3] = -1e30f;
            }
        }

        float mx0 = -1e30f, mx1 = -1e30f;
        #pragma unroll
        for (int ni = 0; ni < 8; ni++) {
            mx0 = fmaxf(mx0, fmaxf(sc[ni][0], sc[ni][1]));
            mx1 = fmaxf(mx1, fmaxf(sc[ni][2], sc[ni][3]));
        }
        #pragma unroll
        for (int o = 1; o <= 2; o <<= 1) {
            mx0 = fmaxf(mx0, __shfl_xor_sync(0xffffffffu, mx0, o));
            mx1 = fmaxf(mx1, __shfl_xor_sync(0xffffffffu, mx1, o));
        }
        float nm0 = fmaxf(m0r, mx0), nm1 = fmaxf(m1r, mx1);
        float cr0 = __expf(m0r - nm0), cr1 = __expf(m1r - nm1);
        float rs0 = 0.f, rs1 = 0.f;
        #pragma unroll
        for (int ni = 0; ni < 8; ni++) {
            sc[ni][0] = __expf(sc[ni][0] - nm0); rs0 += sc[ni][0];
            sc[ni][1] = __expf(sc[ni][1] - nm0); rs0 += sc[ni][1];
            sc[ni][2] = __expf(sc[ni][2] - nm1); rs1 += sc[ni][2];
            sc[ni][3] = __expf(sc[ni][3] - nm1); rs1 += sc[ni][3];
        }
        #pragma unroll
        for (int o = 1; o <= 2; o <<= 1) {
            rs0 += __shfl_xor_sync(0xffffffffu, rs0, o);
            rs1 += __shfl_xor_sync(0xffffffffu, rs1, o);
        }
        l0 = l0 * cr0 + rs0; l1 = l1 * cr1 + rs1;
        m0r = nm0; m1r = nm1;
        #pragma unroll
        for (int ni = 0; ni < 8; ni++) {
            oc[ni][0] *= cr0; oc[ni][1] *= cr0;
            oc[ni][2] *= cr1; oc[ni][3] *= cr1;
        }

        __syncthreads();   // all warps done reading K
        #pragma unroll
        for (int ni = 0; ni < 8; ni++) {
            *(__half2*)(Ks + r0 * FQH + ni * 8 + 2 * tq)       = __floats2half2_rn(sc[ni][0], sc[ni][1]);
            *(__half2*)(Ks + (r0 + 8) * FQH + ni * 8 + 2 * tq) = __floats2half2_rn(sc[ni][2], sc[ni][3]);
        }
        __syncthreads();

        // O += P V  (B = Vt[d][key])
        #pragma unroll
        for (int kk = 0; kk < 4; kk++) {
            uint32_t a[4];
            a[0] = *(const uint32_t*)(Ks + r0 * FQH + kk * 16 + 2 * tq);
            a[1] = *(const uint32_t*)(Ks + (r0 + 8) * FQH + kk * 16 + 2 * tq);
            a[2] = *(const uint32_t*)(Ks + r0 * FQH + kk * 16 + 8 + 2 * tq);
            a[3] = *(const uint32_t*)(Ks + (r0 + 8) * FQH + kk * 16 + 8 + 2 * tq);
            #pragma unroll
            for (int ni = 0; ni < 8; ni++) {
                uint32_t bb[2];
                bb[0] = *(const uint32_t*)(Vt + (ni * 8 + g) * FQH + kk * 16 + 2 * tq);
                bb[1] = *(const uint32_t*)(Vt + (ni * 8 + g) * FQH + kk * 16 + 8 + 2 * tq);
                mma16(oc[ni], a, bb);
            }
        }
    }

    float i0 = 1.f / l0, i1 = 1.f / l1;
    __half* o0 = out + (size_t)(b * TQ + q0 + r0) * DQ + h * HD;
    __half* o1 = out + (size_t)(b * TQ + q0 + r0 + 8) * DQ + h * HD;
    #pragma unroll
    for (int ni = 0; ni < 8; ni++) {
        *(__half2*)(o0 + ni * 8 + 2 * tq) = __floats2half2_rn(oc[ni][0] * i0, oc[ni][1] * i0);
        *(__half2*)(o1 + ni * 8 + 2 * tq) = __floats2half2_rn(oc[ni][2] * i1, oc[ni][3] * i1);
    }
}

// ---------------- NLL reduce + loss ----------------
__global__ void nll_reduce(const float* __restrict__ pm, const float* __restrict__ ps,
                           const float* __restrict__ logits, const int* __restrict__ tgt,
                           float* __restrict__ nll) {
    int row = blockIdx.x, t = threadIdx.x;
    float M = -1e30f, S = 0.f;
    for (int j = t; j < NT_LM; j += 128)
        lse_merge(M, S, pm[(size_t)row * NT_LM + j], ps[(size_t)row * NT_LM + j]);
    __shared__ float sm_[128], ss_[128];
    sm_[t] = M; ss_[t] = S; __syncthreads();
    for (int o = 64; o > 0; o >>= 1) {
        if (t < o) {
            float mm = sm_[t], ssv = ss_[t];
            lse_merge(mm, ssv, sm_[t + o], ss_[t + o]);
            sm_[t] = mm; ss_[t] = ssv;
        }
        __syncthreads();
    }
    if (t == 0) {
        float lse = sm_[0] + logf(ss_[0]);
        nll[row] = lse - logits[(size_t)row * VQ + tgt[row]];
    }
}
__global__ void loss_kernel(const float* __restrict__ nll, float* __restrict__ loss) {
    __shared__ float s[1024];
    float v = nll[threadIdx.x] + nll[threadIdx.x + 1024];
    s[threadIdx.x] = v; __syncthreads();
    for (int o = 512; o > 0; o >>= 1) {
        if (threadIdx.x < o) s[threadIdx.x] += s[threadIdx.x + o];
        __syncthreads();
    }
    if (threadIdx.x == 0) *loss = s[0] * (1.f / 2048.f);
}

// ---------------- launch ----------------
extern "C" void kernel_launch(void* const* d_in, const int* in_sizes, int n_in,
                              void* d_out, int out_size) {
    const int*   ids  = (const int*)d_in[0];
    const int*   tgt  = (const int*)d_in[1];
    const float* tok  = (const float*)d_in[2];
    const float* pos  = (const float*)d_in[3];
    const float* ln1w = (const float*)d_in[4];
    const float* ln1b = (const float*)d_in[5];
    const float* qkvw = (const float*)d_in[6];
    const float* qkvb = (const float*)d_in[7];
    const float* apw  = (const float*)d_in[8];
    const float* apb  = (const float*)d_in[9];
    const float* ln2w = (const float*)d_in[10];
    const float* ln2b = (const float*)d_in[11];
    const float* fcw  = (const float*)d_in[12];
    const float* fcb  = (const float*)d_in[13];
    const float* pw   = (const float*)d_in[14];
    const float* pb   = (const float*)d_in[15];
    const float* lnfw = (const float*)d_in[16];
    const float* lnfb = (const float*)d_in[17];

    float *x, *nll, *lfb, *pm, *ps;
    __half *h, *qkv, *attn, *ffn;
    __half *wqkv, *wap, *wfc, *wpr, *tokt;
    cudaGetSymbolAddress((void**)&x,    g_x);
    cudaGetSymbolAddress((void**)&h,    g_h);
    cudaGetSymbolAddress((void**)&qkv,  g_qkv);
    cudaGetSymbolAddress((void**)&attn, g_attn);
    cudaGetSymbolAddress((void**)&ffn,  g_ffn);
    cudaGetSymbolAddress((void**)&nll,  g_nll);
    cudaGetSymbolAddress((void**)&lfb,  g_logits_fb);
    cudaGetSymbolAddress((void**)&pm,   g_pm);
    cudaGetSymbolAddress((void**)&ps,   g_ps);
    cudaGetSymbolAddress((void**)&wqkv, g_wqkv);
    cudaGetSymbolAddress((void**)&wap,  g_wap);
    cudaGetSymbolAddress((void**)&wfc,  g_wfc);
    cudaGetSymbolAddress((void**)&wpr,  g_wpr);
    cudaGetSymbolAddress((void**)&tokt, g_tokt);

    cudaFuncSetAttribute(flash_h, cudaFuncAttributeMaxDynamicSharedMemorySize, SMEM_FL);
    cudaFuncSetAttribute(gemm_h<0>, cudaFuncAttributeMaxDynamicSharedMemorySize, SMEM_GEMM);
    cudaFuncSetAttribute(gemm_h<1>, cudaFuncAttributeMaxDynamicSharedMemorySize, SMEM_GEMM);
    cudaFuncSetAttribute(gemm_h<2>, cudaFuncAttributeMaxDynamicSharedMemorySize, SMEM_GEMM);
    cudaFuncSetAttribute(gemm_lm,   cudaFuncAttributeMaxDynamicSharedMemorySize, SMEM_GEMM);

    const long long LOGN = (long long)BT * VQ;
    float* out    = (float*)d_out;
    float* logits;
    float* lossp  = nullptr;
    if ((long long)out_size > LOGN) {
        lossp  = out;
        logits = out + ((long long)out_size - LOGN);
    } else if ((long long)out_size == LOGN) {
        logits = out;
    } else {
        lossp  = out;
        logits = lfb;
    }

    // convert + transpose weights to [N][K] fp16; convert tok_emb
    cvtT_kernel<<<dim3(DQ/32, 3*DQ/32, LQ), 256>>>(qkvw, wqkv, DQ, 3*DQ);
    cvtT_kernel<<<dim3(DQ/32, DQ/32,   LQ), 256>>>(apw,  wap,  DQ, DQ);
    cvtT_kernel<<<dim3(DQ/32, 4*DQ/32, LQ), 256>>>(fcw,  wfc,  DQ, 4*DQ);
    cvtT_kernel<<<dim3(4*DQ/32, DQ/32, LQ), 256>>>(pw,   wpr,  4*DQ, DQ);
    {
        int n = (int)((size_t)VQ*DQ/4);
        cvt_kernel<<<(n+255)/256, 256>>>((const float4*)tok, tokt, n);
    }

    embed_kernel<<<(BT * DQ + 255) / 256, 256>>>(ids, tok, pos, x);

    for (int l = 0; l < LQ; l++) {
        ln_kernel<<<BT, 256>>>(x, ln1w + l * DQ, ln1b + l * DQ, h);
        gemm_h<0><<<dim3((3 * DQ) / 128, BT / 128), 256, SMEM_GEMM>>>(
            h, wqkv + (size_t)l * DQ * 3 * DQ, qkvb + l * 3 * DQ, nullptr, qkv, BT, 3 * DQ, DQ);
        flash_h<<<dim3(TQ / 64, HQ, BQ), 128, SMEM_FL>>>(qkv, attn);
        gemm_h<1><<<dim3(DQ / 128, BT / 128), 256, SMEM_GEMM>>>(
            attn, wap + (size_t)l * DQ * DQ, apb + l * DQ, x, x, BT, DQ, DQ);
        ln_kernel<<<BT, 256>>>(x, ln2w + l * DQ, ln2b + l * DQ, h);
        gemm_h<2><<<dim3((4 * DQ) / 128, BT / 128), 256, SMEM_GEMM>>>(
            h, wfc + (size_t)l * DQ * 4 * DQ, fcb + l * 4 * DQ, nullptr, ffn, BT, 4 * DQ, DQ);
        gemm_h<1><<<dim3(DQ / 128, BT / 128), 256, SMEM_GEMM>>>(
            ffn, wpr + (size_t)l * 4 * DQ * DQ, pb + l * DQ, x, x, BT, DQ, 4 * DQ);
    }

    ln_kernel<<<BT, 256>>>(x, lnfw, lnfb, h);
    gemm_lm<<<dim3(BT / 128, NT_LM), 256, SMEM_GEMM>>>(
        h, tokt, logits, pm, ps, BT, VQ, DQ);

    if (lossp) {
        nll_reduce<<<BT, 128>>>(pm, ps, logits, tgt, nll);
        loss_kernel<<<1, 1024>>>(nll, lossp);
    }
}

// round 9
// speedup vs baseline: 1.5251x; 1.5251x over previous
#include <cuda_runtime.h>
#include <cuda_fp16.h>
#include <math.h>
#include <stdint.h>

// ---------------- problem constants ----------------
#define BQ 2
#define TQ 1024
#define DQ 768
#define LQ 4
#define HQ 12
#define VQ 50257
#define BT (BQ*TQ)
#define HD 64
#define NT_LM 393   // ceil(VQ/128)

// ---------------- scratch ----------------
__device__ float  g_x   [BT*DQ];
__device__ __half g_h   [BT*DQ];
__device__ __half g_qkv [BT*3*DQ];
__device__ __half g_attn[BT*DQ];
__device__ __half g_ffn [BT*4*DQ];
__device__ float  g_nll [BT];
__device__ float  g_pm  [BT*NT_LM];
__device__ float  g_ps  [BT*NT_LM];
__device__ float  g_logits_fb[102926336];
__device__ __half g_wqkv[LQ*DQ*3*DQ];
__device__ __half g_wap [LQ*DQ*DQ];
__device__ __half g_wfc [LQ*DQ*4*DQ];
__device__ __half g_wpr [LQ*4*DQ*DQ];
__device__ __half g_tokt[(size_t)VQ*DQ];

__device__ __forceinline__ void lse_merge(float& m, float& s, float m2, float s2) {
    float M = fmaxf(m, m2);
    s = s * __expf(m - M) + s2 * __expf(m2 - M);
    m = M;
}

// ---------------- fp16 pre-convert (tok_emb) ----------------
__global__ void cvt_kernel(const float4* __restrict__ src, __half* __restrict__ dst, int n4) {
    int i = blockIdx.x * 256 + threadIdx.x;
    if (i >= n4) return;
    float4 v = src[i];
    __half2* d = (__half2*)(dst + (size_t)i * 4);
    d[0] = __floats2half2_rn(v.x, v.y);
    d[1] = __floats2half2_rn(v.z, v.w);
}

// ---------------- fp16 convert + transpose: [L][K][N] -> [L][N][K] ----------------
__global__ __launch_bounds__(256)
void cvtT_kernel(const float* __restrict__ src, __half* __restrict__ dst, int K, int N) {
    __shared__ float t[32][33];
    int l = blockIdx.z;
    int k0 = blockIdx.x * 32, n0 = blockIdx.y * 32;
    const float* S = src + (size_t)l * K * N;
    __half* D = dst + (size_t)l * K * N;
    int tid = threadIdx.x;
    int r = tid >> 3, c4 = (tid & 7) << 2;
    float4 v = *(const float4*)(S + (size_t)(k0 + r) * N + n0 + c4);
    t[r][c4 + 0] = v.x; t[r][c4 + 1] = v.y; t[r][c4 + 2] = v.z; t[r][c4 + 3] = v.w;
    __syncthreads();
    __half2* d = (__half2*)(D + (size_t)(n0 + r) * K + k0 + c4);
    d[0] = __floats2half2_rn(t[c4 + 0][r], t[c4 + 1][r]);
    d[1] = __floats2half2_rn(t[c4 + 2][r], t[c4 + 3][r]);
}

// ---------------- embedding ----------------
__global__ void embed_kernel(const int* __restrict__ ids, const float* __restrict__ tok,
                             const float* __restrict__ pos, float* __restrict__ x) {
    int i = blockIdx.x * 256 + threadIdx.x;
    if (i >= BT * DQ) return;
    int r = i / DQ, d = i - r * DQ;
    x[i] = tok[(size_t)ids[r] * DQ + d] + pos[(r % TQ) * DQ + d];
}

// ---------------- layernorm: warp per row, fp32 in fp16 out ----------------
__global__ __launch_bounds__(256)
void ln_kernel(const float* __restrict__ x, const float* __restrict__ w,
               const float* __restrict__ b, __half* __restrict__ y) {
    const int wid = threadIdx.x >> 5, lane = threadIdx.x & 31;
    const int row = blockIdx.x * 8 + wid;
    const float* xr = x + (size_t)row * DQ;
    float4 v[6];
    float s = 0.f, q = 0.f;
    #pragma unroll
    for (int i = 0; i < 6; i++) {
        v[i] = *(const float4*)(xr + lane * 4 + i * 128);
        s += v[i].x + v[i].y + v[i].z + v[i].w;
        q += v[i].x * v[i].x + v[i].y * v[i].y + v[i].z * v[i].z + v[i].w * v[i].w;
    }
    #pragma unroll
    for (int o = 16; o > 0; o >>= 1) {
        s += __shfl_xor_sync(0xffffffffu, s, o);
        q += __shfl_xor_sync(0xffffffffu, q, o);
    }
    float mean = s * (1.f / DQ);
    float var  = q * (1.f / DQ) - mean * mean;
    float inv  = rsqrtf(var + 1e-5f);
    __half* yr = y + (size_t)row * DQ;
    #pragma unroll
    for (int i = 0; i < 6; i++) {
        int c = lane * 4 + i * 128;
        float4 wv = *(const float4*)(w + c);
        float4 bv = *(const float4*)(b + c);
        float o0 = (v[i].x - mean) * inv * wv.x + bv.x;
        float o1 = (v[i].y - mean) * inv * wv.y + bv.y;
        float o2 = (v[i].z - mean) * inv * wv.z + bv.z;
        float o3 = (v[i].w - mean) * inv * wv.w + bv.w;
        __half2 h0 = __floats2half2_rn(o0, o1);
        __half2 h1 = __floats2half2_rn(o2, o3);
        *(uint2*)(yr + c) = make_uint2(*(uint32_t*)&h0, *(uint32_t*)&h1);
    }
}

// ---------------- fp16 mma / cp.async / ldmatrix helpers ----------------
__device__ __forceinline__ void mma16(float* c, const uint32_t* a, const uint32_t* b) {
    asm volatile("mma.sync.aligned.m16n8k16.row.col.f32.f16.f16.f32 "
                 "{%0,%1,%2,%3}, {%4,%5,%6,%7}, {%8,%9}, {%0,%1,%2,%3};\n"
                 : "+f"(c[0]), "+f"(c[1]), "+f"(c[2]), "+f"(c[3])
                 : "r"(a[0]), "r"(a[1]), "r"(a[2]), "r"(a[3]), "r"(b[0]), "r"(b[1]));
}
__device__ __forceinline__ void cpa16(uint32_t dst, const void* src) {
    asm volatile("cp.async.cg.shared.global [%0], [%1], 16;\n" :: "r"(dst), "l"(src));
}
__device__ __forceinline__ void cpa16z(uint32_t dst, const void* src, int bytes) {
    asm volatile("cp.async.cg.shared.global [%0], [%1], 16, %2;\n" :: "r"(dst), "l"(src), "r"(bytes));
}
__device__ __forceinline__ void ldsm4(uint32_t* r, uint32_t addr) {
    asm volatile("ldmatrix.sync.aligned.m8n8.x4.shared.b16 {%0,%1,%2,%3}, [%4];\n"
                 : "=r"(r[0]), "=r"(r[1]), "=r"(r[2]), "=r"(r[3]) : "r"(addr));
}

#define SKH 72
#define STG_H (128*SKH)
#define SMEM_GEMM (4*STG_H*2)      // 73728 bytes

// ---------------- 128x128 GEMMs: C = A[M,K](fp16) * W^T (W [N][K] fp16) ----------------
template<int EPI>   // 0 bias -> half, 1 bias+res -> float, 2 bias+gelu -> half
__global__ __launch_bounds__(256, 2)
void gemm_h(const __half* __restrict__ A, const __half* __restrict__ B,
            const float* __restrict__ bias, const float* __restrict__ res,
            void* __restrict__ Cv, int M, int N, int K) {
    extern __shared__ __half smh[];
    __half* As = smh;
    __half* Bs = smh + 2 * STG_H;

    const int tid  = threadIdx.x;
    const int lane = tid & 31, wid = tid >> 5;
    const int wm = (wid & 1) * 64, wn = (wid >> 1) * 32;
    const int g = lane >> 2, tq = lane & 3;
    const int m0 = blockIdx.y * 128, n0 = blockIdx.x * 128;

    const uint32_t sAu = (uint32_t)__cvta_generic_to_shared(As);
    const uint32_t sBu = (uint32_t)__cvta_generic_to_shared(Bs);

    const int arow = tid >> 2, acol = (tid & 3) << 3;
    const int mrow = lane & 15, khalf = (lane >> 4) << 3;
    int aoff[4], boff[2];
    #pragma unroll
    for (int mi = 0; mi < 4; mi++) aoff[mi] = (wm + mi * 16 + mrow) * SKH + khalf;
    #pragma unroll
    for (int p = 0; p < 2; p++)    boff[p]  = (wn + p * 16 + mrow) * SKH + khalf;

    auto load_tile = [&](int t) {
        int k0 = t * 32, st = t & 1;
        #pragma unroll
        for (int it = 0; it < 2; it++) {
            int r = arow + it * 64;
            cpa16(sAu + ((st * 128 + r) * SKH + acol) * 2, A + (size_t)(m0 + r) * K + k0 + acol);
            cpa16(sBu + ((st * 128 + r) * SKH + acol) * 2, B + (size_t)(n0 + r) * K + k0 + acol);
        }
    };

    float acc[4][4][4] = {};
    const int nt = K / 32;

    load_tile(0);
    asm volatile("cp.async.commit_group;\n");

    for (int t = 0; t < nt; t++) {
        if (t + 1 < nt) load_tile(t + 1);
        asm volatile("cp.async.commit_group;\n");
        asm volatile("cp.async.wait_group 1;\n");
        __syncthreads();

        const int stO = (t & 1) * STG_H;
        #pragma unroll
        for (int ks = 0; ks < 2; ks++) {
            uint32_t af[4][4], bq[2][4];
            #pragma unroll
            for (int mi = 0; mi < 4; mi++)
                ldsm4(af[mi], sAu + (stO + aoff[mi] + ks * 16) * 2);
            #pragma unroll
            for (int p = 0; p < 2; p++)
                ldsm4(bq[p], sBu + (stO + boff[p] + ks * 16) * 2);
            #pragma unroll
            for (int mi = 0; mi < 4; mi++) {
                #pragma unroll
                for (int ni = 0; ni < 4; ni++) {
                    uint32_t bb[2] = { bq[ni >> 1][ni & 1], bq[ni >> 1][(ni & 1) + 2] };
                    mma16(acc[mi][ni], af[mi], bb);
                }
            }
        }
        __syncthreads();
    }

    #pragma unroll
    for (int mi = 0; mi < 4; mi++) {
        #pragma unroll
        for (int ni = 0; ni < 4; ni++) {
            int m = m0 + wm + mi * 16 + g;
            int n = n0 + wn + ni * 8 + tq * 2;
            #pragma unroll
            for (int half_ = 0; half_ < 2; half_++) {
                int mm = m + half_ * 8;
                float v0 = acc[mi][ni][half_ * 2 + 0] + bias[n + 0];
                float v1 = acc[mi][ni][half_ * 2 + 1] + bias[n + 1];
                if (EPI == 1) {
                    float2 rr = *(const float2*)(res + (size_t)mm * N + n);
                    v0 += rr.x; v1 += rr.y;
                    *(float2*)((float*)Cv + (size_t)mm * N + n) = make_float2(v0, v1);
                } else {
                    if (EPI == 2) {
                        v0 = 0.5f * v0 * (1.f + erff(v0 * 0.70710678f));
                        v1 = 0.5f * v1 * (1.f + erff(v1 * 0.70710678f));
                    }
                    *(__half2*)((__half*)Cv + (size_t)mm * N + n) = __floats2half2_rn(v0, v1);
                }
            }
        }
    }
}

// ---------------- 64x64 GEMM (bias+res -> float): for small-N launches ----------------
#define STG64 (64*SKH)
#define SMEM_G64 (4*STG64*2)     // 36864 bytes
__global__ __launch_bounds__(128, 6)
void gemm_h64(const __half* __restrict__ A, const __half* __restrict__ B,
              const float* __restrict__ bias, const float* __restrict__ res,
              float* __restrict__ C, int M, int N, int K) {
    extern __shared__ __half smh[];
    __half* As = smh;
    __half* Bs = smh + 2 * STG64;

    const int tid  = threadIdx.x;
    const int lane = tid & 31, wid = tid >> 5;   // 4 warps
    const int wm = (wid & 1) * 32, wn = (wid >> 1) * 32;
    const int g = lane >> 2, tq = lane & 3;
    const int m0 = blockIdx.y * 64, n0 = blockIdx.x * 64;

    const uint32_t sAu = (uint32_t)__cvta_generic_to_shared(As);
    const uint32_t sBu = (uint32_t)__cvta_generic_to_shared(Bs);

    const int arow = tid >> 1, acol = (tid & 1) << 4;  // 2 chunks of 8 halves per row pair
    const int mrow = lane & 15, khalf = (lane >> 4) << 3;
    int aoff[2], boff[2];
    #pragma unroll
    for (int mi = 0; mi < 2; mi++) aoff[mi] = (wm + mi * 16 + mrow) * SKH + khalf;
    #pragma unroll
    for (int p = 0; p < 2; p++)    boff[p]  = (wn + p * 16 + mrow) * SKH + khalf;

    auto load_tile = [&](int t) {
        int k0 = t * 32, st = t & 1;
        // 64 rows x 32 halves = 64B/row = 2 cpa16/row; 128 rows-halves total per tile
        int r = arow, c8 = acol >> 1;   // c8 in {0,8}
        cpa16(sAu + ((st * 64 + r) * SKH + c8) * 2, A + (size_t)(m0 + r) * K + k0 + c8);
        cpa16(sAu + ((st * 64 + r) * SKH + c8 + 16) * 2, A + (size_t)(m0 + r) * K + k0 + c8 + 16);
        cpa16(sBu + ((st * 64 + r) * SKH + c8) * 2, B + (size_t)(n0 + r) * K + k0 + c8);
        cpa16(sBu + ((st * 64 + r) * SKH + c8 + 16) * 2, B + (size_t)(n0 + r) * K + k0 + c8 + 16);
    };

    float acc[2][4][4] = {};
    const int nt = K / 32;

    load_tile(0);
    asm volatile("cp.async.commit_group;\n");

    for (int t = 0; t < nt; t++) {
        if (t + 1 < nt) load_tile(t + 1);
        asm volatile("cp.async.commit_group;\n");
        asm volatile("cp.async.wait_group 1;\n");
        __syncthreads();

        const int stO = (t & 1) * STG64;
        #pragma unroll
        for (int ks = 0; ks < 2; ks++) {
            uint32_t af[2][4], bq[2][4];
            #pragma unroll
            for (int mi = 0; mi < 2; mi++)
                ldsm4(af[mi], sAu + (stO + aoff[mi] + ks * 16) * 2);
            #pragma unroll
            for (int p = 0; p < 2; p++)
                ldsm4(bq[p], sBu + (stO + boff[p] + ks * 16) * 2);
            #pragma unroll
            for (int mi = 0; mi < 2; mi++) {
                #pragma unroll
                for (int ni = 0; ni < 4; ni++) {
                    uint32_t bb[2] = { bq[ni >> 1][ni & 1], bq[ni >> 1][(ni & 1) + 2] };
                    mma16(acc[mi][ni], af[mi], bb);
                }
            }
        }
        __syncthreads();
    }

    #pragma unroll
    for (int mi = 0; mi < 2; mi++) {
        #pragma unroll
        for (int ni = 0; ni < 4; ni++) {
            int m = m0 + wm + mi * 16 + g;
            int n = n0 + wn + ni * 8 + tq * 2;
            #pragma unroll
            for (int half_ = 0; half_ < 2; half_++) {
                int mm = m + half_ * 8;
                float2 rr = *(const float2*)(res + (size_t)mm * N + n);
                float v0 = acc[mi][ni][half_ * 2 + 0] + bias[n + 0] + rr.x;
                float v1 = acc[mi][ni][half_ * 2 + 1] + bias[n + 1] + rr.y;
                *(float2*)(C + (size_t)mm * N + n) = make_float2(v0, v1);
            }
        }
    }
}

// ---------------- LM-head GEMM + fused NLL partials ----------------
__global__ __launch_bounds__(256, 2)
void gemm_lm(const __half* __restrict__ A, const __half* __restrict__ B,
             float* __restrict__ C, float* __restrict__ pm, float* __restrict__ ps,
             int M, int N, int K) {
    extern __shared__ __half smh[];
    __half* As = smh;
    __half* Bs = smh + 2 * STG_H;
    float* sPm = (float*)smh;
    float* sPs = (float*)smh + 512;

    const int tid  = threadIdx.x;
    const int lane = tid & 31, wid = tid >> 5;
    const int wm = (wid & 1) * 64, wn = (wid >> 1) * 32;
    const int g = lane >> 2, tq = lane & 3;
    const int m0 = blockIdx.x * 128, n0 = blockIdx.y * 128;
    const int tileY = blockIdx.y, NTt = gridDim.y;

    const uint32_t sAu = (uint32_t)__cvta_generic_to_shared(As);
    const uint32_t sBu = (uint32_t)__cvta_generic_to_shared(Bs);

    const int arow = tid >> 2, acol = (tid & 3) << 3;
    const int mrow = lane & 15, khalf = (lane >> 4) << 3;
    int aoff[4], boff[2];
    #pragma unroll
    for (int mi = 0; mi < 4; mi++) aoff[mi] = (wm + mi * 16 + mrow) * SKH + khalf;
    #pragma unroll
    for (int p = 0; p < 2; p++)    boff[p]  = (wn + p * 16 + mrow) * SKH + khalf;

    auto load_tile = [&](int t) {
        int k0 = t * 32, st = t & 1;
        #pragma unroll
        for (int it = 0; it < 2; it++) {
            int r = arow + it * 64;
            cpa16(sAu + ((st * 128 + r) * SKH + acol) * 2, A + (size_t)(m0 + r) * K + k0 + acol);
            int n = n0 + r;
            int ok = (n < N);
            cpa16z(sBu + ((st * 128 + r) * SKH + acol) * 2,
                   B + (size_t)(ok ? n : (N - 1)) * K + k0 + acol, ok ? 16 : 0);
        }
    };

    float acc[4][4][4] = {};
    const int nt = K / 32;

    load_tile(0);
    asm volatile("cp.async.commit_group;\n");

    for (int t = 0; t < nt; t++) {
        if (t + 1 < nt) load_tile(t + 1);
        asm volatile("cp.async.commit_group;\n");
        asm volatile("cp.async.wait_group 1;\n");
        __syncthreads();

        const int stO = (t & 1) * STG_H;
        #pragma unroll
        for (int ks = 0; ks < 2; ks++) {
            uint32_t af[4][4], bq[2][4];
            #pragma unroll
            for (int mi = 0; mi < 4; mi++)
                ldsm4(af[mi], sAu + (stO + aoff[mi] + ks * 16) * 2);
            #pragma unroll
            for (int p = 0; p < 2; p++)
                ldsm4(bq[p], sBu + (stO + boff[p] + ks * 16) * 2);
            #pragma unroll
            for (int mi = 0; mi < 4; mi++) {
                #pragma unroll
                for (int ni = 0; ni < 4; ni++) {
                    uint32_t bb[2] = { bq[ni >> 1][ni & 1], bq[ni >> 1][(ni & 1) + 2] };
                    mma16(acc[mi][ni], af[mi], bb);
                }
            }
        }
        __syncthreads();
    }

    #pragma unroll
    for (int mi = 0; mi < 4; mi++) {
        #pragma unroll
        for (int ni = 0; ni < 4; ni++) {
            int m = m0 + wm + mi * 16 + g;
            int n = n0 + wn + ni * 8 + tq * 2;
            #pragma unroll
            for (int half_ = 0; half_ < 2; half_++) {
                int mm = m + half_ * 8;
                #pragma unroll
                for (int e = 0; e < 2; e++) {
                    int nn = n + e;
                    if (nn >= N) continue;
                    C[(size_t)mm * N + nn] = acc[mi][ni][half_ * 2 + e];
                }
            }
        }
    }

    __syncthreads();
    #pragma unroll
    for (int mi = 0; mi < 4; mi++) {
        #pragma unroll
        for (int half_ = 0; half_ < 2; half_++) {
            float lm = -1e30f, lsum = 0.f;
            #pragma unroll
            for (int ni = 0; ni < 4; ni++) {
                #pragma unroll
                for (int e = 0; e < 2; e++) {
                    int nn = n0 + wn + ni * 8 + tq * 2 + e;
                    if (nn < N) lm = fmaxf(lm, acc[mi][ni][half_ * 2 + e]);
                }
            }
            #pragma unroll
            for (int ni = 0; ni < 4; ni++) {
                #pragma unroll
                for (int e = 0; e < 2; e++) {
                    int nn = n0 + wn + ni * 8 + tq * 2 + e;
                    if (nn < N) lsum += __expf(acc[mi][ni][half_ * 2 + e] - lm);
                }
            }
            #pragma unroll
            for (int o = 1; o <= 2; o <<= 1) {
                float m2 = __shfl_xor_sync(0xffffffffu, lm, o);
                float s2 = __shfl_xor_sync(0xffffffffu, lsum, o);
                lse_merge(lm, lsum, m2, s2);
            }
            if (tq == 0) {
                int rl = wm + mi * 16 + half_ * 8 + g;
                sPm[rl * 4 + (wid >> 1)] = lm;
                sPs[rl * 4 + (wid >> 1)] = lsum;
            }
        }
    }
    __syncthreads();
    if (tid < 128) {
        float M_ = sPm[tid * 4], S_ = sPs[tid * 4];
        #pragma unroll
        for (int gi = 1; gi < 4; gi++) lse_merge(M_, S_, sPm[tid * 4 + gi], sPs[tid * 4 + gi]);
        pm[(size_t)(m0 + tid) * NTt + tileY] = M_;
        ps[(size_t)(m0 + tid) * NTt + tileY] = S_;
    }
}

// ---------------- flash attention (fp16 mma) ----------------
#define FQH 72
#define SMEM_FL (3*64*FQH*2)
__global__ __launch_bounds__(128)
void flash_h(const __half* __restrict__ qkv, __half* __restrict__ out) {
    extern __shared__ __half smh[];
    __half* Qs = smh;
    __half* Ks = smh + 64 * FQH;
    __half* Vt = smh + 2 * 64 * FQH;

    const int tid = threadIdx.x;
    const int lane = tid & 31, wid = tid >> 5;
    const int g = lane >> 2, tq = lane & 3;
    const int q0 = blockIdx.x * 64;
    const int h = blockIdx.y, b = blockIdx.z;
    const int r0 = wid * 16 + g;

    const __half2 sc8 = __floats2half2_rn(0.125f, 0.125f);
    #pragma unroll
    for (int i = 0; i < 4; i++) {
        int idx = tid + i * 128;
        int r = idx >> 3, c8 = (idx & 7) << 3;
        const __half* src = qkv + (size_t)(b * TQ + q0 + r) * (3 * DQ) + h * HD + c8;
        uint4 raw = *(const uint4*)src;
        __half2* hp = (__half2*)&raw;
        hp[0] = __hmul2(hp[0], sc8); hp[1] = __hmul2(hp[1], sc8);
        hp[2] = __hmul2(hp[2], sc8); hp[3] = __hmul2(hp[3], sc8);
        *(uint4*)(Qs + r * FQH + c8) = raw;
    }

    float m0r = -1e30f, m1r = -1e30f, l0 = 0.f, l1 = 0.f;
    float oc[8][4] = {};

    const int ktiles = q0 / 64 + 1;
    for (int kt = 0; kt < ktiles; kt++) {
        int k0 = kt * 64;
        __syncthreads();
        #pragma unroll
        for (int i = 0; i < 4; i++) {
            int idx = tid + i * 128;
            int r = idx >> 3, c8 = (idx & 7) << 3;
            const __half* src = qkv + (size_t)(b * TQ + k0 + r) * (3 * DQ) + h * HD + c8;
            *(uint4*)(Ks + r * FQH + c8) = *(const uint4*)(src + DQ);
            uint4 vv = *(const uint4*)(src + 2 * DQ);
            const __half* vh = (const __half*)&vv;
            #pragma unroll
            for (int j = 0; j < 8; j++) Vt[(c8 + j) * FQH + r] = vh[j];
        }
        __syncthreads();

        float sc[8][4] = {};
        #pragma unroll
        for (int kk = 0; kk < 4; kk++) {
            uint32_t a[4];
            a[0] = *(const uint32_t*)(Qs + r0 * FQH + kk * 16 + 2 * tq);
            a[1] = *(const uint32_t*)(Qs + (r0 + 8) * FQH + kk * 16 + 2 * tq);
            a[2] = *(const uint32_t*)(Qs + r0 * FQH + kk * 16 + 8 + 2 * tq);
            a[3] = *(const uint32_t*)(Qs + (r0 + 8) * FQH + kk * 16 + 8 + 2 * tq);
            #pragma unroll
            for (int ni = 0; ni < 8; ni++) {
                uint32_t bb[2];
                bb[0] = *(const uint32_t*)(Ks + (ni * 8 + g) * FQH + kk * 16 + 2 * tq);
                bb[1] = *(const uint32_t*)(Ks + (ni * 8 + g) * FQH + kk * 16 + 8 + 2 * tq);
                mma16(sc[ni], a, bb);
            }
        }

        if (k0 == q0) {
            #pragma unroll
            for (int ni = 0; ni < 8; ni++) {
                int c0 = ni * 8 + 2 * tq, c1 = c0 + 1;
                if (c0 > r0) sc[ni][0] = -1e30f;
                if (c1 > r0) sc[ni][1] = -1e30f;
                if (c0 > r0 + 8) sc[ni][2] = -1e30f;
                if (c1 > r0 + 8) sc[ni][3] = -1e30f;
            }
        }

        float mx0 = -1e30f, mx1 = -1e30f;
        #pragma unroll
        for (int ni = 0; ni < 8; ni++) {
            mx0 = fmaxf(mx0, fmaxf(sc[ni][0], sc[ni][1]));
            mx1 = fmaxf(mx1, fmaxf(sc[ni][2], sc[ni][3]));
        }
        #pragma unroll
        for (int o = 1; o <= 2; o <<= 1) {
            mx0 = fmaxf(mx0, __shfl_xor_sync(0xffffffffu, mx0, o));
            mx1 = fmaxf(mx1, __shfl_xor_sync(0xffffffffu, mx1, o));
        }
        float nm0 = fmaxf(m0r, mx0), nm1 = fmaxf(m1r, mx1);
        float cr0 = __expf(m0r - nm0), cr1 = __expf(m1r - nm1);
        float rs0 = 0.f, rs1 = 0.f;
        #pragma unroll
        for (int ni = 0; ni < 8; ni++) {
            sc[ni][0] = __expf(sc[ni][0] - nm0); rs0 += sc[ni][0];
            sc[ni][1] = __expf(sc[ni][1] - nm0); rs0 += sc[ni][1];
            sc[ni][2] = __expf(sc[ni][2] - nm1); rs1 += sc[ni][2];
            sc[ni][3] = __expf(sc[ni][3] - nm1); rs1 += sc[ni][3];
        }
        #pragma unroll
        for (int o = 1; o <= 2; o <<= 1) {
            rs0 += __shfl_xor_sync(0xffffffffu, rs0, o);
            rs1 += __shfl_xor_sync(0xffffffffu, rs1, o);
        }
        l0 = l0 * cr0 + rs0; l1 = l1 * cr1 + rs1;
        m0r = nm0; m1r = nm1;
        #pragma unroll
        for (int ni = 0; ni < 8; ni++) {
            oc[ni][0] *= cr0; oc[ni][1] *= cr0;
            oc[ni][2] *= cr1; oc[ni][3] *= cr1;
        }

        __syncthreads();
        #pragma unroll
        for (int ni = 0; ni < 8; ni++) {
            *(__half2*)(Ks + r0 * FQH + ni * 8 + 2 * tq)       = __floats2half2_rn(sc[ni][0], sc[ni][1]);
            *(__half2*)(Ks + (r0 + 8) * FQH + ni * 8 + 2 * tq) = __floats2half2_rn(sc[ni][2], sc[ni][3]);
        }
        __syncthreads();

        #pragma unroll
        for (int kk = 0; kk < 4; kk++) {
            uint32_t a[4];
            a[0] = *(const uint32_t*)(Ks + r0 * FQH + kk * 16 + 2 * tq);
            a[1] = *(const uint32_t*)(Ks + (r0 + 8) * FQH + kk * 16 + 2 * tq);
            a[2] = *(const uint32_t*)(Ks + r0 * FQH + kk * 16 + 8 + 2 * tq);
            a[3] = *(const uint32_t*)(Ks + (r0 + 8) * FQH + kk * 16 + 8 + 2 * tq);
            #pragma unroll
            for (int ni = 0; ni < 8; ni++) {
                uint32_t bb[2];
                bb[0] = *(const uint32_t*)(Vt + (ni * 8 + g) * FQH + kk * 16 + 2 * tq);
                bb[1] = *(const uint32_t*)(Vt + (ni * 8 + g) * FQH + kk * 16 + 8 + 2 * tq);
                mma16(oc[ni], a, bb);
            }
        }
    }

    float i0 = 1.f / l0, i1 = 1.f / l1;
    __half* o0 = out + (size_t)(b * TQ + q0 + r0) * DQ + h * HD;
    __half* o1 = out + (size_t)(b * TQ + q0 + r0 + 8) * DQ + h * HD;
    #pragma unroll
    for (int ni = 0; ni < 8; ni++) {
        *(__half2*)(o0 + ni * 8 + 2 * tq) = __floats2half2_rn(oc[ni][0] * i0, oc[ni][1] * i0);
        *(__half2*)(o1 + ni * 8 + 2 * tq) = __floats2half2_rn(oc[ni][2] * i1, oc[ni][3] * i1);
    }
}

// ---------------- NLL reduce + loss ----------------
__global__ void nll_reduce(const float* __restrict__ pm, const float* __restrict__ ps,
                           const float* __restrict__ logits, const int* __restrict__ tgt,
                           float* __restrict__ nll) {
    int row = blockIdx.x, t = threadIdx.x;
    float M = -1e30f, S = 0.f;
    for (int j = t; j < NT_LM; j += 128)
        lse_merge(M, S, pm[(size_t)row * NT_LM + j], ps[(size_t)row * NT_LM + j]);
    __shared__ float sm_[128], ss_[128];
    sm_[t] = M; ss_[t] = S; __syncthreads();
    for (int o = 64; o > 0; o >>= 1) {
        if (t < o) {
            float mm = sm_[t], ssv = ss_[t];
            lse_merge(mm, ssv, sm_[t + o], ss_[t + o]);
            sm_[t] = mm; ss_[t] = ssv;
        }
        __syncthreads();
    }
    if (t == 0) {
        float lse = sm_[0] + logf(ss_[0]);
        nll[row] = lse - logits[(size_t)row * VQ + tgt[row]];
    }
}
__global__ void loss_kernel(const float* __restrict__ nll, float* __restrict__ loss) {
    __shared__ float s[1024];
    float v = nll[threadIdx.x] + nll[threadIdx.x + 1024];
    s[threadIdx.x] = v; __syncthreads();
    for (int o = 512; o > 0; o >>= 1) {
        if (threadIdx.x < o) s[threadIdx.x] += s[threadIdx.x + o];
        __syncthreads();
    }
    if (threadIdx.x == 0) *loss = s[0] * (1.f / 2048.f);
}

// ---------------- launch ----------------
extern "C" void kernel_launch(void* const* d_in, const int* in_sizes, int n_in,
                              void* d_out, int out_size) {
    const int*   ids  = (const int*)d_in[0];
    const int*   tgt  = (const int*)d_in[1];
    const float* tok  = (const float*)d_in[2];
    const float* pos  = (const float*)d_in[3];
    const float* ln1w = (const float*)d_in[4];
    const float* ln1b = (const float*)d_in[5];
    const float* qkvw = (const float*)d_in[6];
    const float* qkvb = (const float*)d_in[7];
    const float* apw  = (const float*)d_in[8];
    const float* apb  = (const float*)d_in[9];
    const float* ln2w = (const float*)d_in[10];
    const float* ln2b = (const float*)d_in[11];
    const float* fcw  = (const float*)d_in[12];
    const float* fcb  = (const float*)d_in[13];
    const float* pw   = (const float*)d_in[14];
    const float* pb   = (const float*)d_in[15];
    const float* lnfw = (const float*)d_in[16];
    const float* lnfb = (const float*)d_in[17];

    float *x, *nll, *lfb, *pm, *ps;
    __half *h, *qkv, *attn, *ffn;
    __half *wqkv, *wap, *wfc, *wpr, *tokt;
    cudaGetSymbolAddress((void**)&x,    g_x);
    cudaGetSymbolAddress((void**)&h,    g_h);
    cudaGetSymbolAddress((void**)&qkv,  g_qkv);
    cudaGetSymbolAddress((void**)&attn, g_attn);
    cudaGetSymbolAddress((void**)&ffn,  g_ffn);
    cudaGetSymbolAddress((void**)&nll,  g_nll);
    cudaGetSymbolAddress((void**)&lfb,  g_logits_fb);
    cudaGetSymbolAddress((void**)&pm,   g_pm);
    cudaGetSymbolAddress((void**)&ps,   g_ps);
    cudaGetSymbolAddress((void**)&wqkv, g_wqkv);
    cudaGetSymbolAddress((void**)&wap,  g_wap);
    cudaGetSymbolAddress((void**)&wfc,  g_wfc);
    cudaGetSymbolAddress((void**)&wpr,  g_wpr);
    cudaGetSymbolAddress((void**)&tokt, g_tokt);

    cudaFuncSetAttribute(flash_h,   cudaFuncAttributeMaxDynamicSharedMemorySize, SMEM_FL);
    cudaFuncSetAttribute(gemm_h<0>, cudaFuncAttributeMaxDynamicSharedMemorySize, SMEM_GEMM);
    cudaFuncSetAttribute(gemm_h<2>, cudaFuncAttributeMaxDynamicSharedMemorySize, SMEM_GEMM);
    cudaFuncSetAttribute(gemm_h64,  cudaFuncAttributeMaxDynamicSharedMemorySize, SMEM_G64);
    cudaFuncSetAttribute(gemm_lm,   cudaFuncAttributeMaxDynamicSharedMemorySize, SMEM_GEMM);

    const long long LOGN = (long long)BT * VQ;
    float* out    = (float*)d_out;
    float* logits;
    float* lossp  = nullptr;
    if ((long long)out_size > LOGN) {
        lossp  = out;
        logits = out + ((long long)out_size - LOGN);
    } else if ((long long)out_size == LOGN) {
        logits = out;
    } else {
        lossp  = out;
        logits = lfb;
    }

    cvtT_kernel<<<dim3(DQ/32, 3*DQ/32, LQ), 256>>>(qkvw, wqkv, DQ, 3*DQ);
    cvtT_kernel<<<dim3(DQ/32, DQ/32,   LQ), 256>>>(apw,  wap,  DQ, DQ);
    cvtT_kernel<<<dim3(DQ/32, 4*DQ/32, LQ), 256>>>(fcw,  wfc,  DQ, 4*DQ);
    cvtT_kernel<<<dim3(4*DQ/32, DQ/32, LQ), 256>>>(pw,   wpr,  4*DQ, DQ);
    {
        int n = (int)((size_t)VQ*DQ/4);
        cvt_kernel<<<(n+255)/256, 256>>>((const float4*)tok, tokt, n);
    }

    embed_kernel<<<(BT * DQ + 255) / 256, 256>>>(ids, tok, pos, x);

    for (int l = 0; l < LQ; l++) {
        ln_kernel<<<BT/8, 256>>>(x, ln1w + l * DQ, ln1b + l * DQ, h);
        gemm_h<0><<<dim3((3 * DQ) / 128, BT / 128), 256, SMEM_GEMM>>>(
            h, wqkv + (size_t)l * DQ * 3 * DQ, qkvb + l * 3 * DQ, nullptr, qkv, BT, 3 * DQ, DQ);
        flash_h<<<dim3(TQ / 64, HQ, BQ), 128, SMEM_FL>>>(qkv, attn);
        gemm_h64<<<dim3(DQ / 64, BT / 64), 128, SMEM_G64>>>(
            attn, wap + (size_t)l * DQ * DQ, apb + l * DQ, x, x, BT, DQ, DQ);
        ln_kernel<<<BT/8, 256>>>(x, ln2w + l * DQ, ln2b + l * DQ, h);
        gemm_h<2><<<dim3((4 * DQ) / 128, BT / 128), 256, SMEM_GEMM>>>(
            h, wfc + (size_t)l * DQ * 4 * DQ, fcb + l * 4 * DQ, nullptr, ffn, BT, 4 * DQ, DQ);
        gemm_h64<<<dim3(DQ / 64, BT / 64), 128, SMEM_G64>>>(
            ffn, wpr + (size_t)l * 4 * DQ * DQ, pb + l * DQ, x, x, BT, DQ, 4 * DQ);
    }

    ln_kernel<<<BT/8, 256>>>(x, lnfw, lnfb, h);
    gemm_lm<<<dim3(BT / 128, NT_LM), 256, SMEM_GEMM>>>(
        h, tokt, logits, pm, ps, BT, VQ, DQ);

    if (lossp) {
        nll_reduce<<<BT, 128>>>(pm, ps, logits, tgt, nll);
        loss_kernel<<<1, 1024>>>(nll, lossp);
    }
}

// round 10
// speedup vs baseline: 1.5549x; 1.0196x over previous
#include <cuda_runtime.h>
#include <cuda_fp16.h>
#include <math.h>
#include <stdint.h>

// ---------------- problem constants ----------------
#define BQ 2
#define TQ 1024
#define DQ 768
#define LQ 4
#define HQ 12
#define VQ 50257
#define BT (BQ*TQ)
#define HD 64
#define NT_LM 393   // ceil(VQ/128)

// ---------------- scratch ----------------
__device__ float  g_x   [BT*DQ];
__device__ __half g_h   [BT*DQ];
__device__ __half g_qkv [BT*3*DQ];
__device__ __half g_attn[BT*DQ];
__device__ __half g_ffn [BT*4*DQ];
__device__ float  g_nll [BT];
__device__ float  g_pm  [BT*NT_LM];
__device__ float  g_ps  [BT*NT_LM];
__device__ float  g_logits_fb[102926336];
__device__ __half g_wqkv[LQ*DQ*3*DQ];
__device__ __half g_wap [LQ*DQ*DQ];
__device__ __half g_wfc [LQ*DQ*4*DQ];
__device__ __half g_wpr [LQ*4*DQ*DQ];
__device__ __half g_tokt[(size_t)VQ*DQ];

__device__ __forceinline__ void lse_merge(float& m, float& s, float m2, float s2) {
    float M = fmaxf(m, m2);
    s = s * __expf(m - M) + s2 * __expf(m2 - M);
    m = M;
}

// ---------------- fp16 pre-convert (tok_emb) ----------------
__global__ void cvt_kernel(const float4* __restrict__ src, __half* __restrict__ dst, int n4) {
    int i = blockIdx.x * 256 + threadIdx.x;
    if (i >= n4) return;
    float4 v = src[i];
    __half2* d = (__half2*)(dst + (size_t)i * 4);
    d[0] = __floats2half2_rn(v.x, v.y);
    d[1] = __floats2half2_rn(v.z, v.w);
}

// ---------------- fp16 convert + transpose: [L][K][N] -> [L][N][K] ----------------
__global__ __launch_bounds__(256)
void cvtT_kernel(const float* __restrict__ src, __half* __restrict__ dst, int K, int N) {
    __shared__ float t[32][33];
    int l = blockIdx.z;
    int k0 = blockIdx.x * 32, n0 = blockIdx.y * 32;
    const float* S = src + (size_t)l * K * N;
    __half* D = dst + (size_t)l * K * N;
    int tid = threadIdx.x;
    int r = tid >> 3, c4 = (tid & 7) << 2;
    float4 v = *(const float4*)(S + (size_t)(k0 + r) * N + n0 + c4);
    t[r][c4 + 0] = v.x; t[r][c4 + 1] = v.y; t[r][c4 + 2] = v.z; t[r][c4 + 3] = v.w;
    __syncthreads();
    __half2* d = (__half2*)(D + (size_t)(n0 + r) * K + k0 + c4);
    d[0] = __floats2half2_rn(t[c4 + 0][r], t[c4 + 1][r]);
    d[1] = __floats2half2_rn(t[c4 + 2][r], t[c4 + 3][r]);
}

// ---------------- embedding ----------------
__global__ void embed_kernel(const int* __restrict__ ids, const float* __restrict__ tok,
                             const float* __restrict__ pos, float* __restrict__ x) {
    int i = blockIdx.x * 256 + threadIdx.x;
    if (i >= BT * DQ) return;
    int r = i / DQ, d = i - r * DQ;
    x[i] = tok[(size_t)ids[r] * DQ + d] + pos[(r % TQ) * DQ + d];
}

// ---------------- layernorm: warp per row ----------------
__global__ __launch_bounds__(256)
void ln_kernel(const float* __restrict__ x, const float* __restrict__ w,
               const float* __restrict__ b, __half* __restrict__ y) {
    const int wid = threadIdx.x >> 5, lane = threadIdx.x & 31;
    const int row = blockIdx.x * 8 + wid;
    const float* xr = x + (size_t)row * DQ;
    float4 v[6];
    float s = 0.f, q = 0.f;
    #pragma unroll
    for (int i = 0; i < 6; i++) {
        v[i] = *(const float4*)(xr + lane * 4 + i * 128);
        s += v[i].x + v[i].y + v[i].z + v[i].w;
        q += v[i].x * v[i].x + v[i].y * v[i].y + v[i].z * v[i].z + v[i].w * v[i].w;
    }
    #pragma unroll
    for (int o = 16; o > 0; o >>= 1) {
        s += __shfl_xor_sync(0xffffffffu, s, o);
        q += __shfl_xor_sync(0xffffffffu, q, o);
    }
    float mean = s * (1.f / DQ);
    float var  = q * (1.f / DQ) - mean * mean;
    float inv  = rsqrtf(var + 1e-5f);
    __half* yr = y + (size_t)row * DQ;
    #pragma unroll
    for (int i = 0; i < 6; i++) {
        int c = lane * 4 + i * 128;
        float4 wv = *(const float4*)(w + c);
        float4 bv = *(const float4*)(b + c);
        __half2 h0 = __floats2half2_rn((v[i].x - mean) * inv * wv.x + bv.x,
                                       (v[i].y - mean) * inv * wv.y + bv.y);
        __half2 h1 = __floats2half2_rn((v[i].z - mean) * inv * wv.z + bv.z,
                                       (v[i].w - mean) * inv * wv.w + bv.w);
        *(uint2*)(yr + c) = make_uint2(*(uint32_t*)&h0, *(uint32_t*)&h1);
    }
}

// ---------------- fp16 mma / cp.async / ldmatrix helpers ----------------
__device__ __forceinline__ void mma16(float* c, const uint32_t* a, const uint32_t* b) {
    asm volatile("mma.sync.aligned.m16n8k16.row.col.f32.f16.f16.f32 "
                 "{%0,%1,%2,%3}, {%4,%5,%6,%7}, {%8,%9}, {%0,%1,%2,%3};\n"
                 : "+f"(c[0]), "+f"(c[1]), "+f"(c[2]), "+f"(c[3])
                 : "r"(a[0]), "r"(a[1]), "r"(a[2]), "r"(a[3]), "r"(b[0]), "r"(b[1]));
}
__device__ __forceinline__ void cpa16(uint32_t dst, const void* src) {
    asm volatile("cp.async.cg.shared.global [%0], [%1], 16;\n" :: "r"(dst), "l"(src));
}
__device__ __forceinline__ void cpa16z(uint32_t dst, const void* src, int bytes) {
    asm volatile("cp.async.cg.shared.global [%0], [%1], 16, %2;\n" :: "r"(dst), "l"(src), "r"(bytes));
}
__device__ __forceinline__ void ldsm4(uint32_t* r, uint32_t addr) {
    asm volatile("ldmatrix.sync.aligned.m8n8.x4.shared.b16 {%0,%1,%2,%3}, [%4];\n"
                 : "=r"(r[0]), "=r"(r[1]), "=r"(r[2]), "=r"(r[3]) : "r"(addr));
}
__device__ __forceinline__ void ldsm4t(uint32_t* r, uint32_t addr) {
    asm volatile("ldmatrix.sync.aligned.m8n8.x4.trans.shared.b16 {%0,%1,%2,%3}, [%4];\n"
                 : "=r"(r[0]), "=r"(r[1]), "=r"(r[2]), "=r"(r[3]) : "r"(addr));
}
__device__ __forceinline__ uint32_t packh2(float a, float b) {
    __half2 h = __floats2half2_rn(a, b);
    return *(uint32_t*)&h;
}

#define SKH 72
#define STG_H (128*SKH)
#define SMEM_GEMM (4*STG_H*2)      // 73728 bytes

// ---------------- 128x128 GEMM (qkv): C = A * W^T ----------------
__global__ __launch_bounds__(256, 2)
void gemm_h(const __half* __restrict__ A, const __half* __restrict__ B,
            const float* __restrict__ bias, __half* __restrict__ C,
            int M, int N, int K) {
    extern __shared__ __half smh[];
    __half* As = smh;
    __half* Bs = smh + 2 * STG_H;

    const int tid  = threadIdx.x;
    const int lane = tid & 31, wid = tid >> 5;
    const int wm = (wid & 1) * 64, wn = (wid >> 1) * 32;
    const int g = lane >> 2, tq = lane & 3;
    const int m0 = blockIdx.y * 128, n0 = blockIdx.x * 128;

    const uint32_t sAu = (uint32_t)__cvta_generic_to_shared(As);
    const uint32_t sBu = (uint32_t)__cvta_generic_to_shared(Bs);

    const int arow = tid >> 2, acol = (tid & 3) << 3;
    const int mrow = lane & 15, khalf = (lane >> 4) << 3;
    int aoff[4], boff[2];
    #pragma unroll
    for (int mi = 0; mi < 4; mi++) aoff[mi] = (wm + mi * 16 + mrow) * SKH + khalf;
    #pragma unroll
    for (int p = 0; p < 2; p++)    boff[p]  = (wn + p * 16 + mrow) * SKH + khalf;

    auto load_tile = [&](int t) {
        int k0 = t * 32, st = t & 1;
        #pragma unroll
        for (int it = 0; it < 2; it++) {
            int r = arow + it * 64;
            cpa16(sAu + ((st * 128 + r) * SKH + acol) * 2, A + (size_t)(m0 + r) * K + k0 + acol);
            cpa16(sBu + ((st * 128 + r) * SKH + acol) * 2, B + (size_t)(n0 + r) * K + k0 + acol);
        }
    };

    float acc[4][4][4] = {};
    const int nt = K / 32;

    load_tile(0);
    asm volatile("cp.async.commit_group;\n");

    for (int t = 0; t < nt; t++) {
        if (t + 1 < nt) load_tile(t + 1);
        asm volatile("cp.async.commit_group;\n");
        asm volatile("cp.async.wait_group 1;\n");
        __syncthreads();

        const int stO = (t & 1) * STG_H;
        #pragma unroll
        for (int ks = 0; ks < 2; ks++) {
            uint32_t af[4][4], bq[2][4];
            #pragma unroll
            for (int mi = 0; mi < 4; mi++)
                ldsm4(af[mi], sAu + (stO + aoff[mi] + ks * 16) * 2);
            #pragma unroll
            for (int p = 0; p < 2; p++)
                ldsm4(bq[p], sBu + (stO + boff[p] + ks * 16) * 2);
            #pragma unroll
            for (int mi = 0; mi < 4; mi++) {
                #pragma unroll
                for (int ni = 0; ni < 4; ni++) {
                    uint32_t bb[2] = { bq[ni >> 1][ni & 1], bq[ni >> 1][(ni & 1) + 2] };
                    mma16(acc[mi][ni], af[mi], bb);
                }
            }
        }
        __syncthreads();
    }

    #pragma unroll
    for (int mi = 0; mi < 4; mi++) {
        #pragma unroll
        for (int ni = 0; ni < 4; ni++) {
            int m = m0 + wm + mi * 16 + g;
            int n = n0 + wn + ni * 8 + tq * 2;
            #pragma unroll
            for (int half_ = 0; half_ < 2; half_++) {
                int mm = m + half_ * 8;
                float v0 = acc[mi][ni][half_ * 2 + 0] + bias[n + 0];
                float v1 = acc[mi][ni][half_ * 2 + 1] + bias[n + 1];
                *(__half2*)(C + (size_t)mm * N + n) = __floats2half2_rn(v0, v1);
            }
        }
    }
}

// ---------------- 64x64 GEMM, templated epilogue ----------------
#define STG64 (64*SKH)
#define SMEM_G64 (4*STG64*2)     // 36864 bytes
template<int EPI>   // 1: bias+res -> float, 2: bias+gelu -> half
__global__ __launch_bounds__(128, 6)
void gemm_h64(const __half* __restrict__ A, const __half* __restrict__ B,
              const float* __restrict__ bias, const float* __restrict__ res,
              void* __restrict__ Cv, int M, int N, int K) {
    extern __shared__ __half smh[];
    __half* As = smh;
    __half* Bs = smh + 2 * STG64;

    const int tid  = threadIdx.x;
    const int lane = tid & 31, wid = tid >> 5;
    const int wm = (wid & 1) * 32, wn = (wid >> 1) * 32;
    const int g = lane >> 2, tq = lane & 3;
    const int m0 = blockIdx.y * 64, n0 = blockIdx.x * 64;

    const uint32_t sAu = (uint32_t)__cvta_generic_to_shared(As);
    const uint32_t sBu = (uint32_t)__cvta_generic_to_shared(Bs);

    const int arow = tid >> 1, acol = (tid & 1) << 4;
    const int mrow = lane & 15, khalf = (lane >> 4) << 3;
    int aoff[2], boff[2];
    #pragma unroll
    for (int mi = 0; mi < 2; mi++) aoff[mi] = (wm + mi * 16 + mrow) * SKH + khalf;
    #pragma unroll
    for (int p = 0; p < 2; p++)    boff[p]  = (wn + p * 16 + mrow) * SKH + khalf;

    auto load_tile = [&](int t) {
        int k0 = t * 32, st = t & 1;
        int r = arow, c8 = acol >> 1;
        cpa16(sAu + ((st * 64 + r) * SKH + c8) * 2, A + (size_t)(m0 + r) * K + k0 + c8);
        cpa16(sAu + ((st * 64 + r) * SKH + c8 + 16) * 2, A + (size_t)(m0 + r) * K + k0 + c8 + 16);
        cpa16(sBu + ((st * 64 + r) * SKH + c8) * 2, B + (size_t)(n0 + r) * K + k0 + c8);
        cpa16(sBu + ((st * 64 + r) * SKH + c8 + 16) * 2, B + (size_t)(n0 + r) * K + k0 + c8 + 16);
    };

    float acc[2][4][4] = {};
    const int nt = K / 32;

    load_tile(0);
    asm volatile("cp.async.commit_group;\n");

    for (int t = 0; t < nt; t++) {
        if (t + 1 < nt) load_tile(t + 1);
        asm volatile("cp.async.commit_group;\n");
        asm volatile("cp.async.wait_group 1;\n");
        __syncthreads();

        const int stO = (t & 1) * STG64;
        #pragma unroll
        for (int ks = 0; ks < 2; ks++) {
            uint32_t af[2][4], bq[2][4];
            #pragma unroll
            for (int mi = 0; mi < 2; mi++)
                ldsm4(af[mi], sAu + (stO + aoff[mi] + ks * 16) * 2);
            #pragma unroll
            for (int p = 0; p < 2; p++)
                ldsm4(bq[p], sBu + (stO + boff[p] + ks * 16) * 2);
            #pragma unroll
            for (int mi = 0; mi < 2; mi++) {
                #pragma unroll
                for (int ni = 0; ni < 4; ni++) {
                    uint32_t bb[2] = { bq[ni >> 1][ni & 1], bq[ni >> 1][(ni & 1) + 2] };
                    mma16(acc[mi][ni], af[mi], bb);
                }
            }
        }
        __syncthreads();
    }

    #pragma unroll
    for (int mi = 0; mi < 2; mi++) {
        #pragma unroll
        for (int ni = 0; ni < 4; ni++) {
            int m = m0 + wm + mi * 16 + g;
            int n = n0 + wn + ni * 8 + tq * 2;
            #pragma unroll
            for (int half_ = 0; half_ < 2; half_++) {
                int mm = m + half_ * 8;
                float v0 = acc[mi][ni][half_ * 2 + 0] + bias[n + 0];
                float v1 = acc[mi][ni][half_ * 2 + 1] + bias[n + 1];
                if (EPI == 1) {
                    float2 rr = *(const float2*)((const float*)res + (size_t)mm * N + n);
                    v0 += rr.x; v1 += rr.y;
                    *(float2*)((float*)Cv + (size_t)mm * N + n) = make_float2(v0, v1);
                } else {
                    v0 = 0.5f * v0 * (1.f + erff(v0 * 0.70710678f));
                    v1 = 0.5f * v1 * (1.f + erff(v1 * 0.70710678f));
                    *(__half2*)((__half*)Cv + (size_t)mm * N + n) = __floats2half2_rn(v0, v1);
                }
            }
        }
    }
}

// ---------------- LM-head GEMM + fused NLL partials ----------------
__global__ __launch_bounds__(256, 2)
void gemm_lm(const __half* __restrict__ A, const __half* __restrict__ B,
             float* __restrict__ C, float* __restrict__ pm, float* __restrict__ ps,
             int M, int N, int K) {
    extern __shared__ __half smh[];
    __half* As = smh;
    __half* Bs = smh + 2 * STG_H;
    float* sPm = (float*)smh;
    float* sPs = (float*)smh + 512;

    const int tid  = threadIdx.x;
    const int lane = tid & 31, wid = tid >> 5;
    const int wm = (wid & 1) * 64, wn = (wid >> 1) * 32;
    const int g = lane >> 2, tq = lane & 3;
    const int m0 = blockIdx.x * 128, n0 = blockIdx.y * 128;
    const int tileY = blockIdx.y, NTt = gridDim.y;

    const uint32_t sAu = (uint32_t)__cvta_generic_to_shared(As);
    const uint32_t sBu = (uint32_t)__cvta_generic_to_shared(Bs);

    const int arow = tid >> 2, acol = (tid & 3) << 3;
    const int mrow = lane & 15, khalf = (lane >> 4) << 3;
    int aoff[4], boff[2];
    #pragma unroll
    for (int mi = 0; mi < 4; mi++) aoff[mi] = (wm + mi * 16 + mrow) * SKH + khalf;
    #pragma unroll
    for (int p = 0; p < 2; p++)    boff[p]  = (wn + p * 16 + mrow) * SKH + khalf;

    auto load_tile = [&](int t) {
        int k0 = t * 32, st = t & 1;
        #pragma unroll
        for (int it = 0; it < 2; it++) {
            int r = arow + it * 64;
            cpa16(sAu + ((st * 128 + r) * SKH + acol) * 2, A + (size_t)(m0 + r) * K + k0 + acol);
            int n = n0 + r;
            int ok = (n < N);
            cpa16z(sBu + ((st * 128 + r) * SKH + acol) * 2,
                   B + (size_t)(ok ? n : (N - 1)) * K + k0 + acol, ok ? 16 : 0);
        }
    };

    float acc[4][4][4] = {};
    const int nt = K / 32;

    load_tile(0);
    asm volatile("cp.async.commit_group;\n");

    for (int t = 0; t < nt; t++) {
        if (t + 1 < nt) load_tile(t + 1);
        asm volatile("cp.async.commit_group;\n");
        asm volatile("cp.async.wait_group 1;\n");
        __syncthreads();

        const int stO = (t & 1) * STG_H;
        #pragma unroll
        for (int ks = 0; ks < 2; ks++) {
            uint32_t af[4][4], bq[2][4];
            #pragma unroll
            for (int mi = 0; mi < 4; mi++)
                ldsm4(af[mi], sAu + (stO + aoff[mi] + ks * 16) * 2);
            #pragma unroll
            for (int p = 0; p < 2; p++)
                ldsm4(bq[p], sBu + (stO + boff[p] + ks * 16) * 2);
            #pragma unroll
            for (int mi = 0; mi < 4; mi++) {
                #pragma unroll
                for (int ni = 0; ni < 4; ni++) {
                    uint32_t bb[2] = { bq[ni >> 1][ni & 1], bq[ni >> 1][(ni & 1) + 2] };
                    mma16(acc[mi][ni], af[mi], bb);
                }
            }
        }
        __syncthreads();
    }

    #pragma unroll
    for (int mi = 0; mi < 4; mi++) {
        #pragma unroll
        for (int ni = 0; ni < 4; ni++) {
            int m = m0 + wm + mi * 16 + g;
            int n = n0 + wn + ni * 8 + tq * 2;
            #pragma unroll
            for (int half_ = 0; half_ < 2; half_++) {
                int mm = m + half_ * 8;
                #pragma unroll
                for (int e = 0; e < 2; e++) {
                    int nn = n + e;
                    if (nn >= N) continue;
                    C[(size_t)mm * N + nn] = acc[mi][ni][half_ * 2 + e];
                }
            }
        }
    }

    __syncthreads();
    #pragma unroll
    for (int mi = 0; mi < 4; mi++) {
        #pragma unroll
        for (int half_ = 0; half_ < 2; half_++) {
            float lm = -1e30f, lsum = 0.f;
            #pragma unroll
            for (int ni = 0; ni < 4; ni++) {
                #pragma unroll
                for (int e = 0; e < 2; e++) {
                    int nn = n0 + wn + ni * 8 + tq * 2 + e;
                    if (nn < N) lm = fmaxf(lm, acc[mi][ni][half_ * 2 + e]);
                }
            }
            #pragma unroll
            for (int ni = 0; ni < 4; ni++) {
                #pragma unroll
                for (int e = 0; e < 2; e++) {
                    int nn = n0 + wn + ni * 8 + tq * 2 + e;
                    if (nn < N) lsum += __expf(acc[mi][ni][half_ * 2 + e] - lm);
                }
            }
            #pragma unroll
            for (int o = 1; o <= 2; o <<= 1) {
                float m2 = __shfl_xor_sync(0xffffffffu, lm, o);
                float s2 = __shfl_xor_sync(0xffffffffu, lsum, o);
                lse_merge(lm, lsum, m2, s2);
            }
            if (tq == 0) {
                int rl = wm + mi * 16 + half_ * 8 + g;
                sPm[rl * 4 + (wid >> 1)] = lm;
                sPs[rl * 4 + (wid >> 1)] = lsum;
            }
        }
    }
    __syncthreads();
    if (tid < 128) {
        float M_ = sPm[tid * 4], S_ = sPs[tid * 4];
        #pragma unroll
        for (int gi = 1; gi < 4; gi++) lse_merge(M_, S_, sPm[tid * 4 + gi], sPs[tid * 4 + gi]);
        pm[(size_t)(m0 + tid) * NTt + tileY] = M_;
        ps[(size_t)(m0 + tid) * NTt + tileY] = S_;
    }
}

// ---------------- flash attention v3: register-P, cp.async double-buffered ----------------
#define FQH 72
#define FTILE (64*FQH)                // halves per 64x72 tile
#define SMEM_FL (5*FTILE*2)           // Q + 2K + 2V = 46080 bytes
__global__ __launch_bounds__(128)
void flash_h(const __half* __restrict__ qkv, __half* __restrict__ out) {
    extern __shared__ __half smh[];
    __half* Qs = smh;
    const uint32_t sQ = (uint32_t)__cvta_generic_to_shared(Qs);
    const uint32_t sK[2] = { sQ + FTILE * 2,     sQ + 2 * FTILE * 2 };
    const uint32_t sV[2] = { sQ + 3 * FTILE * 2, sQ + 4 * FTILE * 2 };

    const int tid = threadIdx.x;
    const int lane = tid & 31, wid = tid >> 5;
    const int g = lane >> 2, tq = lane & 3;
    const int q0 = blockIdx.x * 64;
    const int h = blockIdx.y, b = blockIdx.z;
    const int r0 = wid * 16 + g;

    // cp.async row mapping: 512 chunks of 8 halves -> (row, col8)
    const int crow = tid >> 1;             // with 4 iters: rows tid>>1 over 2 chunks... use idx scheme
    (void)crow;

    auto loadKV = [&](int t) {
        int k0 = t * 64, st = t & 1;
        #pragma unroll
        for (int i = 0; i < 4; i++) {
            int idx = tid + i * 128;
            int r = idx >> 3, c8 = (idx & 7) << 3;
            const __half* src = qkv + (size_t)(b * TQ + k0 + r) * (3 * DQ) + h * HD + c8;
            cpa16(sK[st] + (r * FQH + c8) * 2, src + DQ);
            cpa16(sV[st] + (r * FQH + c8) * 2, src + 2 * DQ);
        }
    };

    // V ldmatrix.trans lane address components
    const int vkrow = (lane & 7) + ((lane >> 3) & 1) * 8;
    const int vdoff = (lane >> 4) * 8;

    // load + scale Q
    const __half2 sc8 = __floats2half2_rn(0.125f, 0.125f);
    #pragma unroll
    for (int i = 0; i < 4; i++) {
        int idx = tid + i * 128;
        int r = idx >> 3, c8 = (idx & 7) << 3;
        uint4 raw = *(const uint4*)(qkv + (size_t)(b * TQ + q0 + r) * (3 * DQ) + h * HD + c8);
        __half2* hp = (__half2*)&raw;
        hp[0] = __hmul2(hp[0], sc8); hp[1] = __hmul2(hp[1], sc8);
        hp[2] = __hmul2(hp[2], sc8); hp[3] = __hmul2(hp[3], sc8);
        *(uint4*)(Qs + r * FQH + c8) = raw;
    }

    loadKV(0);
    asm volatile("cp.async.commit_group;\n");
    __syncthreads();

    // preload Q fragments (loop-invariant)
    uint32_t qf[4][4];
    #pragma unroll
    for (int kk = 0; kk < 4; kk++) {
        qf[kk][0] = *(const uint32_t*)(Qs + r0 * FQH + kk * 16 + 2 * tq);
        qf[kk][1] = *(const uint32_t*)(Qs + (r0 + 8) * FQH + kk * 16 + 2 * tq);
        qf[kk][2] = *(const uint32_t*)(Qs + r0 * FQH + kk * 16 + 8 + 2 * tq);
        qf[kk][3] = *(const uint32_t*)(Qs + (r0 + 8) * FQH + kk * 16 + 8 + 2 * tq);
    }

    float m0r = -1e30f, m1r = -1e30f, l0 = 0.f, l1 = 0.f;
    float oc[8][4] = {};

    const int ktiles = q0 / 64 + 1;
    for (int kt = 0; kt < ktiles; kt++) {
        if (kt + 1 < ktiles) {
            loadKV(kt + 1);
            asm volatile("cp.async.commit_group;\n");
            asm volatile("cp.async.wait_group 1;\n");
        } else {
            asm volatile("cp.async.wait_group 0;\n");
        }
        __syncthreads();

        const int st = kt & 1;
        const __half* Kb = (const __half*)((const char*)smh + (sK[st] - sQ));
        // S = Q K^T
        float sc[8][4] = {};
        #pragma unroll
        for (int kk = 0; kk < 4; kk++) {
            #pragma unroll
            for (int ni = 0; ni < 8; ni++) {
                uint32_t bb[2];
                bb[0] = *(const uint32_t*)(Kb + (ni * 8 + g) * FQH + kk * 16 + 2 * tq);
                bb[1] = *(const uint32_t*)(Kb + (ni * 8 + g) * FQH + kk * 16 + 8 + 2 * tq);
                mma16(sc[ni], qf[kk], bb);
            }
        }

        if (kt == ktiles - 1) {   // diagonal tile: causal mask
            #pragma unroll
            for (int ni = 0; ni < 8; ni++) {
                int c0 = ni * 8 + 2 * tq, c1 = c0 + 1;
                if (c0 > r0) sc[ni][0] = -1e30f;
                if (c1 > r0) sc[ni][1] = -1e30f;
                if (c0 > r0 + 8) sc[ni][2] = -1e30f;
                if (c1 > r0 + 8) sc[ni][3] = -1e30f;
            }
        }

        // online softmax
        float mx0 = -1e30f, mx1 = -1e30f;
        #pragma unroll
        for (int ni = 0; ni < 8; ni++) {
            mx0 = fmaxf(mx0, fmaxf(sc[ni][0], sc[ni][1]));
            mx1 = fmaxf(mx1, fmaxf(sc[ni][2], sc[ni][3]));
        }
        #pragma unroll
        for (int o = 1; o <= 2; o <<= 1) {
            mx0 = fmaxf(mx0, __shfl_xor_sync(0xffffffffu, mx0, o));
            mx1 = fmaxf(mx1, __shfl_xor_sync(0xffffffffu, mx1, o));
        }
        float nm0 = fmaxf(m0r, mx0), nm1 = fmaxf(m1r, mx1);
        float cr0 = __expf(m0r - nm0), cr1 = __expf(m1r - nm1);
        float rs0 = 0.f, rs1 = 0.f;
        #pragma unroll
        for (int ni = 0; ni < 8; ni++) {
            sc[ni][0] = __expf(sc[ni][0] - nm0); rs0 += sc[ni][0];
            sc[ni][1] = __expf(sc[ni][1] - nm0); rs0 += sc[ni][1];
            sc[ni][2] = __expf(sc[ni][2] - nm1); rs1 += sc[ni][2];
            sc[ni][3] = __expf(sc[ni][3] - nm1); rs1 += sc[ni][3];
        }
        #pragma unroll
        for (int o = 1; o <= 2; o <<= 1) {
            rs0 += __shfl_xor_sync(0xffffffffu, rs0, o);
            rs1 += __shfl_xor_sync(0xffffffffu, rs1, o);
        }
        l0 = l0 * cr0 + rs0; l1 = l1 * cr1 + rs1;
        m0r = nm0; m1r = nm1;
        #pragma unroll
        for (int ni = 0; ni < 8; ni++) {
            oc[ni][0] *= cr0; oc[ni][1] *= cr0;
            oc[ni][2] *= cr1; oc[ni][3] *= cr1;
        }

        // O += P V : P fragments straight from registers; V via ldmatrix.trans
        #pragma unroll
        for (int kk = 0; kk < 4; kk++) {
            uint32_t a[4];
            a[0] = packh2(sc[2 * kk][0],     sc[2 * kk][1]);
            a[1] = packh2(sc[2 * kk][2],     sc[2 * kk][3]);
            a[2] = packh2(sc[2 * kk + 1][0], sc[2 * kk + 1][1]);
            a[3] = packh2(sc[2 * kk + 1][2], sc[2 * kk + 1][3]);
            #pragma unroll
            for (int pr = 0; pr < 4; pr++) {
                uint32_t v4[4];
                ldsm4t(v4, sV[st] + ((kk * 16 + vkrow) * FQH + pr * 16 + vdoff) * 2);
                uint32_t b0[2] = { v4[0], v4[1] };
                uint32_t b1[2] = { v4[2], v4[3] };
                mma16(oc[pr * 2 + 0], a, b0);
                mma16(oc[pr * 2 + 1], a, b1);
            }
        }
        __syncthreads();   // all warps done with buf st before it is overwritten
    }

    float i0 = 1.f / l0, i1 = 1.f / l1;
    __half* o0 = out + (size_t)(b * TQ + q0 + r0) * DQ + h * HD;
    __half* o1 = out + (size_t)(b * TQ + q0 + r0 + 8) * DQ + h * HD;
    #pragma unroll
    for (int ni = 0; ni < 8; ni++) {
        *(__half2*)(o0 + ni * 8 + 2 * tq) = __floats2half2_rn(oc[ni][0] * i0, oc[ni][1] * i0);
        *(__half2*)(o1 + ni * 8 + 2 * tq) = __floats2half2_rn(oc[ni][2] * i1, oc[ni][3] * i1);
    }
}

// ---------------- NLL reduce + loss ----------------
__global__ void nll_reduce(const float* __restrict__ pm, const float* __restrict__ ps,
                           const float* __restrict__ logits, const int* __restrict__ tgt,
                           float* __restrict__ nll) {
    int row = blockIdx.x, t = threadIdx.x;
    float M = -1e30f, S = 0.f;
    for (int j = t; j < NT_LM; j += 128)
        lse_merge(M, S, pm[(size_t)row * NT_LM + j], ps[(size_t)row * NT_LM + j]);
    __shared__ float sm_[128], ss_[128];
    sm_[t] = M; ss_[t] = S; __syncthreads();
    for (int o = 64; o > 0; o >>= 1) {
        if (t < o) {
            float mm = sm_[t], ssv = ss_[t];
            lse_merge(mm, ssv, sm_[t + o], ss_[t + o]);
            sm_[t] = mm; ss_[t] = ssv;
        }
        __syncthreads();
    }
    if (t == 0) {
        float lse = sm_[0] + logf(ss_[0]);
        nll[row] = lse - logits[(size_t)row * VQ + tgt[row]];
    }
}
__global__ void loss_kernel(const float* __restrict__ nll, float* __restrict__ loss) {
    __shared__ float s[1024];
    float v = nll[threadIdx.x] + nll[threadIdx.x + 1024];
    s[threadIdx.x] = v; __syncthreads();
    for (int o = 512; o > 0; o >>= 1) {
        if (threadIdx.x < o) s[threadIdx.x] += s[threadIdx.x + o];
        __syncthreads();
    }
    if (threadIdx.x == 0) *loss = s[0] * (1.f / 2048.f);
}

// ---------------- launch ----------------
extern "C" void kernel_launch(void* const* d_in, const int* in_sizes, int n_in,
                              void* d_out, int out_size) {
    const int*   ids  = (const int*)d_in[0];
    const int*   tgt  = (const int*)d_in[1];
    const float* tok  = (const float*)d_in[2];
    const float* pos  = (const float*)d_in[3];
    const float* ln1w = (const float*)d_in[4];
    const float* ln1b = (const float*)d_in[5];
    const float* qkvw = (const float*)d_in[6];
    const float* qkvb = (const float*)d_in[7];
    const float* apw  = (const float*)d_in[8];
    const float* apb  = (const float*)d_in[9];
    const float* ln2w = (const float*)d_in[10];
    const float* ln2b = (const float*)d_in[11];
    const float* fcw  = (const float*)d_in[12];
    const float* fcb  = (const float*)d_in[13];
    const float* pw   = (const float*)d_in[14];
    const float* pb   = (const float*)d_in[15];
    const float* lnfw = (const float*)d_in[16];
    const float* lnfb = (const float*)d_in[17];

    float *x, *nll, *lfb, *pm, *ps;
    __half *h, *qkv, *attn, *ffn;
    __half *wqkv, *wap, *wfc, *wpr, *tokt;
    cudaGetSymbolAddress((void**)&x,    g_x);
    cudaGetSymbolAddress((void**)&h,    g_h);
    cudaGetSymbolAddress((void**)&qkv,  g_qkv);
    cudaGetSymbolAddress((void**)&attn, g_attn);
    cudaGetSymbolAddress((void**)&ffn,  g_ffn);
    cudaGetSymbolAddress((void**)&nll,  g_nll);
    cudaGetSymbolAddress((void**)&lfb,  g_logits_fb);
    cudaGetSymbolAddress((void**)&pm,   g_pm);
    cudaGetSymbolAddress((void**)&ps,   g_ps);
    cudaGetSymbolAddress((void**)&wqkv, g_wqkv);
    cudaGetSymbolAddress((void**)&wap,  g_wap);
    cudaGetSymbolAddress((void**)&wfc,  g_wfc);
    cudaGetSymbolAddress((void**)&wpr,  g_wpr);
    cudaGetSymbolAddress((void**)&tokt, g_tokt);

    cudaFuncSetAttribute(flash_h,      cudaFuncAttributeMaxDynamicSharedMemorySize, SMEM_FL);
    cudaFuncSetAttribute(gemm_h,       cudaFuncAttributeMaxDynamicSharedMemorySize, SMEM_GEMM);
    cudaFuncSetAttribute(gemm_h64<1>,  cudaFuncAttributeMaxDynamicSharedMemorySize, SMEM_G64);
    cudaFuncSetAttribute(gemm_h64<2>,  cudaFuncAttributeMaxDynamicSharedMemorySize, SMEM_G64);
    cudaFuncSetAttribute(gemm_lm,      cudaFuncAttributeMaxDynamicSharedMemorySize, SMEM_GEMM);

    const long long LOGN = (long long)BT * VQ;
    float* out    = (float*)d_out;
    float* logits;
    float* lossp  = nullptr;
    if ((long long)out_size > LOGN) {
        lossp  = out;
        logits = out + ((long long)out_size - LOGN);
    } else if ((long long)out_size == LOGN) {
        logits = out;
    } else {
        lossp  = out;
        logits = lfb;
    }

    cvtT_kernel<<<dim3(DQ/32, 3*DQ/32, LQ), 256>>>(qkvw, wqkv, DQ, 3*DQ);
    cvtT_kernel<<<dim3(DQ/32, DQ/32,   LQ), 256>>>(apw,  wap,  DQ, DQ);
    cvtT_kernel<<<dim3(DQ/32, 4*DQ/32, LQ), 256>>>(fcw,  wfc,  DQ, 4*DQ);
    cvtT_kernel<<<dim3(4*DQ/32, DQ/32, LQ), 256>>>(pw,   wpr,  4*DQ, DQ);
    {
        int n = (int)((size_t)VQ*DQ/4);
        cvt_kernel<<<(n+255)/256, 256>>>((const float4*)tok, tokt, n);
    }

    embed_kernel<<<(BT * DQ + 255) / 256, 256>>>(ids, tok, pos, x);

    for (int l = 0; l < LQ; l++) {
        ln_kernel<<<BT/8, 256>>>(x, ln1w + l * DQ, ln1b + l * DQ, h);
        gemm_h<<<dim3((3 * DQ) / 128, BT / 128), 256, SMEM_GEMM>>>(
            h, wqkv + (size_t)l * DQ * 3 * DQ, qkvb + l * 3 * DQ, qkv, BT, 3 * DQ, DQ);
        flash_h<<<dim3(TQ / 64, HQ, BQ), 128, SMEM_FL>>>(qkv, attn);
        gemm_h64<1><<<dim3(DQ / 64, BT / 64), 128, SMEM_G64>>>(
            attn, wap + (size_t)l * DQ * DQ, apb + l * DQ, x, x, BT, DQ, DQ);
        ln_kernel<<<BT/8, 256>>>(x, ln2w + l * DQ, ln2b + l * DQ, h);
        gemm_h64<2><<<dim3((4 * DQ) / 64, BT / 64), 128, SMEM_G64>>>(
            h, wfc + (size_t)l * DQ * 4 * DQ, fcb + l * 4 * DQ, nullptr, ffn, BT, 4 * DQ, DQ);
        gemm_h64<1><<<dim3(DQ / 64, BT / 64), 128, SMEM_G64>>>(
            ffn, wpr + (size_t)l * 4 * DQ * DQ, pb + l * DQ, x, x, BT, DQ, 4 * DQ);
    }

    ln_kernel<<<BT/8, 256>>>(x, lnfw, lnfb, h);
    gemm_lm<<<dim3(BT / 128, NT_LM), 256, SMEM_GEMM>>>(
        h, tokt, logits, pm, ps, BT, VQ, DQ);

    if (lossp) {
        nll_reduce<<<BT, 128>>>(pm, ps, logits, tgt, nll);
        loss_kernel<<<1, 1024>>>(nll, lossp);
    }
}

// round 11
// speedup vs baseline: 1.6983x; 1.0922x over previous
#include <cuda_runtime.h>
#include <cuda_fp16.h>
#include <math.h>
#include <stdint.h>

// ---------------- problem constants ----------------
#define BQ 2
#define TQ 1024
#define DQ 768
#define LQ 4
#define HQ 12
#define VQ 50257
#define BT (BQ*TQ)
#define HD 64
#define NT_LM 393   // ceil(VQ/128)

// ---------------- scratch ----------------
__device__ float  g_x   [BT*DQ];
__device__ __half g_h   [BT*DQ];
__device__ __half g_qkv [BT*3*DQ];
__device__ __half g_attn[BT*DQ];
__device__ __half g_ffn [BT*4*DQ];
__device__ float  g_nll [BT];
__device__ float  g_pm  [BT*NT_LM];
__device__ float  g_ps  [BT*NT_LM];
__device__ float  g_logits_fb[102926336];
// fp16 weight copies in NATIVE [K][N] layout (no transpose)
__device__ __half g_wqkv[LQ*DQ*3*DQ];
__device__ __half g_wap [LQ*DQ*DQ];
__device__ __half g_wfc [LQ*DQ*4*DQ];
__device__ __half g_wpr [LQ*4*DQ*DQ];
__device__ __half g_tokt[(size_t)VQ*DQ];   // [V][K]

__device__ __forceinline__ void lse_merge(float& m, float& s, float m2, float s2) {
    float M = fmaxf(m, m2);
    s = s * __expf(m - M) + s2 * __expf(m2 - M);
    m = M;
}

// ---------------- fp16 streaming convert ----------------
__global__ void cvt_kernel(const float4* __restrict__ src, __half* __restrict__ dst, int n4) {
    int i = blockIdx.x * 256 + threadIdx.x;
    if (i >= n4) return;
    float4 v = src[i];
    __half2* d = (__half2*)(dst + (size_t)i * 4);
    d[0] = __floats2half2_rn(v.x, v.y);
    d[1] = __floats2half2_rn(v.z, v.w);
}

// ---------------- embedding ----------------
__global__ void embed_kernel(const int* __restrict__ ids, const float* __restrict__ tok,
                             const float* __restrict__ pos, float* __restrict__ x) {
    int i = blockIdx.x * 256 + threadIdx.x;
    if (i >= BT * DQ) return;
    int r = i / DQ, d = i - r * DQ;
    x[i] = tok[(size_t)ids[r] * DQ + d] + pos[(r % TQ) * DQ + d];
}

// ---------------- layernorm: warp per row ----------------
__global__ __launch_bounds__(256)
void ln_kernel(const float* __restrict__ x, const float* __restrict__ w,
               const float* __restrict__ b, __half* __restrict__ y) {
    const int wid = threadIdx.x >> 5, lane = threadIdx.x & 31;
    const int row = blockIdx.x * 8 + wid;
    const float* xr = x + (size_t)row * DQ;
    float4 v[6];
    float s = 0.f, q = 0.f;
    #pragma unroll
    for (int i = 0; i < 6; i++) {
        v[i] = *(const float4*)(xr + lane * 4 + i * 128);
        s += v[i].x + v[i].y + v[i].z + v[i].w;
        q += v[i].x * v[i].x + v[i].y * v[i].y + v[i].z * v[i].z + v[i].w * v[i].w;
    }
    #pragma unroll
    for (int o = 16; o > 0; o >>= 1) {
        s += __shfl_xor_sync(0xffffffffu, s, o);
        q += __shfl_xor_sync(0xffffffffu, q, o);
    }
    float mean = s * (1.f / DQ);
    float var  = q * (1.f / DQ) - mean * mean;
    float inv  = rsqrtf(var + 1e-5f);
    __half* yr = y + (size_t)row * DQ;
    #pragma unroll
    for (int i = 0; i < 6; i++) {
        int c = lane * 4 + i * 128;
        float4 wv = *(const float4*)(w + c);
        float4 bv = *(const float4*)(b + c);
        __half2 h0 = __floats2half2_rn((v[i].x - mean) * inv * wv.x + bv.x,
                                       (v[i].y - mean) * inv * wv.y + bv.y);
        __half2 h1 = __floats2half2_rn((v[i].z - mean) * inv * wv.z + bv.z,
                                       (v[i].w - mean) * inv * wv.w + bv.w);
        *(uint2*)(yr + c) = make_uint2(*(uint32_t*)&h0, *(uint32_t*)&h1);
    }
}

// ---------------- fp16 mma / cp.async / ldmatrix helpers ----------------
__device__ __forceinline__ void mma16(float* c, const uint32_t* a, const uint32_t* b) {
    asm volatile("mma.sync.aligned.m16n8k16.row.col.f32.f16.f16.f32 "
                 "{%0,%1,%2,%3}, {%4,%5,%6,%7}, {%8,%9}, {%0,%1,%2,%3};\n"
                 : "+f"(c[0]), "+f"(c[1]), "+f"(c[2]), "+f"(c[3])
                 : "r"(a[0]), "r"(a[1]), "r"(a[2]), "r"(a[3]), "r"(b[0]), "r"(b[1]));
}
__device__ __forceinline__ void cpa16(uint32_t dst, const void* src) {
    asm volatile("cp.async.cg.shared.global [%0], [%1], 16;\n" :: "r"(dst), "l"(src));
}
__device__ __forceinline__ void cpa16z(uint32_t dst, const void* src, int bytes) {
    asm volatile("cp.async.cg.shared.global [%0], [%1], 16, %2;\n" :: "r"(dst), "l"(src), "r"(bytes));
}
__device__ __forceinline__ void ldsm4(uint32_t* r, uint32_t addr) {
    asm volatile("ldmatrix.sync.aligned.m8n8.x4.shared.b16 {%0,%1,%2,%3}, [%4];\n"
                 : "=r"(r[0]), "=r"(r[1]), "=r"(r[2]), "=r"(r[3]) : "r"(addr));
}
__device__ __forceinline__ void ldsm4t(uint32_t* r, uint32_t addr) {
    asm volatile("ldmatrix.sync.aligned.m8n8.x4.trans.shared.b16 {%0,%1,%2,%3}, [%4];\n"
                 : "=r"(r[0]), "=r"(r[1]), "=r"(r[2]), "=r"(r[3]) : "r"(addr));
}
__device__ __forceinline__ uint32_t packh2(float a, float b) {
    __half2 h = __floats2half2_rn(a, b);
    return *(uint32_t*)&h;
}

#define SKH 72      // A tile row stride (halves)
#define SNB 136     // B k-major tile row stride for 128-wide (halves)
#define SNB64 72    // B k-major tile row stride for 64-wide (halves)

// ---------------- 128x128 GEMM (qkv): C = A * W, W native [K][N] ----------------
#define STGA_H   (128*SKH)
#define STGB_H   (32*SNB)
#define SMEM_GEMM ((2*STGA_H + 2*STGB_H)*2)   // 54272 bytes
__global__ __launch_bounds__(256, 2)
void gemm_h(const __half* __restrict__ A, const __half* __restrict__ B,
            const float* __restrict__ bias, __half* __restrict__ C,
            int M, int N, int K) {
    extern __shared__ __half smh[];
    __half* As = smh;
    __half* Bs = smh + 2 * STGA_H;

    const int tid  = threadIdx.x;
    const int lane = tid & 31, wid = tid >> 5;
    const int wm = (wid & 1) * 64, wn = (wid >> 1) * 32;
    const int g = lane >> 2, tq = lane & 3;
    const int m0 = blockIdx.y * 128, n0 = blockIdx.x * 128;

    const uint32_t sAu = (uint32_t)__cvta_generic_to_shared(As);
    const uint32_t sBu = (uint32_t)__cvta_generic_to_shared(Bs);

    const int arow = tid >> 2, acol = (tid & 3) << 3;
    const int brow = tid >> 4, bcol = (tid & 15) << 3;   // B: 32 k-rows x 128 n, 2 iters
    const int mrow = lane & 15, khalf = (lane >> 4) << 3;
    const int vkrow = (lane & 7) + ((lane >> 3) & 1) * 8;
    const int vdoff = (lane >> 4) * 8;
    int aoff[4];
    #pragma unroll
    for (int mi = 0; mi < 4; mi++) aoff[mi] = (wm + mi * 16 + mrow) * SKH + khalf;

    auto load_tile = [&](int t) {
        int k0 = t * 32, st = t & 1;
        #pragma unroll
        for (int it = 0; it < 2; it++) {
            int r = arow + it * 64;
            cpa16(sAu + ((st * 128 + r) * SKH + acol) * 2, A + (size_t)(m0 + r) * K + k0 + acol);
            int br = brow + it * 16;
            cpa16(sBu + ((st * 32 + br) * SNB + bcol) * 2, B + (size_t)(k0 + br) * N + n0 + bcol);
        }
    };

    float acc[4][4][4] = {};
    const int nt = K / 32;

    load_tile(0);
    asm volatile("cp.async.commit_group;\n");

    for (int t = 0; t < nt; t++) {
        if (t + 1 < nt) load_tile(t + 1);
        asm volatile("cp.async.commit_group;\n");
        asm volatile("cp.async.wait_group 1;\n");
        __syncthreads();

        const int stA = (t & 1) * STGA_H;
        const int stB = (t & 1) * STGB_H;
        #pragma unroll
        for (int ks = 0; ks < 2; ks++) {
            uint32_t af[4][4], bq[2][4];
            #pragma unroll
            for (int mi = 0; mi < 4; mi++)
                ldsm4(af[mi], sAu + (stA + aoff[mi] + ks * 16) * 2);
            #pragma unroll
            for (int p = 0; p < 2; p++)
                ldsm4t(bq[p], sBu + (stB + (ks * 16 + vkrow) * SNB + wn + p * 16 + vdoff) * 2);
            #pragma unroll
            for (int mi = 0; mi < 4; mi++) {
                #pragma unroll
                for (int ni = 0; ni < 4; ni++) {
                    uint32_t bb[2] = { bq[ni >> 1][(ni & 1) * 2], bq[ni >> 1][(ni & 1) * 2 + 1] };
                    mma16(acc[mi][ni], af[mi], bb);
                }
            }
        }
        __syncthreads();
    }

    #pragma unroll
    for (int mi = 0; mi < 4; mi++) {
        #pragma unroll
        for (int ni = 0; ni < 4; ni++) {
            int m = m0 + wm + mi * 16 + g;
            int n = n0 + wn + ni * 8 + tq * 2;
            #pragma unroll
            for (int half_ = 0; half_ < 2; half_++) {
                int mm = m + half_ * 8;
                float v0 = acc[mi][ni][half_ * 2 + 0] + bias[n + 0];
                float v1 = acc[mi][ni][half_ * 2 + 1] + bias[n + 1];
                *(__half2*)(C + (size_t)mm * N + n) = __floats2half2_rn(v0, v1);
            }
        }
    }
}

// ---------------- 64x64 GEMM, templated epilogue, W native [K][N] ----------------
#define STGA64 (64*SKH)
#define STGB64 (32*SNB64)
#define SMEM_G64 ((2*STGA64 + 2*STGB64)*2)   // 27648 bytes
template<int EPI>   // 1: bias+res -> float, 2: bias+gelu -> half
__global__ __launch_bounds__(128, 6)
void gemm_h64(const __half* __restrict__ A, const __half* __restrict__ B,
              const float* __restrict__ bias, const float* __restrict__ res,
              void* __restrict__ Cv, int M, int N, int K) {
    extern __shared__ __half smh[];
    __half* As = smh;
    __half* Bs = smh + 2 * STGA64;

    const int tid  = threadIdx.x;
    const int lane = tid & 31, wid = tid >> 5;
    const int wm = (wid & 1) * 32, wn = (wid >> 1) * 32;
    const int g = lane >> 2, tq = lane & 3;
    const int m0 = blockIdx.y * 64, n0 = blockIdx.x * 64;

    const uint32_t sAu = (uint32_t)__cvta_generic_to_shared(As);
    const uint32_t sBu = (uint32_t)__cvta_generic_to_shared(Bs);

    const int arow = tid >> 1, acol = (tid & 1) << 4;
    const int brow = tid >> 3, bcol = (tid & 7) << 3;   // 32 k-rows x 64 n, 2 iters
    const int mrow = lane & 15, khalf = (lane >> 4) << 3;
    const int vkrow = (lane & 7) + ((lane >> 3) & 1) * 8;
    const int vdoff = (lane >> 4) * 8;
    int aoff[2];
    #pragma unroll
    for (int mi = 0; mi < 2; mi++) aoff[mi] = (wm + mi * 16 + mrow) * SKH + khalf;

    auto load_tile = [&](int t) {
        int k0 = t * 32, st = t & 1;
        int r = arow, c8 = acol >> 1;
        cpa16(sAu + ((st * 64 + r) * SKH + c8) * 2, A + (size_t)(m0 + r) * K + k0 + c8);
        cpa16(sAu + ((st * 64 + r) * SKH + c8 + 16) * 2, A + (size_t)(m0 + r) * K + k0 + c8 + 16);
        #pragma unroll
        for (int it = 0; it < 2; it++) {
            int br = brow + it * 16;
            cpa16(sBu + ((st * 32 + br) * SNB64 + bcol) * 2, B + (size_t)(k0 + br) * N + n0 + bcol);
        }
    };

    float acc[2][4][4] = {};
    const int nt = K / 32;

    load_tile(0);
    asm volatile("cp.async.commit_group;\n");

    for (int t = 0; t < nt; t++) {
        if (t + 1 < nt) load_tile(t + 1);
        asm volatile("cp.async.commit_group;\n");
        asm volatile("cp.async.wait_group 1;\n");
        __syncthreads();

        const int stA = (t & 1) * STGA64;
        const int stB = (t & 1) * STGB64;
        #pragma unroll
        for (int ks = 0; ks < 2; ks++) {
            uint32_t af[2][4], bq[2][4];
            #pragma unroll
            for (int mi = 0; mi < 2; mi++)
                ldsm4(af[mi], sAu + (stA + aoff[mi] + ks * 16) * 2);
            #pragma unroll
            for (int p = 0; p < 2; p++)
                ldsm4t(bq[p], sBu + (stB + (ks * 16 + vkrow) * SNB64 + wn + p * 16 + vdoff) * 2);
            #pragma unroll
            for (int mi = 0; mi < 2; mi++) {
                #pragma unroll
                for (int ni = 0; ni < 4; ni++) {
                    uint32_t bb[2] = { bq[ni >> 1][(ni & 1) * 2], bq[ni >> 1][(ni & 1) * 2 + 1] };
                    mma16(acc[mi][ni], af[mi], bb);
                }
            }
        }
        __syncthreads();
    }

    #pragma unroll
    for (int mi = 0; mi < 2; mi++) {
        #pragma unroll
        for (int ni = 0; ni < 4; ni++) {
            int m = m0 + wm + mi * 16 + g;
            int n = n0 + wn + ni * 8 + tq * 2;
            #pragma unroll
            for (int half_ = 0; half_ < 2; half_++) {
                int mm = m + half_ * 8;
                float v0 = acc[mi][ni][half_ * 2 + 0] + bias[n + 0];
                float v1 = acc[mi][ni][half_ * 2 + 1] + bias[n + 1];
                if (EPI == 1) {
                    float2 rr = *(const float2*)((const float*)res + (size_t)mm * N + n);
                    v0 += rr.x; v1 += rr.y;
                    *(float2*)((float*)Cv + (size_t)mm * N + n) = make_float2(v0, v1);
                } else {
                    v0 = 0.5f * v0 * (1.f + erff(v0 * 0.70710678f));
                    v1 = 0.5f * v1 * (1.f + erff(v1 * 0.70710678f));
                    *(__half2*)((__half*)Cv + (size_t)mm * N + n) = __floats2half2_rn(v0, v1);
                }
            }
        }
    }
}

// ---------------- LM-head GEMM (tokt [V][K]) + fused NLL partials ----------------
#define STG_H (128*SKH)
#define SMEM_LM (4*STG_H*2)
__global__ __launch_bounds__(256, 2)
void gemm_lm(const __half* __restrict__ A, const __half* __restrict__ B,
             float* __restrict__ C, float* __restrict__ pm, float* __restrict__ ps,
             int M, int N, int K) {
    extern __shared__ __half smh[];
    __half* As = smh;
    __half* Bs = smh + 2 * STG_H;
    float* sPm = (float*)smh;
    float* sPs = (float*)smh + 512;

    const int tid  = threadIdx.x;
    const int lane = tid & 31, wid = tid >> 5;
    const int wm = (wid & 1) * 64, wn = (wid >> 1) * 32;
    const int g = lane >> 2, tq = lane & 3;
    const int m0 = blockIdx.x * 128, n0 = blockIdx.y * 128;
    const int tileY = blockIdx.y, NTt = gridDim.y;

    const uint32_t sAu = (uint32_t)__cvta_generic_to_shared(As);
    const uint32_t sBu = (uint32_t)__cvta_generic_to_shared(Bs);

    const int arow = tid >> 2, acol = (tid & 3) << 3;
    const int mrow = lane & 15, khalf = (lane >> 4) << 3;
    int aoff[4], boff[2];
    #pragma unroll
    for (int mi = 0; mi < 4; mi++) aoff[mi] = (wm + mi * 16 + mrow) * SKH + khalf;
    #pragma unroll
    for (int p = 0; p < 2; p++)    boff[p]  = (wn + p * 16 + mrow) * SKH + khalf;

    auto load_tile = [&](int t) {
        int k0 = t * 32, st = t & 1;
        #pragma unroll
        for (int it = 0; it < 2; it++) {
            int r = arow + it * 64;
            cpa16(sAu + ((st * 128 + r) * SKH + acol) * 2, A + (size_t)(m0 + r) * K + k0 + acol);
            int n = n0 + r;
            int ok = (n < N);
            cpa16z(sBu + ((st * 128 + r) * SKH + acol) * 2,
                   B + (size_t)(ok ? n : (N - 1)) * K + k0 + acol, ok ? 16 : 0);
        }
    };

    float acc[4][4][4] = {};
    const int nt = K / 32;

    load_tile(0);
    asm volatile("cp.async.commit_group;\n");

    for (int t = 0; t < nt; t++) {
        if (t + 1 < nt) load_tile(t + 1);
        asm volatile("cp.async.commit_group;\n");
        asm volatile("cp.async.wait_group 1;\n");
        __syncthreads();

        const int stO = (t & 1) * STG_H;
        #pragma unroll
        for (int ks = 0; ks < 2; ks++) {
            uint32_t af[4][4], bq[2][4];
            #pragma unroll
            for (int mi = 0; mi < 4; mi++)
                ldsm4(af[mi], sAu + (stO + aoff[mi] + ks * 16) * 2);
            #pragma unroll
            for (int p = 0; p < 2; p++)
                ldsm4(bq[p], sBu + (stO + boff[p] + ks * 16) * 2);
            #pragma unroll
            for (int mi = 0; mi < 4; mi++) {
                #pragma unroll
                for (int ni = 0; ni < 4; ni++) {
                    uint32_t bb[2] = { bq[ni >> 1][ni & 1], bq[ni >> 1][(ni & 1) + 2] };
                    mma16(acc[mi][ni], af[mi], bb);
                }
            }
        }
        __syncthreads();
    }

    #pragma unroll
    for (int mi = 0; mi < 4; mi++) {
        #pragma unroll
        for (int ni = 0; ni < 4; ni++) {
            int m = m0 + wm + mi * 16 + g;
            int n = n0 + wn + ni * 8 + tq * 2;
            #pragma unroll
            for (int half_ = 0; half_ < 2; half_++) {
                int mm = m + half_ * 8;
                #pragma unroll
                for (int e = 0; e < 2; e++) {
                    int nn = n + e;
                    if (nn >= N) continue;
                    C[(size_t)mm * N + nn] = acc[mi][ni][half_ * 2 + e];
                }
            }
        }
    }

    __syncthreads();
    #pragma unroll
    for (int mi = 0; mi < 4; mi++) {
        #pragma unroll
        for (int half_ = 0; half_ < 2; half_++) {
            float lm = -1e30f, lsum = 0.f;
            #pragma unroll
            for (int ni = 0; ni < 4; ni++) {
                #pragma unroll
                for (int e = 0; e < 2; e++) {
                    int nn = n0 + wn + ni * 8 + tq * 2 + e;
                    if (nn < N) lm = fmaxf(lm, acc[mi][ni][half_ * 2 + e]);
                }
            }
            #pragma unroll
            for (int ni = 0; ni < 4; ni++) {
                #pragma unroll
                for (int e = 0; e < 2; e++) {
                    int nn = n0 + wn + ni * 8 + tq * 2 + e;
                    if (nn < N) lsum += __expf(acc[mi][ni][half_ * 2 + e] - lm);
                }
            }
            #pragma unroll
            for (int o = 1; o <= 2; o <<= 1) {
                float m2 = __shfl_xor_sync(0xffffffffu, lm, o);
                float s2 = __shfl_xor_sync(0xffffffffu, lsum, o);
                lse_merge(lm, lsum, m2, s2);
            }
            if (tq == 0) {
                int rl = wm + mi * 16 + half_ * 8 + g;
                sPm[rl * 4 + (wid >> 1)] = lm;
                sPs[rl * 4 + (wid >> 1)] = lsum;
            }
        }
    }
    __syncthreads();
    if (tid < 128) {
        float M_ = sPm[tid * 4], S_ = sPs[tid * 4];
        #pragma unroll
        for (int gi = 1; gi < 4; gi++) lse_merge(M_, S_, sPm[tid * 4 + gi], sPs[tid * 4 + gi]);
        pm[(size_t)(m0 + tid) * NTt + tileY] = M_;
        ps[(size_t)(m0 + tid) * NTt + tileY] = S_;
    }
}

// ---------------- flash attention (register-P, cp.async, reversed launch order) ----------------
#define FQH 72
#define FTILE (64*FQH)
#define SMEM_FL (5*FTILE*2)
__global__ __launch_bounds__(128)
void flash_h(const __half* __restrict__ qkv, __half* __restrict__ out) {
    extern __shared__ __half smh[];
    __half* Qs = smh;
    const uint32_t sQ = (uint32_t)__cvta_generic_to_shared(Qs);
    const uint32_t sK[2] = { sQ + FTILE * 2,     sQ + 2 * FTILE * 2 };
    const uint32_t sV[2] = { sQ + 3 * FTILE * 2, sQ + 4 * FTILE * 2 };

    const int tid = threadIdx.x;
    const int lane = tid & 31, wid = tid >> 5;
    const int g = lane >> 2, tq = lane & 3;
    const int q0 = (gridDim.x - 1 - blockIdx.x) * 64;   // longest blocks first
    const int h = blockIdx.y, b = blockIdx.z;
    const int r0 = wid * 16 + g;

    auto loadKV = [&](int t) {
        int k0 = t * 64, st = t & 1;
        #pragma unroll
        for (int i = 0; i < 4; i++) {
            int idx = tid + i * 128;
            int r = idx >> 3, c8 = (idx & 7) << 3;
            const __half* src = qkv + (size_t)(b * TQ + k0 + r) * (3 * DQ) + h * HD + c8;
            cpa16(sK[st] + (r * FQH + c8) * 2, src + DQ);
            cpa16(sV[st] + (r * FQH + c8) * 2, src + 2 * DQ);
        }
    };

    const int vkrow = (lane & 7) + ((lane >> 3) & 1) * 8;
    const int vdoff = (lane >> 4) * 8;

    const __half2 sc8 = __floats2half2_rn(0.125f, 0.125f);
    #pragma unroll
    for (int i = 0; i < 4; i++) {
        int idx = tid + i * 128;
        int r = idx >> 3, c8 = (idx & 7) << 3;
        uint4 raw = *(const uint4*)(qkv + (size_t)(b * TQ + q0 + r) * (3 * DQ) + h * HD + c8);
        __half2* hp = (__half2*)&raw;
        hp[0] = __hmul2(hp[0], sc8); hp[1] = __hmul2(hp[1], sc8);
        hp[2] = __hmul2(hp[2], sc8); hp[3] = __hmul2(hp[3], sc8);
        *(uint4*)(Qs + r * FQH + c8) = raw;
    }

    loadKV(0);
    asm volatile("cp.async.commit_group;\n");
    __syncthreads();

    uint32_t qf[4][4];
    #pragma unroll
    for (int kk = 0; kk < 4; kk++) {
        qf[kk][0] = *(const uint32_t*)(Qs + r0 * FQH + kk * 16 + 2 * tq);
        qf[kk][1] = *(const uint32_t*)(Qs + (r0 + 8) * FQH + kk * 16 + 2 * tq);
        qf[kk][2] = *(const uint32_t*)(Qs + r0 * FQH + kk * 16 + 8 + 2 * tq);
        qf[kk][3] = *(const uint32_t*)(Qs + (r0 + 8) * FQH + kk * 16 + 8 + 2 * tq);
    }

    float m0r = -1e30f, m1r = -1e30f, l0 = 0.f, l1 = 0.f;
    float oc[8][4] = {};

    const int ktiles = q0 / 64 + 1;
    for (int kt = 0; kt < ktiles; kt++) {
        if (kt + 1 < ktiles) {
            loadKV(kt + 1);
            asm volatile("cp.async.commit_group;\n");
            asm volatile("cp.async.wait_group 1;\n");
        } else {
            asm volatile("cp.async.wait_group 0;\n");
        }
        __syncthreads();

        const int st = kt & 1;
        const __half* Kb = (const __half*)((const char*)smh + (sK[st] - sQ));
        float sc[8][4] = {};
        #pragma unroll
        for (int kk = 0; kk < 4; kk++) {
            #pragma unroll
            for (int ni = 0; ni < 8; ni++) {
                uint32_t bb[2];
                bb[0] = *(const uint32_t*)(Kb + (ni * 8 + g) * FQH + kk * 16 + 2 * tq);
                bb[1] = *(const uint32_t*)(Kb + (ni * 8 + g) * FQH + kk * 16 + 8 + 2 * tq);
                mma16(sc[ni], qf[kk], bb);
            }
        }

        if (kt == ktiles - 1) {
            #pragma unroll
            for (int ni = 0; ni < 8; ni++) {
                int c0 = ni * 8 + 2 * tq, c1 = c0 + 1;
                if (c0 > r0) sc[ni][0] = -1e30f;
                if (c1 > r0) sc[ni][1] = -1e30f;
                if (c0 > r0 + 8) sc[ni][2] = -1e30f;
                if (c1 > r0 + 8) sc[ni][3] = -1e30f;
            }
        }

        float mx0 = -1e30f, mx1 = -1e30f;
        #pragma unroll
        for (int ni = 0; ni < 8; ni++) {
            mx0 = fmaxf(mx0, fmaxf(sc[ni][0], sc[ni][1]));
            mx1 = fmaxf(mx1, fmaxf(sc[ni][2], sc[ni][3]));
        }
        #pragma unroll
        for (int o = 1; o <= 2; o <<= 1) {
            mx0 = fmaxf(mx0, __shfl_xor_sync(0xffffffffu, mx0, o));
            mx1 = fmaxf(mx1, __shfl_xor_sync(0xffffffffu, mx1, o));
        }
        float nm0 = fmaxf(m0r, mx0), nm1 = fmaxf(m1r, mx1);
        float cr0 = __expf(m0r - nm0), cr1 = __expf(m1r - nm1);
        float rs0 = 0.f, rs1 = 0.f;
        #pragma unroll
        for (int ni = 0; ni < 8; ni++) {
            sc[ni][0] = __expf(sc[ni][0] - nm0); rs0 += sc[ni][0];
            sc[ni][1] = __expf(sc[ni][1] - nm0); rs0 += sc[ni][1];
            sc[ni][2] = __expf(sc[ni][2] - nm1); rs1 += sc[ni][2];
            sc[ni][3] = __expf(sc[ni][3] - nm1); rs1 += sc[ni][3];
        }
        #pragma unroll
        for (int o = 1; o <= 2; o <<= 1) {
            rs0 += __shfl_xor_sync(0xffffffffu, rs0, o);
            rs1 += __shfl_xor_sync(0xffffffffu, rs1, o);
        }
        l0 = l0 * cr0 + rs0; l1 = l1 * cr1 + rs1;
        m0r = nm0; m1r = nm1;
        #pragma unroll
        for (int ni = 0; ni < 8; ni++) {
            oc[ni][0] *= cr0; oc[ni][1] *= cr0;
            oc[ni][2] *= cr1; oc[ni][3] *= cr1;
        }

        #pragma unroll
        for (int kk = 0; kk < 4; kk++) {
            uint32_t a[4];
            a[0] = packh2(sc[2 * kk][0],     sc[2 * kk][1]);
            a[1] = packh2(sc[2 * kk][2],     sc[2 * kk][3]);
            a[2] = packh2(sc[2 * kk + 1][0], sc[2 * kk + 1][1]);
            a[3] = packh2(sc[2 * kk + 1][2], sc[2 * kk + 1][3]);
            #pragma unroll
            for (int pr = 0; pr < 4; pr++) {
                uint32_t v4[4];
                ldsm4t(v4, sV[st] + ((kk * 16 + vkrow) * FQH + pr * 16 + vdoff) * 2);
                uint32_t b0[2] = { v4[0], v4[1] };
                uint32_t b1[2] = { v4[2], v4[3] };
                mma16(oc[pr * 2 + 0], a, b0);
                mma16(oc[pr * 2 + 1], a, b1);
            }
        }
        __syncthreads();
    }

    float i0 = 1.f / l0, i1 = 1.f / l1;
    __half* o0 = out + (size_t)(b * TQ + q0 + r0) * DQ + h * HD;
    __half* o1 = out + (size_t)(b * TQ + q0 + r0 + 8) * DQ + h * HD;
    #pragma unroll
    for (int ni = 0; ni < 8; ni++) {
        *(__half2*)(o0 + ni * 8 + 2 * tq) = __floats2half2_rn(oc[ni][0] * i0, oc[ni][1] * i0);
        *(__half2*)(o1 + ni * 8 + 2 * tq) = __floats2half2_rn(oc[ni][2] * i1, oc[ni][3] * i1);
    }
}

// ---------------- NLL reduce + loss ----------------
__global__ void nll_reduce(const float* __restrict__ pm, const float* __restrict__ ps,
                           const float* __restrict__ logits, const int* __restrict__ tgt,
                           float* __restrict__ nll) {
    int row = blockIdx.x, t = threadIdx.x;
    float M = -1e30f, S = 0.f;
    for (int j = t; j < NT_LM; j += 128)
        lse_merge(M, S, pm[(size_t)row * NT_LM + j], ps[(size_t)row * NT_LM + j]);
    __shared__ float sm_[128], ss_[128];
    sm_[t] = M; ss_[t] = S; __syncthreads();
    for (int o = 64; o > 0; o >>= 1) {
        if (t < o) {
            float mm = sm_[t], ssv = ss_[t];
            lse_merge(mm, ssv, sm_[t + o], ss_[t + o]);
            sm_[t] = mm; ss_[t] = ssv;
        }
        __syncthreads();
    }
    if (t == 0) {
        float lse = sm_[0] + logf(ss_[0]);
        nll[row] = lse - logits[(size_t)row * VQ + tgt[row]];
    }
}
__global__ void loss_kernel(const float* __restrict__ nll, float* __restrict__ loss) {
    __shared__ float s[1024];
    float v = nll[threadIdx.x] + nll[threadIdx.x + 1024];
    s[threadIdx.x] = v; __syncthreads();
    for (int o = 512; o > 0; o >>= 1) {
        if (threadIdx.x < o) s[threadIdx.x] += s[threadIdx.x + o];
        __syncthreads();
    }
    if (threadIdx.x == 0) *loss = s[0] * (1.f / 2048.f);
}

// ---------------- launch ----------------
extern "C" void kernel_launch(void* const* d_in, const int* in_sizes, int n_in,
                              void* d_out, int out_size) {
    const int*   ids  = (const int*)d_in[0];
    const int*   tgt  = (const int*)d_in[1];
    const float* tok  = (const float*)d_in[2];
    const float* pos  = (const float*)d_in[3];
    const float* ln1w = (const float*)d_in[4];
    const float* ln1b = (const float*)d_in[5];
    const float* qkvw = (const float*)d_in[6];
    const float* qkvb = (const float*)d_in[7];
    const float* apw  = (const float*)d_in[8];
    const float* apb  = (const float*)d_in[9];
    const float* ln2w = (const float*)d_in[10];
    const float* ln2b = (const float*)d_in[11];
    const float* fcw  = (const float*)d_in[12];
    const float* fcb  = (const float*)d_in[13];
    const float* pw   = (const float*)d_in[14];
    const float* pb   = (const float*)d_in[15];
    const float* lnfw = (const float*)d_in[16];
    const float* lnfb = (const float*)d_in[17];

    float *x, *nll, *lfb, *pm, *ps;
    __half *h, *qkv, *attn, *ffn;
    __half *wqkv, *wap, *wfc, *wpr, *tokt;
    cudaGetSymbolAddress((void**)&x,    g_x);
    cudaGetSymbolAddress((void**)&h,    g_h);
    cudaGetSymbolAddress((void**)&qkv,  g_qkv);
    cudaGetSymbolAddress((void**)&attn, g_attn);
    cudaGetSymbolAddress((void**)&ffn,  g_ffn);
    cudaGetSymbolAddress((void**)&nll,  g_nll);
    cudaGetSymbolAddress((void**)&lfb,  g_logits_fb);
    cudaGetSymbolAddress((void**)&pm,   g_pm);
    cudaGetSymbolAddress((void**)&ps,   g_ps);
    cudaGetSymbolAddress((void**)&wqkv, g_wqkv);
    cudaGetSymbolAddress((void**)&wap,  g_wap);
    cudaGetSymbolAddress((void**)&wfc,  g_wfc);
    cudaGetSymbolAddress((void**)&wpr,  g_wpr);
    cudaGetSymbolAddress((void**)&tokt, g_tokt);

    cudaFuncSetAttribute(flash_h,      cudaFuncAttributeMaxDynamicSharedMemorySize, SMEM_FL);
    cudaFuncSetAttribute(gemm_h,       cudaFuncAttributeMaxDynamicSharedMemorySize, SMEM_GEMM);
    cudaFuncSetAttribute(gemm_h64<1>,  cudaFuncAttributeMaxDynamicSharedMemorySize, SMEM_G64);
    cudaFuncSetAttribute(gemm_h64<2>,  cudaFuncAttributeMaxDynamicSharedMemorySize, SMEM_G64);
    cudaFuncSetAttribute(gemm_lm,      cudaFuncAttributeMaxDynamicSharedMemorySize, SMEM_LM);

    const long long LOGN = (long long)BT * VQ;
    float* out    = (float*)d_out;
    float* logits;
    float* lossp  = nullptr;
    if ((long long)out_size > LOGN) {
        lossp  = out;
        logits = out + ((long long)out_size - LOGN);
    } else if ((long long)out_size == LOGN) {
        logits = out;
    } else {
        lossp  = out;
        logits = lfb;
    }

    // streaming fp16 conversion, native layouts (no transpose)
    {
        int n;
        n = LQ*DQ*3*DQ/4;  cvt_kernel<<<(n+255)/256, 256>>>((const float4*)qkvw, wqkv, n);
        n = LQ*DQ*DQ/4;    cvt_kernel<<<(n+255)/256, 256>>>((const float4*)apw,  wap,  n);
        n = LQ*DQ*4*DQ/4;  cvt_kernel<<<(n+255)/256, 256>>>((const float4*)fcw,  wfc,  n);
        n = LQ*4*DQ*DQ/4;  cvt_kernel<<<(n+255)/256, 256>>>((const float4*)pw,   wpr,  n);
        n = (int)((size_t)VQ*DQ/4); cvt_kernel<<<(n+255)/256, 256>>>((const float4*)tok, tokt, n);
    }

    embed_kernel<<<(BT * DQ + 255) / 256, 256>>>(ids, tok, pos, x);

    for (int l = 0; l < LQ; l++) {
        ln_kernel<<<BT/8, 256>>>(x, ln1w + l * DQ, ln1b + l * DQ, h);
        gemm_h<<<dim3((3 * DQ) / 128, BT / 128), 256, SMEM_GEMM>>>(
            h, wqkv + (size_t)l * DQ * 3 * DQ, qkvb + l * 3 * DQ, qkv, BT, 3 * DQ, DQ);
        flash_h<<<dim3(TQ / 64, HQ, BQ), 128, SMEM_FL>>>(qkv, attn);
        gemm_h64<1><<<dim3(DQ / 64, BT / 64), 128, SMEM_G64>>>(
            attn, wap + (size_t)l * DQ * DQ, apb + l * DQ, x, x, BT, DQ, DQ);
        ln_kernel<<<BT/8, 256>>>(x, ln2w + l * DQ, ln2b + l * DQ, h);
        gemm_h64<2><<<dim3((4 * DQ) / 64, BT / 64), 128, SMEM_G64>>>(
            h, wfc + (size_t)l * DQ * 4 * DQ, fcb + l * 4 * DQ, nullptr, ffn, BT, 4 * DQ, DQ);
        gemm_h64<1><<<dim3(DQ / 64, BT / 64), 128, SMEM_G64>>>(
            ffn, wpr + (size_t)l * 4 * DQ * DQ, pb + l * DQ, x, x, BT, DQ, 4 * DQ);
    }

    ln_kernel<<<BT/8, 256>>>(x, lnfw, lnfb, h);
    gemm_lm<<<dim3(BT / 128, NT_LM), 256, SMEM_LM>>>(
        h, tokt, logits, pm, ps, BT, VQ, DQ);

    if (lossp) {
        nll_reduce<<<BT, 128>>>(pm, ps, logits, tgt, nll);
        loss_kernel<<<1, 1024>>>(nll, lossp);
    }
}

// round 12
// speedup vs baseline: 1.7302x; 1.0188x over previous
#include <cuda_runtime.h>
#include <cuda_fp16.h>
#include <math.h>
#include <stdint.h>

// ---------------- problem constants ----------------
#define BQ 2
#define TQ 1024
#define DQ 768
#define LQ 4
#define HQ 12
#define VQ 50257
#define BT (BQ*TQ)
#define HD 64
#define NT_LM 393   // ceil(VQ/128)
#define NBH (BQ*HQ) // 24
#define NSPL 8      // q-tiles 8..15 are split

// ---------------- scratch ----------------
__device__ float  g_x   [BT*DQ];
__device__ __half g_h   [BT*DQ];
__device__ __half g_qkv [BT*3*DQ];
__device__ __half g_attn[BT*DQ];
__device__ __half g_ffn [BT*4*DQ];
__device__ float  g_nll [BT];
__device__ float  g_pm  [BT*NT_LM];
__device__ float  g_ps  [BT*NT_LM];
__device__ float  g_logits_fb[102926336];
// split-K attention partials: [2 splits][24 bh][8 qtiles][64 rows][64 dims]
__device__ float  g_pO  [2*NBH*NSPL*64*64];
__device__ float2 g_pml [2*NBH*NSPL*64];
// fp16 weight copies in NATIVE [K][N] layout
__device__ __half g_wqkv[LQ*DQ*3*DQ];
__device__ __half g_wap [LQ*DQ*DQ];
__device__ __half g_wfc [LQ*DQ*4*DQ];
__device__ __half g_wpr [LQ*4*DQ*DQ];
__device__ __half g_tokt[(size_t)VQ*DQ];

__device__ __forceinline__ void lse_merge(float& m, float& s, float m2, float s2) {
    float M = fmaxf(m, m2);
    s = s * __expf(m - M) + s2 * __expf(m2 - M);
    m = M;
}

// ---------------- fp16 streaming convert: 8 floats/thread, 16B store ----------------
__global__ void cvt_kernel(const float4* __restrict__ src, uint4* __restrict__ dst, int n8) {
    int i = blockIdx.x * 256 + threadIdx.x;
    if (i >= n8) return;
    float4 a = src[2 * i], b = src[2 * i + 1];
    __half2 h0 = __floats2half2_rn(a.x, a.y);
    __half2 h1 = __floats2half2_rn(a.z, a.w);
    __half2 h2 = __floats2half2_rn(b.x, b.y);
    __half2 h3 = __floats2half2_rn(b.z, b.w);
    dst[i] = make_uint4(*(uint32_t*)&h0, *(uint32_t*)&h1, *(uint32_t*)&h2, *(uint32_t*)&h3);
}

// ---------------- embedding ----------------
__global__ void embed_kernel(const int* __restrict__ ids, const float* __restrict__ tok,
                             const float* __restrict__ pos, float* __restrict__ x) {
    int i = blockIdx.x * 256 + threadIdx.x;
    if (i >= BT * DQ) return;
    int r = i / DQ, d = i - r * DQ;
    x[i] = tok[(size_t)ids[r] * DQ + d] + pos[(r % TQ) * DQ + d];
}

// ---------------- layernorm: warp per row ----------------
__global__ __launch_bounds__(256)
void ln_kernel(const float* __restrict__ x, const float* __restrict__ w,
               const float* __restrict__ b, __half* __restrict__ y) {
    const int wid = threadIdx.x >> 5, lane = threadIdx.x & 31;
    const int row = blockIdx.x * 8 + wid;
    const float* xr = x + (size_t)row * DQ;
    float4 v[6];
    float s = 0.f, q = 0.f;
    #pragma unroll
    for (int i = 0; i < 6; i++) {
        v[i] = *(const float4*)(xr + lane * 4 + i * 128);
        s += v[i].x + v[i].y + v[i].z + v[i].w;
        q += v[i].x * v[i].x + v[i].y * v[i].y + v[i].z * v[i].z + v[i].w * v[i].w;
    }
    #pragma unroll
    for (int o = 16; o > 0; o >>= 1) {
        s += __shfl_xor_sync(0xffffffffu, s, o);
        q += __shfl_xor_sync(0xffffffffu, q, o);
    }
    float mean = s * (1.f / DQ);
    float var  = q * (1.f / DQ) - mean * mean;
    float inv  = rsqrtf(var + 1e-5f);
    __half* yr = y + (size_t)row * DQ;
    #pragma unroll
    for (int i = 0; i < 6; i++) {
        int c = lane * 4 + i * 128;
        float4 wv = *(const float4*)(w + c);
        float4 bv = *(const float4*)(b + c);
        __half2 h0 = __floats2half2_rn((v[i].x - mean) * inv * wv.x + bv.x,
                                       (v[i].y - mean) * inv * wv.y + bv.y);
        __half2 h1 = __floats2half2_rn((v[i].z - mean) * inv * wv.z + bv.z,
                                       (v[i].w - mean) * inv * wv.w + bv.w);
        *(uint2*)(yr + c) = make_uint2(*(uint32_t*)&h0, *(uint32_t*)&h1);
    }
}

// ---------------- fp16 mma / cp.async / ldmatrix helpers ----------------
__device__ __forceinline__ void mma16(float* c, const uint32_t* a, const uint32_t* b) {
    asm volatile("mma.sync.aligned.m16n8k16.row.col.f32.f16.f16.f32 "
                 "{%0,%1,%2,%3}, {%4,%5,%6,%7}, {%8,%9}, {%0,%1,%2,%3};\n"
                 : "+f"(c[0]), "+f"(c[1]), "+f"(c[2]), "+f"(c[3])
                 : "r"(a[0]), "r"(a[1]), "r"(a[2]), "r"(a[3]), "r"(b[0]), "r"(b[1]));
}
__device__ __forceinline__ void cpa16(uint32_t dst, const void* src) {
    asm volatile("cp.async.cg.shared.global [%0], [%1], 16;\n" :: "r"(dst), "l"(src));
}
__device__ __forceinline__ void cpa16z(uint32_t dst, const void* src, int bytes) {
    asm volatile("cp.async.cg.shared.global [%0], [%1], 16, %2;\n" :: "r"(dst), "l"(src), "r"(bytes));
}
__device__ __forceinline__ void ldsm4(uint32_t* r, uint32_t addr) {
    asm volatile("ldmatrix.sync.aligned.m8n8.x4.shared.b16 {%0,%1,%2,%3}, [%4];\n"
                 : "=r"(r[0]), "=r"(r[1]), "=r"(r[2]), "=r"(r[3]) : "r"(addr));
}
__device__ __forceinline__ void ldsm4t(uint32_t* r, uint32_t addr) {
    asm volatile("ldmatrix.sync.aligned.m8n8.x4.trans.shared.b16 {%0,%1,%2,%3}, [%4];\n"
                 : "=r"(r[0]), "=r"(r[1]), "=r"(r[2]), "=r"(r[3]) : "r"(addr));
}
__device__ __forceinline__ uint32_t packh2(float a, float b) {
    __half2 h = __floats2half2_rn(a, b);
    return *(uint32_t*)&h;
}

#define SKH 72
#define SNB 136
#define SNB64 72

// ---------------- 128x128 GEMM (qkv): C = A * W, W native [K][N] ----------------
#define STGA_H   (128*SKH)
#define STGB_H   (32*SNB)
#define SMEM_GEMM ((2*STGA_H + 2*STGB_H)*2)
__global__ __launch_bounds__(256, 2)
void gemm_h(const __half* __restrict__ A, const __half* __restrict__ B,
            const float* __restrict__ bias, __half* __restrict__ C,
            int M, int N, int K) {
    extern __shared__ __half smh[];
    __half* As = smh;
    __half* Bs = smh + 2 * STGA_H;

    const int tid  = threadIdx.x;
    const int lane = tid & 31, wid = tid >> 5;
    const int wm = (wid & 1) * 64, wn = (wid >> 1) * 32;
    const int g = lane >> 2, tq = lane & 3;
    const int m0 = blockIdx.y * 128, n0 = blockIdx.x * 128;

    const uint32_t sAu = (uint32_t)__cvta_generic_to_shared(As);
    const uint32_t sBu = (uint32_t)__cvta_generic_to_shared(Bs);

    const int arow = tid >> 2, acol = (tid & 3) << 3;
    const int brow = tid >> 4, bcol = (tid & 15) << 3;
    const int mrow = lane & 15, khalf = (lane >> 4) << 3;
    const int vkrow = (lane & 7) + ((lane >> 3) & 1) * 8;
    const int vdoff = (lane >> 4) * 8;
    int aoff[4];
    #pragma unroll
    for (int mi = 0; mi < 4; mi++) aoff[mi] = (wm + mi * 16 + mrow) * SKH + khalf;

    auto load_tile = [&](int t) {
        int k0 = t * 32, st = t & 1;
        #pragma unroll
        for (int it = 0; it < 2; it++) {
            int r = arow + it * 64;
            cpa16(sAu + ((st * 128 + r) * SKH + acol) * 2, A + (size_t)(m0 + r) * K + k0 + acol);
            int br = brow + it * 16;
            cpa16(sBu + ((st * 32 + br) * SNB + bcol) * 2, B + (size_t)(k0 + br) * N + n0 + bcol);
        }
    };

    float acc[4][4][4] = {};
    const int nt = K / 32;

    load_tile(0);
    asm volatile("cp.async.commit_group;\n");

    for (int t = 0; t < nt; t++) {
        if (t + 1 < nt) load_tile(t + 1);
        asm volatile("cp.async.commit_group;\n");
        asm volatile("cp.async.wait_group 1;\n");
        __syncthreads();

        const int stA = (t & 1) * STGA_H;
        const int stB = (t & 1) * STGB_H;
        #pragma unroll
        for (int ks = 0; ks < 2; ks++) {
            uint32_t af[4][4], bq[2][4];
            #pragma unroll
            for (int mi = 0; mi < 4; mi++)
                ldsm4(af[mi], sAu + (stA + aoff[mi] + ks * 16) * 2);
            #pragma unroll
            for (int p = 0; p < 2; p++)
                ldsm4t(bq[p], sBu + (stB + (ks * 16 + vkrow) * SNB + wn + p * 16 + vdoff) * 2);
            #pragma unroll
            for (int mi = 0; mi < 4; mi++) {
                #pragma unroll
                for (int ni = 0; ni < 4; ni++) {
                    uint32_t bb[2] = { bq[ni >> 1][(ni & 1) * 2], bq[ni >> 1][(ni & 1) * 2 + 1] };
                    mma16(acc[mi][ni], af[mi], bb);
                }
            }
        }
        __syncthreads();
    }

    #pragma unroll
    for (int mi = 0; mi < 4; mi++) {
        #pragma unroll
        for (int ni = 0; ni < 4; ni++) {
            int m = m0 + wm + mi * 16 + g;
            int n = n0 + wn + ni * 8 + tq * 2;
            #pragma unroll
            for (int half_ = 0; half_ < 2; half_++) {
                int mm = m + half_ * 8;
                float v0 = acc[mi][ni][half_ * 2 + 0] + bias[n + 0];
                float v1 = acc[mi][ni][half_ * 2 + 1] + bias[n + 1];
                *(__half2*)(C + (size_t)mm * N + n) = __floats2half2_rn(v0, v1);
            }
        }
    }
}

// ---------------- 64x64 GEMM, templated epilogue, W native [K][N] ----------------
#define STGA64 (64*SKH)
#define STGB64 (32*SNB64)
#define SMEM_G64 ((2*STGA64 + 2*STGB64)*2)
template<int EPI>   // 1: bias+res -> float, 2: bias+gelu -> half
__global__ __launch_bounds__(128, 6)
void gemm_h64(const __half* __restrict__ A, const __half* __restrict__ B,
              const float* __restrict__ bias, const float* __restrict__ res,
              void* __restrict__ Cv, int M, int N, int K) {
    extern __shared__ __half smh[];
    __half* As = smh;
    __half* Bs = smh + 2 * STGA64;

    const int tid  = threadIdx.x;
    const int lane = tid & 31, wid = tid >> 5;
    const int wm = (wid & 1) * 32, wn = (wid >> 1) * 32;
    const int g = lane >> 2, tq = lane & 3;
    const int m0 = blockIdx.y * 64, n0 = blockIdx.x * 64;

    const uint32_t sAu = (uint32_t)__cvta_generic_to_shared(As);
    const uint32_t sBu = (uint32_t)__cvta_generic_to_shared(Bs);

    const int arow = tid >> 1, acol = (tid & 1) << 4;
    const int brow = tid >> 3, bcol = (tid & 7) << 3;
    const int mrow = lane & 15, khalf = (lane >> 4) << 3;
    const int vkrow = (lane & 7) + ((lane >> 3) & 1) * 8;
    const int vdoff = (lane >> 4) * 8;
    int aoff[2];
    #pragma unroll
    for (int mi = 0; mi < 2; mi++) aoff[mi] = (wm + mi * 16 + mrow) * SKH + khalf;

    auto load_tile = [&](int t) {
        int k0 = t * 32, st = t & 1;
        int r = arow, c8 = acol >> 1;
        cpa16(sAu + ((st * 64 + r) * SKH + c8) * 2, A + (size_t)(m0 + r) * K + k0 + c8);
        cpa16(sAu + ((st * 64 + r) * SKH + c8 + 16) * 2, A + (size_t)(m0 + r) * K + k0 + c8 + 16);
        #pragma unroll
        for (int it = 0; it < 2; it++) {
            int br = brow + it * 16;
            cpa16(sBu + ((st * 32 + br) * SNB64 + bcol) * 2, B + (size_t)(k0 + br) * N + n0 + bcol);
        }
    };

    float acc[2][4][4] = {};
    const int nt = K / 32;

    load_tile(0);
    asm volatile("cp.async.commit_group;\n");

    for (int t = 0; t < nt; t++) {
        if (t + 1 < nt) load_tile(t + 1);
        asm volatile("cp.async.commit_group;\n");
        asm volatile("cp.async.wait_group 1;\n");
        __syncthreads();

        const int stA = (t & 1) * STGA64;
        const int stB = (t & 1) * STGB64;
        #pragma unroll
        for (int ks = 0; ks < 2; ks++) {
            uint32_t af[2][4], bq[2][4];
            #pragma unroll
            for (int mi = 0; mi < 2; mi++)
                ldsm4(af[mi], sAu + (stA + aoff[mi] + ks * 16) * 2);
            #pragma unroll
            for (int p = 0; p < 2; p++)
                ldsm4t(bq[p], sBu + (stB + (ks * 16 + vkrow) * SNB64 + wn + p * 16 + vdoff) * 2);
            #pragma unroll
            for (int mi = 0; mi < 2; mi++) {
                #pragma unroll
                for (int ni = 0; ni < 4; ni++) {
                    uint32_t bb[2] = { bq[ni >> 1][(ni & 1) * 2], bq[ni >> 1][(ni & 1) * 2 + 1] };
                    mma16(acc[mi][ni], af[mi], bb);
                }
            }
        }
        __syncthreads();
    }

    #pragma unroll
    for (int mi = 0; mi < 2; mi++) {
        #pragma unroll
        for (int ni = 0; ni < 4; ni++) {
            int m = m0 + wm + mi * 16 + g;
            int n = n0 + wn + ni * 8 + tq * 2;
            #pragma unroll
            for (int half_ = 0; half_ < 2; half_++) {
                int mm = m + half_ * 8;
                float v0 = acc[mi][ni][half_ * 2 + 0] + bias[n + 0];
                float v1 = acc[mi][ni][half_ * 2 + 1] + bias[n + 1];
                if (EPI == 1) {
                    float2 rr = *(const float2*)((const float*)res + (size_t)mm * N + n);
                    v0 += rr.x; v1 += rr.y;
                    *(float2*)((float*)Cv + (size_t)mm * N + n) = make_float2(v0, v1);
                } else {
                    v0 = 0.5f * v0 * (1.f + erff(v0 * 0.70710678f));
                    v1 = 0.5f * v1 * (1.f + erff(v1 * 0.70710678f));
                    *(__half2*)((__half*)Cv + (size_t)mm * N + n) = __floats2half2_rn(v0, v1);
                }
            }
        }
    }
}

// ---------------- LM-head GEMM (tokt [V][K]) + fused NLL partials ----------------
#define STG_H (128*SKH)
#define SMEM_LM (4*STG_H*2)
__global__ __launch_bounds__(256, 2)
void gemm_lm(const __half* __restrict__ A, const __half* __restrict__ B,
             float* __restrict__ C, float* __restrict__ pm, float* __restrict__ ps,
             int M, int N, int K) {
    extern __shared__ __half smh[];
    __half* As = smh;
    __half* Bs = smh + 2 * STG_H;
    float* sPm = (float*)smh;
    float* sPs = (float*)smh + 512;

    const int tid  = threadIdx.x;
    const int lane = tid & 31, wid = tid >> 5;
    const int wm = (wid & 1) * 64, wn = (wid >> 1) * 32;
    const int g = lane >> 2, tq = lane & 3;
    const int m0 = blockIdx.x * 128, n0 = blockIdx.y * 128;
    const int tileY = blockIdx.y, NTt = gridDim.y;

    const uint32_t sAu = (uint32_t)__cvta_generic_to_shared(As);
    const uint32_t sBu = (uint32_t)__cvta_generic_to_shared(Bs);

    const int arow = tid >> 2, acol = (tid & 3) << 3;
    const int mrow = lane & 15, khalf = (lane >> 4) << 3;
    int aoff[4], boff[2];
    #pragma unroll
    for (int mi = 0; mi < 4; mi++) aoff[mi] = (wm + mi * 16 + mrow) * SKH + khalf;
    #pragma unroll
    for (int p = 0; p < 2; p++)    boff[p]  = (wn + p * 16 + mrow) * SKH + khalf;

    auto load_tile = [&](int t) {
        int k0 = t * 32, st = t & 1;
        #pragma unroll
        for (int it = 0; it < 2; it++) {
            int r = arow + it * 64;
            cpa16(sAu + ((st * 128 + r) * SKH + acol) * 2, A + (size_t)(m0 + r) * K + k0 + acol);
            int n = n0 + r;
            int ok = (n < N);
            cpa16z(sBu + ((st * 128 + r) * SKH + acol) * 2,
                   B + (size_t)(ok ? n : (N - 1)) * K + k0 + acol, ok ? 16 : 0);
        }
    };

    float acc[4][4][4] = {};
    const int nt = K / 32;

    load_tile(0);
    asm volatile("cp.async.commit_group;\n");

    for (int t = 0; t < nt; t++) {
        if (t + 1 < nt) load_tile(t + 1);
        asm volatile("cp.async.commit_group;\n");
        asm volatile("cp.async.wait_group 1;\n");
        __syncthreads();

        const int stO = (t & 1) * STG_H;
        #pragma unroll
        for (int ks = 0; ks < 2; ks++) {
            uint32_t af[4][4], bq[2][4];
            #pragma unroll
            for (int mi = 0; mi < 4; mi++)
                ldsm4(af[mi], sAu + (stO + aoff[mi] + ks * 16) * 2);
            #pragma unroll
            for (int p = 0; p < 2; p++)
                ldsm4(bq[p], sBu + (stO + boff[p] + ks * 16) * 2);
            #pragma unroll
            for (int mi = 0; mi < 4; mi++) {
                #pragma unroll
                for (int ni = 0; ni < 4; ni++) {
                    uint32_t bb[2] = { bq[ni >> 1][ni & 1], bq[ni >> 1][(ni & 1) + 2] };
                    mma16(acc[mi][ni], af[mi], bb);
                }
            }
        }
        __syncthreads();
    }

    #pragma unroll
    for (int mi = 0; mi < 4; mi++) {
        #pragma unroll
        for (int ni = 0; ni < 4; ni++) {
            int m = m0 + wm + mi * 16 + g;
            int n = n0 + wn + ni * 8 + tq * 2;
            #pragma unroll
            for (int half_ = 0; half_ < 2; half_++) {
                int mm = m + half_ * 8;
                #pragma unroll
                for (int e = 0; e < 2; e++) {
                    int nn = n + e;
                    if (nn >= N) continue;
                    C[(size_t)mm * N + nn] = acc[mi][ni][half_ * 2 + e];
                }
            }
        }
    }

    __syncthreads();
    #pragma unroll
    for (int mi = 0; mi < 4; mi++) {
        #pragma unroll
        for (int half_ = 0; half_ < 2; half_++) {
            float lm = -1e30f, lsum = 0.f;
            #pragma unroll
            for (int ni = 0; ni < 4; ni++) {
                #pragma unroll
                for (int e = 0; e < 2; e++) {
                    int nn = n0 + wn + ni * 8 + tq * 2 + e;
                    if (nn < N) lm = fmaxf(lm, acc[mi][ni][half_ * 2 + e]);
                }
            }
            #pragma unroll
            for (int ni = 0; ni < 4; ni++) {
                #pragma unroll
                for (int e = 0; e < 2; e++) {
                    int nn = n0 + wn + ni * 8 + tq * 2 + e;
                    if (nn < N) lsum += __expf(acc[mi][ni][half_ * 2 + e] - lm);
                }
            }
            #pragma unroll
            for (int o = 1; o <= 2; o <<= 1) {
                float m2 = __shfl_xor_sync(0xffffffffu, lm, o);
                float s2 = __shfl_xor_sync(0xffffffffu, lsum, o);
                lse_merge(lm, lsum, m2, s2);
            }
            if (tq == 0) {
                int rl = wm + mi * 16 + half_ * 8 + g;
                sPm[rl * 4 + (wid >> 1)] = lm;
                sPs[rl * 4 + (wid >> 1)] = lsum;
            }
        }
    }
    __syncthreads();
    if (tid < 128) {
        float M_ = sPm[tid * 4], S_ = sPs[tid * 4];
        #pragma unroll
        for (int gi = 1; gi < 4; gi++) lse_merge(M_, S_, sPm[tid * 4 + gi], sPs[tid * 4 + gi]);
        pm[(size_t)(m0 + tid) * NTt + tileY] = M_;
        ps[(size_t)(m0 + tid) * NTt + tileY] = S_;
    }
}

// ---------------- flash attention: register-P + split-K partial softmax ----------------
// grid.x = 24: bx<16 -> qi=bx (full if qi<8, else split1); bx>=16 -> qi=bx-8, split2
#define FQH 72
#define FTILE (64*FQH)
#define SMEM_FL (5*FTILE*2)
__global__ __launch_bounds__(128)
void flash_h(const __half* __restrict__ qkv, __half* __restrict__ out,
             float* __restrict__ pO, float2* __restrict__ pml) {
    extern __shared__ __half smh[];
    __half* Qs = smh;
    const uint32_t sQ = (uint32_t)__cvta_generic_to_shared(Qs);
    const uint32_t sK[2] = { sQ + FTILE * 2,     sQ + 2 * FTILE * 2 };
    const uint32_t sV[2] = { sQ + 3 * FTILE * 2, sQ + 4 * FTILE * 2 };

    const int tid = threadIdx.x;
    const int lane = tid & 31, wid = tid >> 5;
    const int g = lane >> 2, tq = lane & 3;
    const int h = blockIdx.y, b = blockIdx.z;
    const int r0 = wid * 16 + g;

    int qi, kt0, kt1, role;   // 0=full, 1=split1 (no diag), 2=split2 (diag)
    const int bx = blockIdx.x;
    if (bx < 16) {
        qi = bx;
        if (qi < 8) { kt0 = 0; kt1 = qi + 1; role = 0; }
        else        { kt0 = 0; kt1 = (qi + 2) >> 1; role = 1; }
    } else {
        qi = bx - 8;
        kt0 = (qi + 2) >> 1; kt1 = qi + 1; role = 2;
    }
    const int q0 = qi * 64;

    auto loadKV = [&](int t, int st) {
        int k0 = t * 64;
        #pragma unroll
        for (int i = 0; i < 4; i++) {
            int idx = tid + i * 128;
            int r = idx >> 3, c8 = (idx & 7) << 3;
            const __half* src = qkv + (size_t)(b * TQ + k0 + r) * (3 * DQ) + h * HD + c8;
            cpa16(sK[st] + (r * FQH + c8) * 2, src + DQ);
            cpa16(sV[st] + (r * FQH + c8) * 2, src + 2 * DQ);
        }
    };

    const int vkrow = (lane & 7) + ((lane >> 3) & 1) * 8;
    const int vdoff = (lane >> 4) * 8;

    const __half2 sc8 = __floats2half2_rn(0.125f, 0.125f);
    #pragma unroll
    for (int i = 0; i < 4; i++) {
        int idx = tid + i * 128;
        int r = idx >> 3, c8 = (idx & 7) << 3;
        uint4 raw = *(const uint4*)(qkv + (size_t)(b * TQ + q0 + r) * (3 * DQ) + h * HD + c8);
        __half2* hp = (__half2*)&raw;
        hp[0] = __hmul2(hp[0], sc8); hp[1] = __hmul2(hp[1], sc8);
        hp[2] = __hmul2(hp[2], sc8); hp[3] = __hmul2(hp[3], sc8);
        *(uint4*)(Qs + r * FQH + c8) = raw;
    }

    loadKV(kt0, 0);
    asm volatile("cp.async.commit_group;\n");
    __syncthreads();

    uint32_t qf[4][4];
    #pragma unroll
    for (int kk = 0; kk < 4; kk++) {
        qf[kk][0] = *(const uint32_t*)(Qs + r0 * FQH + kk * 16 + 2 * tq);
        qf[kk][1] = *(const uint32_t*)(Qs + (r0 + 8) * FQH + kk * 16 + 2 * tq);
        qf[kk][2] = *(const uint32_t*)(Qs + r0 * FQH + kk * 16 + 8 + 2 * tq);
        qf[kk][3] = *(const uint32_t*)(Qs + (r0 + 8) * FQH + kk * 16 + 8 + 2 * tq);
    }

    float m0r = -1e30f, m1r = -1e30f, l0 = 0.f, l1 = 0.f;
    float oc[8][4] = {};

    for (int kt = kt0; kt < kt1; kt++) {
        const int li = kt - kt0;
        const int st = li & 1;
        if (kt + 1 < kt1) {
            loadKV(kt + 1, st ^ 1);
            asm volatile("cp.async.commit_group;\n");
            asm volatile("cp.async.wait_group 1;\n");
        } else {
            asm volatile("cp.async.wait_group 0;\n");
        }
        __syncthreads();

        const __half* Kb = (const __half*)((const char*)smh + (sK[st] - sQ));
        float sc[8][4] = {};
        #pragma unroll
        for (int kk = 0; kk < 4; kk++) {
            #pragma unroll
            for (int ni = 0; ni < 8; ni++) {
                uint32_t bb[2];
                bb[0] = *(const uint32_t*)(Kb + (ni * 8 + g) * FQH + kk * 16 + 2 * tq);
                bb[1] = *(const uint32_t*)(Kb + (ni * 8 + g) * FQH + kk * 16 + 8 + 2 * tq);
                mma16(sc[ni], qf[kk], bb);
            }
        }

        if (role != 1 && kt == kt1 - 1) {  // diagonal tile
            #pragma unroll
            for (int ni = 0; ni < 8; ni++) {
                int c0 = ni * 8 + 2 * tq, c1 = c0 + 1;
                if (c0 > r0) sc[ni][0] = -1e30f;
                if (c1 > r0) sc[ni][1] = -1e30f;
                if (c0 > r0 + 8) sc[ni][2] = -1e30f;
                if (c1 > r0 + 8) sc[ni][3] = -1e30f;
            }
        }

        float mx0 = -1e30f, mx1 = -1e30f;
        #pragma unroll
        for (int ni = 0; ni < 8; ni++) {
            mx0 = fmaxf(mx0, fmaxf(sc[ni][0], sc[ni][1]));
            mx1 = fmaxf(mx1, fmaxf(sc[ni][2], sc[ni][3]));
        }
        #pragma unroll
        for (int o = 1; o <= 2; o <<= 1) {
            mx0 = fmaxf(mx0, __shfl_xor_sync(0xffffffffu, mx0, o));
            mx1 = fmaxf(mx1, __shfl_xor_sync(0xffffffffu, mx1, o));
        }
        float nm0 = fmaxf(m0r, mx0), nm1 = fmaxf(m1r, mx1);
        float cr0 = __expf(m0r - nm0), cr1 = __expf(m1r - nm1);
        float rs0 = 0.f, rs1 = 0.f;
        #pragma unroll
        for (int ni = 0; ni < 8; ni++) {
            sc[ni][0] = __expf(sc[ni][0] - nm0); rs0 += sc[ni][0];
            sc[ni][1] = __expf(sc[ni][1] - nm0); rs0 += sc[ni][1];
            sc[ni][2] = __expf(sc[ni][2] - nm1); rs1 += sc[ni][2];
            sc[ni][3] = __expf(sc[ni][3] - nm1); rs1 += sc[ni][3];
        }
        #pragma unroll
        for (int o = 1; o <= 2; o <<= 1) {
            rs0 += __shfl_xor_sync(0xffffffffu, rs0, o);
            rs1 += __shfl_xor_sync(0xffffffffu, rs1, o);
        }
        l0 = l0 * cr0 + rs0; l1 = l1 * cr1 + rs1;
        m0r = nm0; m1r = nm1;
        #pragma unroll
        for (int ni = 0; ni < 8; ni++) {
            oc[ni][0] *= cr0; oc[ni][1] *= cr0;
            oc[ni][2] *= cr1; oc[ni][3] *= cr1;
        }

        #pragma unroll
        for (int kk = 0; kk < 4; kk++) {
            uint32_t a[4];
            a[0] = packh2(sc[2 * kk][0],     sc[2 * kk][1]);
            a[1] = packh2(sc[2 * kk][2],     sc[2 * kk][3]);
            a[2] = packh2(sc[2 * kk + 1][0], sc[2 * kk + 1][1]);
            a[3] = packh2(sc[2 * kk + 1][2], sc[2 * kk + 1][3]);
            #pragma unroll
            for (int pr = 0; pr < 4; pr++) {
                uint32_t v4[4];
                ldsm4t(v4, sV[st] + ((kk * 16 + vkrow) * FQH + pr * 16 + vdoff) * 2);
                uint32_t b0[2] = { v4[0], v4[1] };
                uint32_t b1[2] = { v4[2], v4[3] };
                mma16(oc[pr * 2 + 0], a, b0);
                mma16(oc[pr * 2 + 1], a, b1);
            }
        }
        __syncthreads();
    }

    if (role == 0) {
        float i0 = 1.f / l0, i1 = 1.f / l1;
        __half* o0 = out + (size_t)(b * TQ + q0 + r0) * DQ + h * HD;
        __half* o1 = out + (size_t)(b * TQ + q0 + r0 + 8) * DQ + h * HD;
        #pragma unroll
        for (int ni = 0; ni < 8; ni++) {
            *(__half2*)(o0 + ni * 8 + 2 * tq) = __floats2half2_rn(oc[ni][0] * i0, oc[ni][1] * i0);
            *(__half2*)(o1 + ni * 8 + 2 * tq) = __floats2half2_rn(oc[ni][2] * i1, oc[ni][3] * i1);
        }
    } else {
        const int split = role - 1;
        const int sidx = (b * HQ + h) * NSPL + (qi - 8);
        float* Od = pO + ((size_t)split * NBH * NSPL + sidx) * 4096;
        #pragma unroll
        for (int ni = 0; ni < 8; ni++) {
            int c = ni * 8 + 2 * tq;
            *(float2*)(Od + r0 * 64 + c)       = make_float2(oc[ni][0], oc[ni][1]);
            *(float2*)(Od + (r0 + 8) * 64 + c) = make_float2(oc[ni][2], oc[ni][3]);
        }
        if (tq == 0) {
            float2* Ml = pml + ((size_t)split * NBH * NSPL + sidx) * 64;
            Ml[r0]     = make_float2(m0r, l0);
            Ml[r0 + 8] = make_float2(m1r, l1);
        }
    }
}

// ---------------- split-K combine ----------------
__global__ __launch_bounds__(256)
void flash_combine(const float* __restrict__ pO, const float2* __restrict__ pml,
                   __half* __restrict__ out) {
    const int qi8 = blockIdx.x;             // 0..7 -> qi = qi8+8
    const int h = blockIdx.y, b = blockIdx.z;
    const int sidx = (b * HQ + h) * NSPL + qi8;
    const int t = threadIdx.x;
    const int row = t >> 2, c0 = (t & 3) * 16;

    float2 ml1 = pml[(size_t)sidx * 64 + row];
    float2 ml2 = pml[((size_t)NBH * NSPL + sidx) * 64 + row];
    float M = fmaxf(ml1.x, ml2.x);
    float w1 = __expf(ml1.x - M), w2 = __expf(ml2.x - M);
    float inv = 1.f / (ml1.y * w1 + ml2.y * w2);
    const float* O1 = pO + (size_t)sidx * 4096 + row * 64;
    const float* O2 = pO + ((size_t)NBH * NSPL + sidx) * 4096 + row * 64;
    __half* o = out + (size_t)(b * TQ + (qi8 + 8) * 64 + row) * DQ + h * HD;
    #pragma unroll
    for (int c = 0; c < 16; c += 2) {
        float2 a = *(const float2*)(O1 + c0 + c);
        float2 d = *(const float2*)(O2 + c0 + c);
        float v0 = (a.x * w1 + d.x * w2) * inv;
        float v1 = (a.y * w1 + d.y * w2) * inv;
        *(__half2*)(o + c0 + c) = __floats2half2_rn(v0, v1);
    }
}

// ---------------- NLL reduce + loss ----------------
__global__ void nll_reduce(const float* __restrict__ pm, const float* __restrict__ ps,
                           const float* __restrict__ logits, const int* __restrict__ tgt,
                           float* __restrict__ nll) {
    int row = blockIdx.x, t = threadIdx.x;
    float M = -1e30f, S = 0.f;
    for (int j = t; j < NT_LM; j += 128)
        lse_merge(M, S, pm[(size_t)row * NT_LM + j], ps[(size_t)row * NT_LM + j]);
    __shared__ float sm_[128], ss_[128];
    sm_[t] = M; ss_[t] = S; __syncthreads();
    for (int o = 64; o > 0; o >>= 1) {
        if (t < o) {
            float mm = sm_[t], ssv = ss_[t];
            lse_merge(mm, ssv, sm_[t + o], ss_[t + o]);
            sm_[t] = mm; ss_[t] = ssv;
        }
        __syncthreads();
    }
    if (t == 0) {
        float lse = sm_[0] + logf(ss_[0]);
        nll[row] = lse - logits[(size_t)row * VQ + tgt[row]];
    }
}
__global__ void loss_kernel(const float* __restrict__ nll, float* __restrict__ loss) {
    __shared__ float s[1024];
    float v = nll[threadIdx.x] + nll[threadIdx.x + 1024];
    s[threadIdx.x] = v; __syncthreads();
    for (int o = 512; o > 0; o >>= 1) {
        if (threadIdx.x < o) s[threadIdx.x] += s[threadIdx.x + o];
        __syncthreads();
    }
    if (threadIdx.x == 0) *loss = s[0] * (1.f / 2048.f);
}

// ---------------- launch ----------------
extern "C" void kernel_launch(void* const* d_in, const int* in_sizes, int n_in,
                              void* d_out, int out_size) {
    const int*   ids  = (const int*)d_in[0];
    const int*   tgt  = (const int*)d_in[1];
    const float* tok  = (const float*)d_in[2];
    const float* pos  = (const float*)d_in[3];
    const float* ln1w = (const float*)d_in[4];
    const float* ln1b = (const float*)d_in[5];
    const float* qkvw = (const float*)d_in[6];
    const float* qkvb = (const float*)d_in[7];
    const float* apw  = (const float*)d_in[8];
    const float* apb  = (const float*)d_in[9];
    const float* ln2w = (const float*)d_in[10];
    const float* ln2b = (const float*)d_in[11];
    const float* fcw  = (const float*)d_in[12];
    const float* fcb  = (const float*)d_in[13];
    const float* pw   = (const float*)d_in[14];
    const float* pb   = (const float*)d_in[15];
    const float* lnfw = (const float*)d_in[16];
    const float* lnfb = (const float*)d_in[17];

    float *x, *nll, *lfb, *pm, *ps, *pO;
    float2* pml;
    __half *h, *qkv, *attn, *ffn;
    __half *wqkv, *wap, *wfc, *wpr, *tokt;
    cudaGetSymbolAddress((void**)&x,    g_x);
    cudaGetSymbolAddress((void**)&h,    g_h);
    cudaGetSymbolAddress((void**)&qkv,  g_qkv);
    cudaGetSymbolAddress((void**)&attn, g_attn);
    cudaGetSymbolAddress((void**)&ffn,  g_ffn);
    cudaGetSymbolAddress((void**)&nll,  g_nll);
    cudaGetSymbolAddress((void**)&lfb,  g_logits_fb);
    cudaGetSymbolAddress((void**)&pm,   g_pm);
    cudaGetSymbolAddress((void**)&ps,   g_ps);
    cudaGetSymbolAddress((void**)&pO,   g_pO);
    cudaGetSymbolAddress((void**)&pml,  g_pml);
    cudaGetSymbolAddress((void**)&wqkv, g_wqkv);
    cudaGetSymbolAddress((void**)&wap,  g_wap);
    cudaGetSymbolAddress((void**)&wfc,  g_wfc);
    cudaGetSymbolAddress((void**)&wpr,  g_wpr);
    cudaGetSymbolAddress((void**)&tokt, g_tokt);

    cudaFuncSetAttribute(flash_h,      cudaFuncAttributeMaxDynamicSharedMemorySize, SMEM_FL);
    cudaFuncSetAttribute(gemm_h,       cudaFuncAttributeMaxDynamicSharedMemorySize, SMEM_GEMM);
    cudaFuncSetAttribute(gemm_h64<1>,  cudaFuncAttributeMaxDynamicSharedMemorySize, SMEM_G64);
    cudaFuncSetAttribute(gemm_h64<2>,  cudaFuncAttributeMaxDynamicSharedMemorySize, SMEM_G64);
    cudaFuncSetAttribute(gemm_lm,      cudaFuncAttributeMaxDynamicSharedMemorySize, SMEM_LM);

    const long long LOGN = (long long)BT * VQ;
    float* out    = (float*)d_out;
    float* logits;
    float* lossp  = nullptr;
    if ((long long)out_size > LOGN) {
        lossp  = out;
        logits = out + ((long long)out_size - LOGN);
    } else if ((long long)out_size == LOGN) {
        logits = out;
    } else {
        lossp  = out;
        logits = lfb;
    }

    {   // streaming fp16 conversion, native layouts
        int n;
        n = LQ*DQ*3*DQ/8;  cvt_kernel<<<(n+255)/256, 256>>>((const float4*)qkvw, (uint4*)wqkv, n);
        n = LQ*DQ*DQ/8;    cvt_kernel<<<(n+255)/256, 256>>>((const float4*)apw,  (uint4*)wap,  n);
        n = LQ*DQ*4*DQ/8;  cvt_kernel<<<(n+255)/256, 256>>>((const float4*)fcw,  (uint4*)wfc,  n);
        n = LQ*4*DQ*DQ/8;  cvt_kernel<<<(n+255)/256, 256>>>((const float4*)pw,   (uint4*)wpr,  n);
        n = (int)((size_t)VQ*DQ/8); cvt_kernel<<<(n+255)/256, 256>>>((const float4*)tok, (uint4*)tokt, n);
    }

    embed_kernel<<<(BT * DQ + 255) / 256, 256>>>(ids, tok, pos, x);

    for (int l = 0; l < LQ; l++) {
        ln_kernel<<<BT/8, 256>>>(x, ln1w + l * DQ, ln1b + l * DQ, h);
        gemm_h<<<dim3((3 * DQ) / 128, BT / 128), 256, SMEM_GEMM>>>(
            h, wqkv + (size_t)l * DQ * 3 * DQ, qkvb + l * 3 * DQ, qkv, BT, 3 * DQ, DQ);
        flash_h<<<dim3(TQ / 64 + NSPL, HQ, BQ), 128, SMEM_FL>>>(qkv, attn, pO, pml);
        flash_combine<<<dim3(NSPL, HQ, BQ), 256>>>(pO, pml, attn);
        gemm_h64<1><<<dim3(DQ / 64, BT / 64), 128, SMEM_G64>>>(
            attn, wap + (size_t)l * DQ * DQ, apb + l * DQ, x, x, BT, DQ, DQ);
        ln_kernel<<<BT/8, 256>>>(x, ln2w + l * DQ, ln2b + l * DQ, h);
        gemm_h64<2><<<dim3((4 * DQ) / 64, BT / 64), 128, SMEM_G64>>>(
            h, wfc + (size_t)l * DQ * 4 * DQ, fcb + l * 4 * DQ, nullptr, ffn, BT, 4 * DQ, DQ);
        gemm_h64<1><<<dim3(DQ / 64, BT / 64), 128, SMEM_G64>>>(
            ffn, wpr + (size_t)l * 4 * DQ * DQ, pb + l * DQ, x, x, BT, DQ, 4 * DQ);
    }

    ln_kernel<<<BT/8, 256>>>(x, lnfw, lnfb, h);
    gemm_lm<<<dim3(BT / 128, NT_LM), 256, SMEM_LM>>>(
        h, tokt, logits, pm, ps, BT, VQ, DQ);

    if (lossp) {
        nll_reduce<<<BT, 128>>>(pm, ps, logits, tgt, nll);
        loss_kernel<<<1, 1024>>>(nll, lossp);
    }
}

// round 14
// speedup vs baseline: 1.7483x; 1.0105x over previous
#include <cuda_runtime.h>
#include <cuda_fp16.h>
#include <math.h>
#include <stdint.h>

// ---------------- problem constants ----------------
#define BQ 2
#define TQ 1024
#define DQ 768
#define LQ 4
#define HQ 12
#define VQ 50257
#define BT (BQ*TQ)
#define HD 64
#define NT_LM 393
#define NBH (BQ*HQ)
#define NSPL 8

// ---------------- scratch ----------------
__device__ float  g_x   [BT*DQ];
__device__ __half g_h   [BT*DQ];
__device__ __half g_qkv [BT*3*DQ];
__device__ __half g_attn[BT*DQ];
__device__ __half g_ffn [BT*4*DQ];
__device__ float  g_nll [BT];
__device__ float  g_pm  [BT*NT_LM];
__device__ float  g_ps  [BT*NT_LM];
__device__ float  g_logits_fb[102926336];
__device__ float  g_pO  [2*NBH*NSPL*64*64];
__device__ float2 g_pml [2*NBH*NSPL*64];
__device__ __half g_wqkv[LQ*DQ*3*DQ];
__device__ __half g_wap [LQ*DQ*DQ];
__device__ __half g_wfc [LQ*DQ*4*DQ];
__device__ __half g_wpr [LQ*4*DQ*DQ];
__device__ __half g_tokt[(size_t)VQ*DQ];

__device__ __forceinline__ void lse_merge(float& m, float& s, float m2, float s2) {
    float M = fmaxf(m, m2);
    s = s * __expf(m - M) + s2 * __expf(m2 - M);
    m = M;
}

// ---------------- merged fp16 convert: all 5 weight tensors, one launch ----------------
#define CV0 884736    // qkv
#define CV1 294912    // ap
#define CV2 1179648   // fc
#define CV3 1179648   // pr
#define CV4 4824672   // tok
#define CVT_TOT (CV0+CV1+CV2+CV3+CV4)
__global__ void cvt_all(const float4* __restrict__ s0, const float4* __restrict__ s1,
                        const float4* __restrict__ s2, const float4* __restrict__ s3,
                        const float4* __restrict__ s4,
                        uint4* __restrict__ d0, uint4* __restrict__ d1,
                        uint4* __restrict__ d2, uint4* __restrict__ d3,
                        uint4* __restrict__ d4) {
    int i = blockIdx.x * 256 + threadIdx.x;
    if (i >= CVT_TOT) return;
    const float4* s; uint4* d; int off = i;
    if (off < CV0) { s = s0; d = d0; }
    else if ((off -= CV0) < CV1) { s = s1; d = d1; }
    else if ((off -= CV1) < CV2) { s = s2; d = d2; }
    else if ((off -= CV2) < CV3) { s = s3; d = d3; }
    else { off -= CV3; s = s4; d = d4; }
    float4 a = s[2 * off], b = s[2 * off + 1];
    __half2 h0 = __floats2half2_rn(a.x, a.y);
    __half2 h1 = __floats2half2_rn(a.z, a.w);
    __half2 h2 = __floats2half2_rn(b.x, b.y);
    __half2 h3 = __floats2half2_rn(b.z, b.w);
    d[off] = make_uint4(*(uint32_t*)&h0, *(uint32_t*)&h1, *(uint32_t*)&h2, *(uint32_t*)&h3);
}

// ---------------- fused embedding + layernorm (layer 0) ----------------
__global__ __launch_bounds__(256)
void embedln_kernel(const int* __restrict__ ids, const float* __restrict__ tok,
                    const float* __restrict__ pos, const float* __restrict__ w,
                    const float* __restrict__ b, float* __restrict__ x,
                    __half* __restrict__ y) {
    const int wid = threadIdx.x >> 5, lane = threadIdx.x & 31;
    const int row = blockIdx.x * 8 + wid;
    const float* te = tok + (size_t)ids[row] * DQ;
    const float* pe = pos + (size_t)(row % TQ) * DQ;
    float4 v[6];
    float s = 0.f, q = 0.f;
    #pragma unroll
    for (int i = 0; i < 6; i++) {
        int c = lane * 4 + i * 128;
        float4 t = *(const float4*)(te + c);
        float4 p = *(const float4*)(pe + c);
        v[i] = make_float4(t.x + p.x, t.y + p.y, t.z + p.z, t.w + p.w);
        *(float4*)(x + (size_t)row * DQ + c) = v[i];
        s += v[i].x + v[i].y + v[i].z + v[i].w;
        q += v[i].x * v[i].x + v[i].y * v[i].y + v[i].z * v[i].z + v[i].w * v[i].w;
    }
    #pragma unroll
    for (int o = 16; o > 0; o >>= 1) {
        s += __shfl_xor_sync(0xffffffffu, s, o);
        q += __shfl_xor_sync(0xffffffffu, q, o);
    }
    float mean = s * (1.f / DQ);
    float var  = q * (1.f / DQ) - mean * mean;
    float inv  = rsqrtf(var + 1e-5f);
    __half* yr = y + (size_t)row * DQ;
    #pragma unroll
    for (int i = 0; i < 6; i++) {
        int c = lane * 4 + i * 128;
        float4 wv = *(const float4*)(w + c);
        float4 bv = *(const float4*)(b + c);
        __half2 h0 = __floats2half2_rn((v[i].x - mean) * inv * wv.x + bv.x,
                                       (v[i].y - mean) * inv * wv.y + bv.y);
        __half2 h1 = __floats2half2_rn((v[i].z - mean) * inv * wv.z + bv.z,
                                       (v[i].w - mean) * inv * wv.w + bv.w);
        *(uint2*)(yr + c) = make_uint2(*(uint32_t*)&h0, *(uint32_t*)&h1);
    }
}

// ---------------- layernorm: warp per row ----------------
__global__ __launch_bounds__(256)
void ln_kernel(const float* __restrict__ x, const float* __restrict__ w,
               const float* __restrict__ b, __half* __restrict__ y) {
    const int wid = threadIdx.x >> 5, lane = threadIdx.x & 31;
    const int row = blockIdx.x * 8 + wid;
    const float* xr = x + (size_t)row * DQ;
    float4 v[6];
    float s = 0.f, q = 0.f;
    #pragma unroll
    for (int i = 0; i < 6; i++) {
        v[i] = *(const float4*)(xr + lane * 4 + i * 128);
        s += v[i].x + v[i].y + v[i].z + v[i].w;
        q += v[i].x * v[i].x + v[i].y * v[i].y + v[i].z * v[i].z + v[i].w * v[i].w;
    }
    #pragma unroll
    for (int o = 16; o > 0; o >>= 1) {
        s += __shfl_xor_sync(0xffffffffu, s, o);
        q += __shfl_xor_sync(0xffffffffu, q, o);
    }
    float mean = s * (1.f / DQ);
    float var  = q * (1.f / DQ) - mean * mean;
    float inv  = rsqrtf(var + 1e-5f);
    __half* yr = y + (size_t)row * DQ;
    #pragma unroll
    for (int i = 0; i < 6; i++) {
        int c = lane * 4 + i * 128;
        float4 wv = *(const float4*)(w + c);
        float4 bv = *(const float4*)(b + c);
        __half2 h0 = __floats2half2_rn((v[i].x - mean) * inv * wv.x + bv.x,
                                       (v[i].y - mean) * inv * wv.y + bv.y);
        __half2 h1 = __floats2half2_rn((v[i].z - mean) * inv * wv.z + bv.z,
                                       (v[i].w - mean) * inv * wv.w + bv.w);
        *(uint2*)(yr + c) = make_uint2(*(uint32_t*)&h0, *(uint32_t*)&h1);
    }
}

// ---------------- fp16 mma / cp.async / ldmatrix helpers ----------------
__device__ __forceinline__ void mma16(float* c, const uint32_t* a, const uint32_t* b) {
    asm volatile("mma.sync.aligned.m16n8k16.row.col.f32.f16.f16.f32 "
                 "{%0,%1,%2,%3}, {%4,%5,%6,%7}, {%8,%9}, {%0,%1,%2,%3};\n"
                 : "+f"(c[0]), "+f"(c[1]), "+f"(c[2]), "+f"(c[3])
                 : "r"(a[0]), "r"(a[1]), "r"(a[2]), "r"(a[3]), "r"(b[0]), "r"(b[1]));
}
__device__ __forceinline__ void cpa16(uint32_t dst, const void* src) {
    asm volatile("cp.async.cg.shared.global [%0], [%1], 16;\n" :: "r"(dst), "l"(src));
}
__device__ __forceinline__ void cpa16z(uint32_t dst, const void* src, int bytes) {
    asm volatile("cp.async.cg.shared.global [%0], [%1], 16, %2;\n" :: "r"(dst), "l"(src), "r"(bytes));
}
__device__ __forceinline__ void ldsm4(uint32_t* r, uint32_t addr) {
    asm volatile("ldmatrix.sync.aligned.m8n8.x4.shared.b16 {%0,%1,%2,%3}, [%4];\n"
                 : "=r"(r[0]), "=r"(r[1]), "=r"(r[2]), "=r"(r[3]) : "r"(addr));
}
__device__ __forceinline__ void ldsm4t(uint32_t* r, uint32_t addr) {
    asm volatile("ldmatrix.sync.aligned.m8n8.x4.trans.shared.b16 {%0,%1,%2,%3}, [%4];\n"
                 : "=r"(r[0]), "=r"(r[1]), "=r"(r[2]), "=r"(r[3]) : "r"(addr));
}
__device__ __forceinline__ uint32_t packh2(float a, float b) {
    __half2 h = __floats2half2_rn(a, b);
    return *(uint32_t*)&h;
}

#define SKH 72
#define SNB 136
#define SNB64 72

// ---------------- 128x128 GEMM (qkv): C = A * W, W native [K][N] ----------------
#define STGA_H   (128*SKH)
#define STGB_H   (32*SNB)
#define SMEM_GEMM ((2*STGA_H + 2*STGB_H)*2)
__global__ __launch_bounds__(256, 2)
void gemm_h(const __half* __restrict__ A, const __half* __restrict__ B,
            const float* __restrict__ bias, __half* __restrict__ C,
            int M, int N, int K) {
    extern __shared__ __half smh[];
    __half* As = smh;
    __half* Bs = smh + 2 * STGA_H;

    const int tid  = threadIdx.x;
    const int lane = tid & 31, wid = tid >> 5;
    const int wm = (wid & 1) * 64, wn = (wid >> 1) * 32;
    const int g = lane >> 2, tq = lane & 3;
    const int m0 = blockIdx.y * 128, n0 = blockIdx.x * 128;

    const uint32_t sAu = (uint32_t)__cvta_generic_to_shared(As);
    const uint32_t sBu = (uint32_t)__cvta_generic_to_shared(Bs);

    const int arow = tid >> 2, acol = (tid & 3) << 3;
    const int brow = tid >> 4, bcol = (tid & 15) << 3;
    const int mrow = lane & 15, khalf = (lane >> 4) << 3;
    const int vkrow = (lane & 7) + ((lane >> 3) & 1) * 8;
    const int vdoff = (lane >> 4) * 8;
    int aoff[4];
    #pragma unroll
    for (int mi = 0; mi < 4; mi++) aoff[mi] = (wm + mi * 16 + mrow) * SKH + khalf;

    auto load_tile = [&](int t) {
        int k0 = t * 32, st = t & 1;
        #pragma unroll
        for (int it = 0; it < 2; it++) {
            int r = arow + it * 64;
            cpa16(sAu + ((st * 128 + r) * SKH + acol) * 2, A + (size_t)(m0 + r) * K + k0 + acol);
            int br = brow + it * 16;
            cpa16(sBu + ((st * 32 + br) * SNB + bcol) * 2, B + (size_t)(k0 + br) * N + n0 + bcol);
        }
    };

    float acc[4][4][4] = {};
    const int nt = K / 32;

    load_tile(0);
    asm volatile("cp.async.commit_group;\n");

    for (int t = 0; t < nt; t++) {
        if (t + 1 < nt) load_tile(t + 1);
        asm volatile("cp.async.commit_group;\n");
        asm volatile("cp.async.wait_group 1;\n");
        __syncthreads();

        const int stA = (t & 1) * STGA_H;
        const int stB = (t & 1) * STGB_H;
        #pragma unroll
        for (int ks = 0; ks < 2; ks++) {
            uint32_t af[4][4], bq[2][4];
            #pragma unroll
            for (int mi = 0; mi < 4; mi++)
                ldsm4(af[mi], sAu + (stA + aoff[mi] + ks * 16) * 2);
            #pragma unroll
            for (int p = 0; p < 2; p++)
                ldsm4t(bq[p], sBu + (stB + (ks * 16 + vkrow) * SNB + wn + p * 16 + vdoff) * 2);
            #pragma unroll
            for (int mi = 0; mi < 4; mi++) {
                #pragma unroll
                for (int ni = 0; ni < 4; ni++) {
                    uint32_t bb[2] = { bq[ni >> 1][(ni & 1) * 2], bq[ni >> 1][(ni & 1) * 2 + 1] };
                    mma16(acc[mi][ni], af[mi], bb);
                }
            }
        }
        __syncthreads();
    }

    #pragma unroll
    for (int mi = 0; mi < 4; mi++) {
        #pragma unroll
        for (int ni = 0; ni < 4; ni++) {
            int m = m0 + wm + mi * 16 + g;
            int n = n0 + wn + ni * 8 + tq * 2;
            #pragma unroll
            for (int half_ = 0; half_ < 2; half_++) {
                int mm = m + half_ * 8;
                float v0 = acc[mi][ni][half_ * 2 + 0] + bias[n + 0];
                float v1 = acc[mi][ni][half_ * 2 + 1] + bias[n + 1];
                *(__half2*)(C + (size_t)mm * N + n) = __floats2half2_rn(v0, v1);
            }
        }
    }
}

// ---------------- 64x64 GEMM, templated epilogue, W native [K][N] ----------------
#define STGA64 (64*SKH)
#define STGB64 (32*SNB64)
#define SMEM_G64 ((2*STGA64 + 2*STGB64)*2)
template<int EPI>   // 1: bias+res -> float, 2: bias+gelu -> half
__global__ __launch_bounds__(128, 6)
void gemm_h64(const __half* __restrict__ A, const __half* __restrict__ B,
              const float* __restrict__ bias, const float* __restrict__ res,
              void* __restrict__ Cv, int M, int N, int K) {
    extern __shared__ __half smh[];
    __half* As = smh;
    __half* Bs = smh + 2 * STGA64;

    const int tid  = threadIdx.x;
    const int lane = tid & 31, wid = tid >> 5;
    const int wm = (wid & 1) * 32, wn = (wid >> 1) * 32;
    const int g = lane >> 2, tq = lane & 3;
    const int m0 = blockIdx.y * 64, n0 = blockIdx.x * 64;

    const uint32_t sAu = (uint32_t)__cvta_generic_to_shared(As);
    const uint32_t sBu = (uint32_t)__cvta_generic_to_shared(Bs);

    const int arow = tid >> 1, acol = (tid & 1) << 4;
    const int brow = tid >> 3, bcol = (tid & 7) << 3;
    const int mrow = lane & 15, khalf = (lane >> 4) << 3;
    const int vkrow = (lane & 7) + ((lane >> 3) & 1) * 8;
    const int vdoff = (lane >> 4) * 8;
    int aoff[2];
    #pragma unroll
    for (int mi = 0; mi < 2; mi++) aoff[mi] = (wm + mi * 16 + mrow) * SKH + khalf;

    auto load_tile = [&](int t) {
        int k0 = t * 32, st = t & 1;
        int r = arow, c8 = acol >> 1;
        cpa16(sAu + ((st * 64 + r) * SKH + c8) * 2, A + (size_t)(m0 + r) * K + k0 + c8);
        cpa16(sAu + ((st * 64 + r) * SKH + c8 + 16) * 2, A + (size_t)(m0 + r) * K + k0 + c8 + 16);
        #pragma unroll
        for (int it = 0; it < 2; it++) {
            int br = brow + it * 16;
            cpa16(sBu + ((st * 32 + br) * SNB64 + bcol) * 2, B + (size_t)(k0 + br) * N + n0 + bcol);
        }
    };

    float acc[2][4][4] = {};
    const int nt = K / 32;

    load_tile(0);
    asm volatile("cp.async.commit_group;\n");

    for (int t = 0; t < nt; t++) {
        if (t + 1 < nt) load_tile(t + 1);
        asm volatile("cp.async.commit_group;\n");
        asm volatile("cp.async.wait_group 1;\n");
        __syncthreads();

        const int stA = (t & 1) * STGA64;
        const int stB = (t & 1) * STGB64;
        #pragma unroll
        for (int ks = 0; ks < 2; ks++) {
            uint32_t af[2][4], bq[2][4];
            #pragma unroll
            for (int mi = 0; mi < 2; mi++)
                ldsm4(af[mi], sAu + (stA + aoff[mi] + ks * 16) * 2);
            #pragma unroll
            for (int p = 0; p < 2; p++)
                ldsm4t(bq[p], sBu + (stB + (ks * 16 + vkrow) * SNB64 + wn + p * 16 + vdoff) * 2);
            #pragma unroll
            for (int mi = 0; mi < 2; mi++) {
                #pragma unroll
                for (int ni = 0; ni < 4; ni++) {
                    uint32_t bb[2] = { bq[ni >> 1][(ni & 1) * 2], bq[ni >> 1][(ni & 1) * 2 + 1] };
                    mma16(acc[mi][ni], af[mi], bb);
                }
            }
        }
        __syncthreads();
    }

    #pragma unroll
    for (int mi = 0; mi < 2; mi++) {
        #pragma unroll
        for (int ni = 0; ni < 4; ni++) {
            int m = m0 + wm + mi * 16 + g;
            int n = n0 + wn + ni * 8 + tq * 2;
            #pragma unroll
            for (int half_ = 0; half_ < 2; half_++) {
                int mm = m + half_ * 8;
                float v0 = acc[mi][ni][half_ * 2 + 0] + bias[n + 0];
                float v1 = acc[mi][ni][half_ * 2 + 1] + bias[n + 1];
                if (EPI == 1) {
                    float2 rr = *(const float2*)((const float*)res + (size_t)mm * N + n);
                    v0 += rr.x; v1 += rr.y;
                    *(float2*)((float*)Cv + (size_t)mm * N + n) = make_float2(v0, v1);
                } else {
                    v0 = 0.5f * v0 * (1.f + erff(v0 * 0.70710678f));
                    v1 = 0.5f * v1 * (1.f + erff(v1 * 0.70710678f));
                    *(__half2*)((__half*)Cv + (size_t)mm * N + n) = __floats2half2_rn(v0, v1);
                }
            }
        }
    }
}

// ---------------- LM-head GEMM (tokt [V][K]) + fused NLL partials ----------------
#define STG_H (128*SKH)
#define SMEM_LM (4*STG_H*2)
__global__ __launch_bounds__(256, 2)
void gemm_lm(const __half* __restrict__ A, const __half* __restrict__ B,
             float* __restrict__ C, float* __restrict__ pm, float* __restrict__ ps,
             int M, int N, int K) {
    extern __shared__ __half smh[];
    __half* As = smh;
    __half* Bs = smh + 2 * STG_H;
    float* sPm = (float*)smh;
    float* sPs = (float*)smh + 512;

    const int tid  = threadIdx.x;
    const int lane = tid & 31, wid = tid >> 5;
    const int wm = (wid & 1) * 64, wn = (wid >> 1) * 32;
    const int g = lane >> 2, tq = lane & 3;
    const int m0 = blockIdx.x * 128, n0 = blockIdx.y * 128;
    const int tileY = blockIdx.y, NTt = gridDim.y;

    const uint32_t sAu = (uint32_t)__cvta_generic_to_shared(As);
    const uint32_t sBu = (uint32_t)__cvta_generic_to_shared(Bs);

    const int arow = tid >> 2, acol = (tid & 3) << 3;
    const int mrow = lane & 15, khalf = (lane >> 4) << 3;
    int aoff[4], boff[2];
    #pragma unroll
    for (int mi = 0; mi < 4; mi++) aoff[mi] = (wm + mi * 16 + mrow) * SKH + khalf;
    #pragma unroll
    for (int p = 0; p < 2; p++)    boff[p]  = (wn + p * 16 + mrow) * SKH + khalf;

    auto load_tile = [&](int t) {
        int k0 = t * 32, st = t & 1;
        #pragma unroll
        for (int it = 0; it < 2; it++) {
            int r = arow + it * 64;
            cpa16(sAu + ((st * 128 + r) * SKH + acol) * 2, A + (size_t)(m0 + r) * K + k0 + acol);
            int n = n0 + r;
            int ok = (n < N);
            cpa16z(sBu + ((st * 128 + r) * SKH + acol) * 2,
                   B + (size_t)(ok ? n : (N - 1)) * K + k0 + acol, ok ? 16 : 0);
        }
    };

    float acc[4][4][4] = {};
    const int nt = K / 32;

    load_tile(0);
    asm volatile("cp.async.commit_group;\n");

    for (int t = 0; t < nt; t++) {
        if (t + 1 < nt) load_tile(t + 1);
        asm volatile("cp.async.commit_group;\n");
        asm volatile("cp.async.wait_group 1;\n");
        __syncthreads();

        const int stO = (t & 1) * STG_H;
        #pragma unroll
        for (int ks = 0; ks < 2; ks++) {
            uint32_t af[4][4], bq[2][4];
            #pragma unroll
            for (int mi = 0; mi < 4; mi++)
                ldsm4(af[mi], sAu + (stO + aoff[mi] + ks * 16) * 2);
            #pragma unroll
            for (int p = 0; p < 2; p++)
                ldsm4(bq[p], sBu + (stO + boff[p] + ks * 16) * 2);
            #pragma unroll
            for (int mi = 0; mi < 4; mi++) {
                #pragma unroll
                for (int ni = 0; ni < 4; ni++) {
                    uint32_t bb[2] = { bq[ni >> 1][ni & 1], bq[ni >> 1][(ni & 1) + 2] };
                    mma16(acc[mi][ni], af[mi], bb);
                }
            }
        }
        __syncthreads();
    }

    // scalar stores (row stride N=50257 is odd: vector stores would misalign)
    #pragma unroll
    for (int mi = 0; mi < 4; mi++) {
        #pragma unroll
        for (int ni = 0; ni < 4; ni++) {
            int m = m0 + wm + mi * 16 + g;
            int n = n0 + wn + ni * 8 + tq * 2;
            #pragma unroll
            for (int half_ = 0; half_ < 2; half_++) {
                int mm = m + half_ * 8;
                #pragma unroll
                for (int e = 0; e < 2; e++) {
                    int nn = n + e;
                    if (nn >= N) continue;
                    C[(size_t)mm * N + nn] = acc[mi][ni][half_ * 2 + e];
                }
            }
        }
    }

    __syncthreads();
    #pragma unroll
    for (int mi = 0; mi < 4; mi++) {
        #pragma unroll
        for (int half_ = 0; half_ < 2; half_++) {
            float lm = -1e30f, lsum = 0.f;
            #pragma unroll
            for (int ni = 0; ni < 4; ni++) {
                #pragma unroll
                for (int e = 0; e < 2; e++) {
                    int nn = n0 + wn + ni * 8 + tq * 2 + e;
                    if (nn < N) lm = fmaxf(lm, acc[mi][ni][half_ * 2 + e]);
                }
            }
            #pragma unroll
            for (int ni = 0; ni < 4; ni++) {
                #pragma unroll
                for (int e = 0; e < 2; e++) {
                    int nn = n0 + wn + ni * 8 + tq * 2 + e;
                    if (nn < N) lsum += __expf(acc[mi][ni][half_ * 2 + e] - lm);
                }
            }
            #pragma unroll
            for (int o = 1; o <= 2; o <<= 1) {
                float m2 = __shfl_xor_sync(0xffffffffu, lm, o);
                float s2 = __shfl_xor_sync(0xffffffffu, lsum, o);
                lse_merge(lm, lsum, m2, s2);
            }
            if (tq == 0) {
                int rl = wm + mi * 16 + half_ * 8 + g;
                sPm[rl * 4 + (wid >> 1)] = lm;
                sPs[rl * 4 + (wid >> 1)] = lsum;
            }
        }
    }
    __syncthreads();
    if (tid < 128) {
        float M_ = sPm[tid * 4], S_ = sPs[tid * 4];
        #pragma unroll
        for (int gi = 1; gi < 4; gi++) lse_merge(M_, S_, sPm[tid * 4 + gi], sPs[tid * 4 + gi]);
        pm[(size_t)(m0 + tid) * NTt + tileY] = M_;
        ps[(size_t)(m0 + tid) * NTt + tileY] = S_;
    }
}

// ---------------- flash attention: register-P + split-K partial softmax ----------------
#define FQH 72
#define FTILE (64*FQH)
#define SMEM_FL (5*FTILE*2)
__global__ __launch_bounds__(128)
void flash_h(const __half* __restrict__ qkv, __half* __restrict__ out,
             float* __restrict__ pO, float2* __restrict__ pml) {
    extern __shared__ __half smh[];
    __half* Qs = smh;
    const uint32_t sQ = (uint32_t)__cvta_generic_to_shared(Qs);
    const uint32_t sK[2] = { sQ + FTILE * 2,     sQ + 2 * FTILE * 2 };
    const uint32_t sV[2] = { sQ + 3 * FTILE * 2, sQ + 4 * FTILE * 2 };

    const int tid = threadIdx.x;
    const int lane = tid & 31, wid = tid >> 5;
    const int g = lane >> 2, tq = lane & 3;
    const int h = blockIdx.y, b = blockIdx.z;
    const int r0 = wid * 16 + g;

    int qi, kt0, kt1, role;
    const int bx = blockIdx.x;
    if (bx < 16) {
        qi = bx;
        if (qi < 8) { kt0 = 0; kt1 = qi + 1; role = 0; }
        else        { kt0 = 0; kt1 = (qi + 2) >> 1; role = 1; }
    } else {
        qi = bx - 8;
        kt0 = (qi + 2) >> 1; kt1 = qi + 1; role = 2;
    }
    const int q0 = qi * 64;

    auto loadKV = [&](int t, int st) {
        int k0 = t * 64;
        #pragma unroll
        for (int i = 0; i < 4; i++) {
            int idx = tid + i * 128;
            int r = idx >> 3, c8 = (idx & 7) << 3;
            const __half* src = qkv + (size_t)(b * TQ + k0 + r) * (3 * DQ) + h * HD + c8;
            cpa16(sK[st] + (r * FQH + c8) * 2, src + DQ);
            cpa16(sV[st] + (r * FQH + c8) * 2, src + 2 * DQ);
        }
    };

    const int vkrow = (lane & 7) + ((lane >> 3) & 1) * 8;
    const int vdoff = (lane >> 4) * 8;

    const __half2 sc8 = __floats2half2_rn(0.125f, 0.125f);
    #pragma unroll
    for (int i = 0; i < 4; i++) {
        int idx = tid + i * 128;
        int r = idx >> 3, c8 = (idx & 7) << 3;
        uint4 raw = *(const uint4*)(qkv + (size_t)(b * TQ + q0 + r) * (3 * DQ) + h * HD + c8);
        __half2* hp = (__half2*)&raw;
        hp[0] = __hmul2(hp[0], sc8); hp[1] = __hmul2(hp[1], sc8);
        hp[2] = __hmul2(hp[2], sc8); hp[3] = __hmul2(hp[3], sc8);
        *(uint4*)(Qs + r * FQH + c8) = raw;
    }

    loadKV(kt0, 0);
    asm volatile("cp.async.commit_group;\n");
    __syncthreads();

    uint32_t qf[4][4];
    #pragma unroll
    for (int kk = 0; kk < 4; kk++) {
        qf[kk][0] = *(const uint32_t*)(Qs + r0 * FQH + kk * 16 + 2 * tq);
        qf[kk][1] = *(const uint32_t*)(Qs + (r0 + 8) * FQH + kk * 16 + 2 * tq);
        qf[kk][2] = *(const uint32_t*)(Qs + r0 * FQH + kk * 16 + 8 + 2 * tq);
        qf[kk][3] = *(const uint32_t*)(Qs + (r0 + 8) * FQH + kk * 16 + 8 + 2 * tq);
    }

    float m0r = -1e30f, m1r = -1e30f, l0 = 0.f, l1 = 0.f;
    float oc[8][4] = {};

    for (int kt = kt0; kt < kt1; kt++) {
        const int li = kt - kt0;
        const int st = li & 1;
        if (kt + 1 < kt1) {
            loadKV(kt + 1, st ^ 1);
            asm volatile("cp.async.commit_group;\n");
            asm volatile("cp.async.wait_group 1;\n");
        } else {
            asm volatile("cp.async.wait_group 0;\n");
        }
        __syncthreads();

        const __half* Kb = (const __half*)((const char*)smh + (sK[st] - sQ));
        float sc[8][4] = {};
        #pragma unroll
        for (int kk = 0; kk < 4; kk++) {
            #pragma unroll
            for (int ni = 0; ni < 8; ni++) {
                uint32_t bb[2];
                bb[0] = *(const uint32_t*)(Kb + (ni * 8 + g) * FQH + kk * 16 + 2 * tq);
                bb[1] = *(const uint32_t*)(Kb + (ni * 8 + g) * FQH + kk * 16 + 8 + 2 * tq);
                mma16(sc[ni], qf[kk], bb);
            }
        }

        if (role != 1 && kt == kt1 - 1) {
            #pragma unroll
            for (int ni = 0; ni < 8; ni++) {
                int c0 = ni * 8 + 2 * tq, c1 = c0 + 1;
                if (c0 > r0) sc[ni][0] = -1e30f;
                if (c1 > r0) sc[ni][1] = -1e30f;
                if (c0 > r0 + 8) sc[ni][2] = -1e30f;
                if (c1 > r0 + 8) sc[ni][3] = -1e30f;
            }
        }

        float mx0 = -1e30f, mx1 = -1e30f;
        #pragma unroll
        for (int ni = 0; ni < 8; ni++) {
            mx0 = fmaxf(mx0, fmaxf(sc[ni][0], sc[ni][1]));
            mx1 = fmaxf(mx1, fmaxf(sc[ni][2], sc[ni][3]));
        }
        #pragma unroll
        for (int o = 1; o <= 2; o <<= 1) {
            mx0 = fmaxf(mx0, __shfl_xor_sync(0xffffffffu, mx0, o));
            mx1 = fmaxf(mx1, __shfl_xor_sync(0xffffffffu, mx1, o));
        }
        float nm0 = fmaxf(m0r, mx0), nm1 = fmaxf(m1r, mx1);
        float cr0 = __expf(m0r - nm0), cr1 = __expf(m1r - nm1);
        float rs0 = 0.f, rs1 = 0.f;
        #pragma unroll
        for (int ni = 0; ni < 8; ni++) {
            sc[ni][0] = __expf(sc[ni][0] - nm0); rs0 += sc[ni][0];
            sc[ni][1] = __expf(sc[ni][1] - nm0); rs0 += sc[ni][1];
            sc[ni][2] = __expf(sc[ni][2] - nm1); rs1 += sc[ni][2];
            sc[ni][3] = __expf(sc[ni][3] - nm1); rs1 += sc[ni][3];
        }
        #pragma unroll
        for (int o = 1; o <= 2; o <<= 1) {
            rs0 += __shfl_xor_sync(0xffffffffu, rs0, o);
            rs1 += __shfl_xor_sync(0xffffffffu, rs1, o);
        }
        l0 = l0 * cr0 + rs0; l1 = l1 * cr1 + rs1;
        m0r = nm0; m1r = nm1;
        #pragma unroll
        for (int ni = 0; ni < 8; ni++) {
            oc[ni][0] *= cr0; oc[ni][1] *= cr0;
            oc[ni][2] *= cr1; oc[ni][3] *= cr1;
        }

        #pragma unroll
        for (int kk = 0; kk < 4; kk++) {
            uint32_t a[4];
            a[0] = packh2(sc[2 * kk][0],     sc[2 * kk][1]);
            a[1] = packh2(sc[2 * kk][2],     sc[2 * kk][3]);
            a[2] = packh2(sc[2 * kk + 1][0], sc[2 * kk + 1][1]);
            a[3] = packh2(sc[2 * kk + 1][2], sc[2 * kk + 1][3]);
            #pragma unroll
            for (int pr = 0; pr < 4; pr++) {
                uint32_t v4[4];
                ldsm4t(v4, sV[st] + ((kk * 16 + vkrow) * FQH + pr * 16 + vdoff) * 2);
                uint32_t b0[2] = { v4[0], v4[1] };
                uint32_t b1[2] = { v4[2], v4[3] };
                mma16(oc[pr * 2 + 0], a, b0);
                mma16(oc[pr * 2 + 1], a, b1);
            }
        }
        __syncthreads();
    }

    if (role == 0) {
        float i0 = 1.f / l0, i1 = 1.f / l1;
        __half* o0 = out + (size_t)(b * TQ + q0 + r0) * DQ + h * HD;
        __half* o1 = out + (size_t)(b * TQ + q0 + r0 + 8) * DQ + h * HD;
        #pragma unroll
        for (int ni = 0; ni < 8; ni++) {
            *(__half2*)(o0 + ni * 8 + 2 * tq) = __floats2half2_rn(oc[ni][0] * i0, oc[ni][1] * i0);
            *(__half2*)(o1 + ni * 8 + 2 * tq) = __floats2half2_rn(oc[ni][2] * i1, oc[ni][3] * i1);
        }
    } else {
        const int split = role - 1;
        const int sidx = (b * HQ + h) * NSPL + (qi - 8);
        float* Od = pO + ((size_t)split * NBH * NSPL + sidx) * 4096;
        #pragma unroll
        for (int ni = 0; ni < 8; ni++) {
            int c = ni * 8 + 2 * tq;
            *(float2*)(Od + r0 * 64 + c)       = make_float2(oc[ni][0], oc[ni][1]);
            *(float2*)(Od + (r0 + 8) * 64 + c) = make_float2(oc[ni][2], oc[ni][3]);
        }
        if (tq == 0) {
            float2* Ml = pml + ((size_t)split * NBH * NSPL + sidx) * 64;
            Ml[r0]     = make_float2(m0r, l0);
            Ml[r0 + 8] = make_float2(m1r, l1);
        }
    }
}

// ---------------- split-K combine ----------------
__global__ __launch_bounds__(256)
void flash_combine(const float* __restrict__ pO, const float2* __restrict__ pml,
                   __half* __restrict__ out) {
    const int qi8 = blockIdx.x;
    const int h = blockIdx.y, b = blockIdx.z;
    const int sidx = (b * HQ + h) * NSPL + qi8;
    const int t = threadIdx.x;
    const int row = t >> 2, c0 = (t & 3) * 16;

    float2 ml1 = pml[(size_t)sidx * 64 + row];
    float2 ml2 = pml[((size_t)NBH * NSPL + sidx) * 64 + row];
    float M = fmaxf(ml1.x, ml2.x);
    float w1 = __expf(ml1.x - M), w2 = __expf(ml2.x - M);
    float inv = 1.f / (ml1.y * w1 + ml2.y * w2);
    const float* O1 = pO + (size_t)sidx * 4096 + row * 64;
    const float* O2 = pO + ((size_t)NBH * NSPL + sidx) * 4096 + row * 64;
    __half* o = out + (size_t)(b * TQ + (qi8 + 8) * 64 + row) * DQ + h * HD;
    #pragma unroll
    for (int c = 0; c < 16; c += 2) {
        float2 a = *(const float2*)(O1 + c0 + c);
        float2 d = *(const float2*)(O2 + c0 + c);
        float v0 = (a.x * w1 + d.x * w2) * inv;
        float v1 = (a.y * w1 + d.y * w2) * inv;
        *(__half2*)(o + c0 + c) = __floats2half2_rn(v0, v1);
    }
}

// ---------------- NLL reduce + loss ----------------
__global__ void nll_reduce(const float* __restrict__ pm, const float* __restrict__ ps,
                           const float* __restrict__ logits, const int* __restrict__ tgt,
                           float* __restrict__ nll) {
    int row = blockIdx.x, t = threadIdx.x;
    float M = -1e30f, S = 0.f;
    for (int j = t; j < NT_LM; j += 128)
        lse_merge(M, S, pm[(size_t)row * NT_LM + j], ps[(size_t)row * NT_LM + j]);
    __shared__ float sm_[128], ss_[128];
    sm_[t] = M; ss_[t] = S; __syncthreads();
    for (int o = 64; o > 0; o >>= 1) {
        if (t < o) {
            float mm = sm_[t], ssv = ss_[t];
            lse_merge(mm, ssv, sm_[t + o], ss_[t + o]);
            sm_[t] = mm; ss_[t] = ssv;
        }
        __syncthreads();
    }
    if (t == 0) {
        float lse = sm_[0] + logf(ss_[0]);
        nll[row] = lse - logits[(size_t)row * VQ + tgt[row]];
    }
}
__global__ void loss_kernel(const float* __restrict__ nll, float* __restrict__ loss) {
    __shared__ float s[1024];
    float v = nll[threadIdx.x] + nll[threadIdx.x + 1024];
    s[threadIdx.x] = v; __syncthreads();
    for (int o = 512; o > 0; o >>= 1) {
        if (threadIdx.x < o) s[threadIdx.x] += s[threadIdx.x + o];
        __syncthreads();
    }
    if (threadIdx.x == 0) *loss = s[0] * (1.f / 2048.f);
}

// ---------------- launch ----------------
extern "C" void kernel_launch(void* const* d_in, const int* in_sizes, int n_in,
                              void* d_out, int out_size) {
    const int*   ids  = (const int*)d_in[0];
    const int*   tgt  = (const int*)d_in[1];
    const float* tok  = (const float*)d_in[2];
    const float* pos  = (const float*)d_in[3];
    const float* ln1w = (const float*)d_in[4];
    const float* ln1b = (const float*)d_in[5];
    const float* qkvw = (const float*)d_in[6];
    const float* qkvb = (const float*)d_in[7];
    const float* apw  = (const float*)d_in[8];
    const float* apb  = (const float*)d_in[9];
    const float* ln2w = (const float*)d_in[10];
    const float* ln2b = (const float*)d_in[11];
    const float* fcw  = (const float*)d_in[12];
    const float* fcb  = (const float*)d_in[13];
    const float* pw   = (const float*)d_in[14];
    const float* pb   = (const float*)d_in[15];
    const float* lnfw = (const float*)d_in[16];
    const float* lnfb = (const float*)d_in[17];

    float *x, *nll, *lfb, *pm, *ps, *pO;
    float2* pml;
    __half *h, *qkv, *attn, *ffn;
    __half *wqkv, *wap, *wfc, *wpr, *tokt;
    cudaGetSymbolAddress((void**)&x,    g_x);
    cudaGetSymbolAddress((void**)&h,    g_h);
    cudaGetSymbolAddress((void**)&qkv,  g_qkv);
    cudaGetSymbolAddress((void**)&attn, g_attn);
    cudaGetSymbolAddress((void**)&ffn,  g_ffn);
    cudaGetSymbolAddress((void**)&nll,  g_nll);
    cudaGetSymbolAddress((void**)&lfb,  g_logits_fb);
    cudaGetSymbolAddress((void**)&pm,   g_pm);
    cudaGetSymbolAddress((void**)&ps,   g_ps);
    cudaGetSymbolAddress((void**)&pO,   g_pO);
    cudaGetSymbolAddress((void**)&pml,  g_pml);
    cudaGetSymbolAddress((void**)&wqkv, g_wqkv);
    cudaGetSymbolAddress((void**)&wap,  g_wap);
    cudaGetSymbolAddress((void**)&wfc,  g_wfc);
    cudaGetSymbolAddress((void**)&wpr,  g_wpr);
    cudaGetSymbolAddress((void**)&tokt, g_tokt);

    cudaFuncSetAttribute(flash_h,      cudaFuncAttributeMaxDynamicSharedMemorySize, SMEM_FL);
    cudaFuncSetAttribute(gemm_h,       cudaFuncAttributeMaxDynamicSharedMemorySize, SMEM_GEMM);
    cudaFuncSetAttribute(gemm_h64<1>,  cudaFuncAttributeMaxDynamicSharedMemorySize, SMEM_G64);
    cudaFuncSetAttribute(gemm_h64<2>,  cudaFuncAttributeMaxDynamicSharedMemorySize, SMEM_G64);
    cudaFuncSetAttribute(gemm_lm,      cudaFuncAttributeMaxDynamicSharedMemorySize, SMEM_LM);

    const long long LOGN = (long long)BT * VQ;
    float* out    = (float*)d_out;
    float* logits;
    float* lossp  = nullptr;
    if ((long long)out_size > LOGN) {
        lossp  = out;
        logits = out + ((long long)out_size - LOGN);
    } else if ((long long)out_size == LOGN) {
        logits = out;
    } else {
        lossp  = out;
        logits = lfb;
    }

    cvt_all<<<(CVT_TOT + 255) / 256, 256>>>(
        (const float4*)qkvw, (const float4*)apw, (const float4*)fcw,
        (const float4*)pw,   (const float4*)tok,
        (uint4*)wqkv, (uint4*)wap, (uint4*)wfc, (uint4*)wpr, (uint4*)tokt);

    for (int l = 0; l < LQ; l++) {
        if (l == 0)
            embedln_kernel<<<BT/8, 256>>>(ids, tok, pos, ln1w, ln1b, x, h);
        else
            ln_kernel<<<BT/8, 256>>>(x, ln1w + l * DQ, ln1b + l * DQ, h);
        gemm_h<<<dim3((3 * DQ) / 128, BT / 128), 256, SMEM_GEMM>>>(
            h, wqkv + (size_t)l * DQ * 3 * DQ, qkvb + l * 3 * DQ, qkv, BT, 3 * DQ, DQ);
        flash_h<<<dim3(TQ / 64 + NSPL, HQ, BQ), 128, SMEM_FL>>>(qkv, attn, pO, pml);
        flash_combine<<<dim3(NSPL, HQ, BQ), 256>>>(pO, pml, attn);
        gemm_h64<1><<<dim3(DQ / 64, BT / 64), 128, SMEM_G64>>>(
            attn, wap + (size_t)l * DQ * DQ, apb + l * DQ, x, x, BT, DQ, DQ);
        ln_kernel<<<BT/8, 256>>>(x, ln2w + l * DQ, ln2b + l * DQ, h);
        gemm_h64<2><<<dim3((4 * DQ) / 64, BT / 64), 128, SMEM_G64>>>(
            h, wfc + (size_t)l * DQ * 4 * DQ, fcb + l * 4 * DQ, nullptr, ffn, BT, 4 * DQ, DQ);
        gemm_h64<1><<<dim3(DQ / 64, BT / 64), 128, SMEM_G64>>>(
            ffn, wpr + (size_t)l * 4 * DQ * DQ, pb + l * DQ, x, x, BT, DQ, 4 * DQ);
    }

    ln_kernel<<<BT/8, 256>>>(x, lnfw, lnfb, h);
    gemm_lm<<<dim3(BT / 128, NT_LM), 256, SMEM_LM>>>(
        h, tokt, logits, pm, ps, BT, VQ, DQ);

    if (lossp) {
        nll_reduce<<<BT, 128>>>(pm, ps, logits, tgt, nll);
        loss_kernel<<<1, 1024>>>(nll, lossp);
    }
}

// round 15
// speedup vs baseline: 1.7557x; 1.0042x over previous
#include <cuda_runtime.h>
#include <cuda_fp16.h>
#include <math.h>
#include <stdint.h>

// ---------------- problem constants ----------------
#define BQ 2
#define TQ 1024
#define DQ 768
#define LQ 4
#define HQ 12
#define VQ 50257
#define BT (BQ*TQ)
#define HD 64
#define NT_LM 393
#define NBH (BQ*HQ)
#define NSPL 8

// ---------------- scratch ----------------
__device__ float  g_x   [BT*DQ];
__device__ __half g_h   [BT*DQ];
__device__ __half g_qkv [BT*3*DQ];
__device__ __half g_attn[BT*DQ];
__device__ __half g_ffn [BT*4*DQ];
__device__ float  g_nll [BT];
__device__ float  g_pm  [BT*NT_LM];
__device__ float  g_ps  [BT*NT_LM];
__device__ float  g_logits_fb[102926336];
__device__ float  g_pO  [NBH*NSPL*64*64];
__device__ float2 g_pml [NBH*NSPL*64];
__device__ int    g_flag[NBH*NSPL];      // zero-init; generation cycles 1..4 per pass
__device__ __half g_wqkv[LQ*DQ*3*DQ];
__device__ __half g_wap [LQ*DQ*DQ];
__device__ __half g_wfc [LQ*DQ*4*DQ];
__device__ __half g_wpr [LQ*4*DQ*DQ];
__device__ __half g_tokt[(size_t)VQ*DQ];

__device__ __forceinline__ void lse_merge(float& m, float& s, float m2, float s2) {
    float M = fmaxf(m, m2);
    s = s * __expf(m - M) + s2 * __expf(m2 - M);
    m = M;
}

// ---------------- merged fp16 convert: all 5 weight tensors, one launch ----------------
#define CV0 884736
#define CV1 294912
#define CV2 1179648
#define CV3 1179648
#define CV4 4824672
#define CVT_TOT (CV0+CV1+CV2+CV3+CV4)
__global__ void cvt_all(const float4* __restrict__ s0, const float4* __restrict__ s1,
                        const float4* __restrict__ s2, const float4* __restrict__ s3,
                        const float4* __restrict__ s4,
                        uint4* __restrict__ d0, uint4* __restrict__ d1,
                        uint4* __restrict__ d2, uint4* __restrict__ d3,
                        uint4* __restrict__ d4) {
    int i = blockIdx.x * 256 + threadIdx.x;
    if (i >= CVT_TOT) return;
    const float4* s; uint4* d; int off = i;
    if (off < CV0) { s = s0; d = d0; }
    else if ((off -= CV0) < CV1) { s = s1; d = d1; }
    else if ((off -= CV1) < CV2) { s = s2; d = d2; }
    else if ((off -= CV2) < CV3) { s = s3; d = d3; }
    else { off -= CV3; s = s4; d = d4; }
    float4 a = s[2 * off], b = s[2 * off + 1];
    __half2 h0 = __floats2half2_rn(a.x, a.y);
    __half2 h1 = __floats2half2_rn(a.z, a.w);
    __half2 h2 = __floats2half2_rn(b.x, b.y);
    __half2 h3 = __floats2half2_rn(b.z, b.w);
    d[off] = make_uint4(*(uint32_t*)&h0, *(uint32_t*)&h1, *(uint32_t*)&h2, *(uint32_t*)&h3);
}

// ---------------- fused embedding + layernorm (layer 0) ----------------
__global__ __launch_bounds__(256)
void embedln_kernel(const int* __restrict__ ids, const float* __restrict__ tok,
                    const float* __restrict__ pos, const float* __restrict__ w,
                    const float* __restrict__ b, float* __restrict__ x,
                    __half* __restrict__ y) {
    const int wid = threadIdx.x >> 5, lane = threadIdx.x & 31;
    const int row = blockIdx.x * 8 + wid;
    const float* te = tok + (size_t)ids[row] * DQ;
    const float* pe = pos + (size_t)(row % TQ) * DQ;
    float4 v[6];
    float s = 0.f, q = 0.f;
    #pragma unroll
    for (int i = 0; i < 6; i++) {
        int c = lane * 4 + i * 128;
        float4 t = *(const float4*)(te + c);
        float4 p = *(const float4*)(pe + c);
        v[i] = make_float4(t.x + p.x, t.y + p.y, t.z + p.z, t.w + p.w);
        *(float4*)(x + (size_t)row * DQ + c) = v[i];
        s += v[i].x + v[i].y + v[i].z + v[i].w;
        q += v[i].x * v[i].x + v[i].y * v[i].y + v[i].z * v[i].z + v[i].w * v[i].w;
    }
    #pragma unroll
    for (int o = 16; o > 0; o >>= 1) {
        s += __shfl_xor_sync(0xffffffffu, s, o);
        q += __shfl_xor_sync(0xffffffffu, q, o);
    }
    float mean = s * (1.f / DQ);
    float var  = q * (1.f / DQ) - mean * mean;
    float inv  = rsqrtf(var + 1e-5f);
    __half* yr = y + (size_t)row * DQ;
    #pragma unroll
    for (int i = 0; i < 6; i++) {
        int c = lane * 4 + i * 128;
        float4 wv = *(const float4*)(w + c);
        float4 bv = *(const float4*)(b + c);
        __half2 h0 = __floats2half2_rn((v[i].x - mean) * inv * wv.x + bv.x,
                                       (v[i].y - mean) * inv * wv.y + bv.y);
        __half2 h1 = __floats2half2_rn((v[i].z - mean) * inv * wv.z + bv.z,
                                       (v[i].w - mean) * inv * wv.w + bv.w);
        *(uint2*)(yr + c) = make_uint2(*(uint32_t*)&h0, *(uint32_t*)&h1);
    }
}

// ---------------- layernorm: warp per row ----------------
__global__ __launch_bounds__(256)
void ln_kernel(const float* __restrict__ x, const float* __restrict__ w,
               const float* __restrict__ b, __half* __restrict__ y) {
    const int wid = threadIdx.x >> 5, lane = threadIdx.x & 31;
    const int row = blockIdx.x * 8 + wid;
    const float* xr = x + (size_t)row * DQ;
    float4 v[6];
    float s = 0.f, q = 0.f;
    #pragma unroll
    for (int i = 0; i < 6; i++) {
        v[i] = *(const float4*)(xr + lane * 4 + i * 128);
        s += v[i].x + v[i].y + v[i].z + v[i].w;
        q += v[i].x * v[i].x + v[i].y * v[i].y + v[i].z * v[i].z + v[i].w * v[i].w;
    }
    #pragma unroll
    for (int o = 16; o > 0; o >>= 1) {
        s += __shfl_xor_sync(0xffffffffu, s, o);
        q += __shfl_xor_sync(0xffffffffu, q, o);
    }
    float mean = s * (1.f / DQ);
    float var  = q * (1.f / DQ) - mean * mean;
    float inv  = rsqrtf(var + 1e-5f);
    __half* yr = y + (size_t)row * DQ;
    #pragma unroll
    for (int i = 0; i < 6; i++) {
        int c = lane * 4 + i * 128;
        float4 wv = *(const float4*)(w + c);
        float4 bv = *(const float4*)(b + c);
        __half2 h0 = __floats2half2_rn((v[i].x - mean) * inv * wv.x + bv.x,
                                       (v[i].y - mean) * inv * wv.y + bv.y);
        __half2 h1 = __floats2half2_rn((v[i].z - mean) * inv * wv.z + bv.z,
                                       (v[i].w - mean) * inv * wv.w + bv.w);
        *(uint2*)(yr + c) = make_uint2(*(uint32_t*)&h0, *(uint32_t*)&h1);
    }
}

// ---------------- fp16 mma / cp.async / ldmatrix helpers ----------------
__device__ __forceinline__ void mma16(float* c, const uint32_t* a, const uint32_t* b) {
    asm volatile("mma.sync.aligned.m16n8k16.row.col.f32.f16.f16.f32 "
                 "{%0,%1,%2,%3}, {%4,%5,%6,%7}, {%8,%9}, {%0,%1,%2,%3};\n"
                 : "+f"(c[0]), "+f"(c[1]), "+f"(c[2]), "+f"(c[3])
                 : "r"(a[0]), "r"(a[1]), "r"(a[2]), "r"(a[3]), "r"(b[0]), "r"(b[1]));
}
__device__ __forceinline__ void cpa16(uint32_t dst, const void* src) {
    asm volatile("cp.async.cg.shared.global [%0], [%1], 16;\n" :: "r"(dst), "l"(src));
}
__device__ __forceinline__ void cpa16z(uint32_t dst, const void* src, int bytes) {
    asm volatile("cp.async.cg.shared.global [%0], [%1], 16, %2;\n" :: "r"(dst), "l"(src), "r"(bytes));
}
__device__ __forceinline__ void ldsm4(uint32_t* r, uint32_t addr) {
    asm volatile("ldmatrix.sync.aligned.m8n8.x4.shared.b16 {%0,%1,%2,%3}, [%4];\n"
                 : "=r"(r[0]), "=r"(r[1]), "=r"(r[2]), "=r"(r[3]) : "r"(addr));
}
__device__ __forceinline__ void ldsm4t(uint32_t* r, uint32_t addr) {
    asm volatile("ldmatrix.sync.aligned.m8n8.x4.trans.shared.b16 {%0,%1,%2,%3}, [%4];\n"
                 : "=r"(r[0]), "=r"(r[1]), "=r"(r[2]), "=r"(r[3]) : "r"(addr));
}
__device__ __forceinline__ uint32_t packh2(float a, float b) {
    __half2 h = __floats2half2_rn(a, b);
    return *(uint32_t*)&h;
}

#define SKH 72
#define SNB 136
#define SNB64 72

// ---------------- 128x128 GEMM (qkv): C = A * W, W native [K][N] ----------------
#define STGA_H   (128*SKH)
#define STGB_H   (32*SNB)
#define SMEM_GEMM ((2*STGA_H + 2*STGB_H)*2)
__global__ __launch_bounds__(256, 2)
void gemm_h(const __half* __restrict__ A, const __half* __restrict__ B,
            const float* __restrict__ bias, __half* __restrict__ C,
            int M, int N, int K) {
    extern __shared__ __half smh[];
    __half* As = smh;
    __half* Bs = smh + 2 * STGA_H;

    const int tid  = threadIdx.x;
    const int lane = tid & 31, wid = tid >> 5;
    const int wm = (wid & 1) * 64, wn = (wid >> 1) * 32;
    const int g = lane >> 2, tq = lane & 3;
    const int m0 = blockIdx.y * 128, n0 = blockIdx.x * 128;

    const uint32_t sAu = (uint32_t)__cvta_generic_to_shared(As);
    const uint32_t sBu = (uint32_t)__cvta_generic_to_shared(Bs);

    const int arow = tid >> 2, acol = (tid & 3) << 3;
    const int brow = tid >> 4, bcol = (tid & 15) << 3;
    const int mrow = lane & 15, khalf = (lane >> 4) << 3;
    const int vkrow = (lane & 7) + ((lane >> 3) & 1) * 8;
    const int vdoff = (lane >> 4) * 8;
    int aoff[4];
    #pragma unroll
    for (int mi = 0; mi < 4; mi++) aoff[mi] = (wm + mi * 16 + mrow) * SKH + khalf;

    auto load_tile = [&](int t) {
        int k0 = t * 32, st = t & 1;
        #pragma unroll
        for (int it = 0; it < 2; it++) {
            int r = arow + it * 64;
            cpa16(sAu + ((st * 128 + r) * SKH + acol) * 2, A + (size_t)(m0 + r) * K + k0 + acol);
            int br = brow + it * 16;
            cpa16(sBu + ((st * 32 + br) * SNB + bcol) * 2, B + (size_t)(k0 + br) * N + n0 + bcol);
        }
    };

    float acc[4][4][4] = {};
    const int nt = K / 32;

    load_tile(0);
    asm volatile("cp.async.commit_group;\n");

    for (int t = 0; t < nt; t++) {
        if (t + 1 < nt) load_tile(t + 1);
        asm volatile("cp.async.commit_group;\n");
        asm volatile("cp.async.wait_group 1;\n");
        __syncthreads();

        const int stA = (t & 1) * STGA_H;
        const int stB = (t & 1) * STGB_H;
        #pragma unroll
        for (int ks = 0; ks < 2; ks++) {
            uint32_t af[4][4], bq[2][4];
            #pragma unroll
            for (int mi = 0; mi < 4; mi++)
                ldsm4(af[mi], sAu + (stA + aoff[mi] + ks * 16) * 2);
            #pragma unroll
            for (int p = 0; p < 2; p++)
                ldsm4t(bq[p], sBu + (stB + (ks * 16 + vkrow) * SNB + wn + p * 16 + vdoff) * 2);
            #pragma unroll
            for (int mi = 0; mi < 4; mi++) {
                #pragma unroll
                for (int ni = 0; ni < 4; ni++) {
                    uint32_t bb[2] = { bq[ni >> 1][(ni & 1) * 2], bq[ni >> 1][(ni & 1) * 2 + 1] };
                    mma16(acc[mi][ni], af[mi], bb);
                }
            }
        }
        __syncthreads();
    }

    #pragma unroll
    for (int mi = 0; mi < 4; mi++) {
        #pragma unroll
        for (int ni = 0; ni < 4; ni++) {
            int m = m0 + wm + mi * 16 + g;
            int n = n0 + wn + ni * 8 + tq * 2;
            #pragma unroll
            for (int half_ = 0; half_ < 2; half_++) {
                int mm = m + half_ * 8;
                float v0 = acc[mi][ni][half_ * 2 + 0] + bias[n + 0];
                float v1 = acc[mi][ni][half_ * 2 + 1] + bias[n + 1];
                *(__half2*)(C + (size_t)mm * N + n) = __floats2half2_rn(v0, v1);
            }
        }
    }
}

// ---------------- 64x64 GEMM, templated epilogue, W native [K][N] ----------------
#define STGA64 (64*SKH)
#define STGB64 (32*SNB64)
#define SMEM_G64 ((2*STGA64 + 2*STGB64)*2)
template<int EPI>   // 1: bias+res -> float, 2: bias+gelu -> half
__global__ __launch_bounds__(128, 6)
void gemm_h64(const __half* __restrict__ A, const __half* __restrict__ B,
              const float* __restrict__ bias, const float* __restrict__ res,
              void* __restrict__ Cv, int M, int N, int K) {
    extern __shared__ __half smh[];
    __half* As = smh;
    __half* Bs = smh + 2 * STGA64;

    const int tid  = threadIdx.x;
    const int lane = tid & 31, wid = tid >> 5;
    const int wm = (wid & 1) * 32, wn = (wid >> 1) * 32;
    const int g = lane >> 2, tq = lane & 3;
    const int m0 = blockIdx.y * 64, n0 = blockIdx.x * 64;

    const uint32_t sAu = (uint32_t)__cvta_generic_to_shared(As);
    const uint32_t sBu = (uint32_t)__cvta_generic_to_shared(Bs);

    const int arow = tid >> 1, acol = (tid & 1) << 4;
    const int brow = tid >> 3, bcol = (tid & 7) << 3;
    const int mrow = lane & 15, khalf = (lane >> 4) << 3;
    const int vkrow = (lane & 7) + ((lane >> 3) & 1) * 8;
    const int vdoff = (lane >> 4) * 8;
    int aoff[2];
    #pragma unroll
    for (int mi = 0; mi < 2; mi++) aoff[mi] = (wm + mi * 16 + mrow) * SKH + khalf;

    auto load_tile = [&](int t) {
        int k0 = t * 32, st = t & 1;
        int r = arow, c8 = acol >> 1;
        cpa16(sAu + ((st * 64 + r) * SKH + c8) * 2, A + (size_t)(m0 + r) * K + k0 + c8);
        cpa16(sAu + ((st * 64 + r) * SKH + c8 + 16) * 2, A + (size_t)(m0 + r) * K + k0 + c8 + 16);
        #pragma unroll
        for (int it = 0; it < 2; it++) {
            int br = brow + it * 16;
            cpa16(sBu + ((st * 32 + br) * SNB64 + bcol) * 2, B + (size_t)(k0 + br) * N + n0 + bcol);
        }
    };

    float acc[2][4][4] = {};
    const int nt = K / 32;

    load_tile(0);
    asm volatile("cp.async.commit_group;\n");

    for (int t = 0; t < nt; t++) {
        if (t + 1 < nt) load_tile(t + 1);
        asm volatile("cp.async.commit_group;\n");
        asm volatile("cp.async.wait_group 1;\n");
        __syncthreads();

        const int stA = (t & 1) * STGA64;
        const int stB = (t & 1) * STGB64;
        #pragma unroll
        for (int ks = 0; ks < 2; ks++) {
            uint32_t af[2][4], bq[2][4];
            #pragma unroll
            for (int mi = 0; mi < 2; mi++)
                ldsm4(af[mi], sAu + (stA + aoff[mi] + ks * 16) * 2);
            #pragma unroll
            for (int p = 0; p < 2; p++)
                ldsm4t(bq[p], sBu + (stB + (ks * 16 + vkrow) * SNB64 + wn + p * 16 + vdoff) * 2);
            #pragma unroll
            for (int mi = 0; mi < 2; mi++) {
                #pragma unroll
                for (int ni = 0; ni < 4; ni++) {
                    uint32_t bb[2] = { bq[ni >> 1][(ni & 1) * 2], bq[ni >> 1][(ni & 1) * 2 + 1] };
                    mma16(acc[mi][ni], af[mi], bb);
                }
            }
        }
        __syncthreads();
    }

    #pragma unroll
    for (int mi = 0; mi < 2; mi++) {
        #pragma unroll
        for (int ni = 0; ni < 4; ni++) {
            int m = m0 + wm + mi * 16 + g;
            int n = n0 + wn + ni * 8 + tq * 2;
            #pragma unroll
            for (int half_ = 0; half_ < 2; half_++) {
                int mm = m + half_ * 8;
                float v0 = acc[mi][ni][half_ * 2 + 0] + bias[n + 0];
                float v1 = acc[mi][ni][half_ * 2 + 1] + bias[n + 1];
                if (EPI == 1) {
                    float2 rr = *(const float2*)((const float*)res + (size_t)mm * N + n);
                    v0 += rr.x; v1 += rr.y;
                    *(float2*)((float*)Cv + (size_t)mm * N + n) = make_float2(v0, v1);
                } else {
                    v0 = 0.5f * v0 * (1.f + erff(v0 * 0.70710678f));
                    v1 = 0.5f * v1 * (1.f + erff(v1 * 0.70710678f));
                    *(__half2*)((__half*)Cv + (size_t)mm * N + n) = __floats2half2_rn(v0, v1);
                }
            }
        }
    }
}

// ---------------- LM-head GEMM (tokt [V][K]) + fused NLL partials ----------------
#define STG_H (128*SKH)
#define SMEM_LM (4*STG_H*2)
__global__ __launch_bounds__(256, 2)
void gemm_lm(const __half* __restrict__ A, const __half* __restrict__ B,
             float* __restrict__ C, float* __restrict__ pm, float* __restrict__ ps,
             int M, int N, int K) {
    extern __shared__ __half smh[];
    __half* As = smh;
    __half* Bs = smh + 2 * STG_H;
    float* sPm = (float*)smh;
    float* sPs = (float*)smh + 512;

    const int tid  = threadIdx.x;
    const int lane = tid & 31, wid = tid >> 5;
    const int wm = (wid & 1) * 64, wn = (wid >> 1) * 32;
    const int g = lane >> 2, tq = lane & 3;
    const int m0 = blockIdx.x * 128, n0 = blockIdx.y * 128;
    const int tileY = blockIdx.y, NTt = gridDim.y;

    const uint32_t sAu = (uint32_t)__cvta_generic_to_shared(As);
    const uint32_t sBu = (uint32_t)__cvta_generic_to_shared(Bs);

    const int arow = tid >> 2, acol = (tid & 3) << 3;
    const int mrow = lane & 15, khalf = (lane >> 4) << 3;
    int aoff[4], boff[2];
    #pragma unroll
    for (int mi = 0; mi < 4; mi++) aoff[mi] = (wm + mi * 16 + mrow) * SKH + khalf;
    #pragma unroll
    for (int p = 0; p < 2; p++)    boff[p]  = (wn + p * 16 + mrow) * SKH + khalf;

    auto load_tile = [&](int t) {
        int k0 = t * 32, st = t & 1;
        #pragma unroll
        for (int it = 0; it < 2; it++) {
            int r = arow + it * 64;
            cpa16(sAu + ((st * 128 + r) * SKH + acol) * 2, A + (size_t)(m0 + r) * K + k0 + acol);
            int n = n0 + r;
            int ok = (n < N);
            cpa16z(sBu + ((st * 128 + r) * SKH + acol) * 2,
                   B + (size_t)(ok ? n : (N - 1)) * K + k0 + acol, ok ? 16 : 0);
        }
    };

    float acc[4][4][4] = {};
    const int nt = K / 32;

    load_tile(0);
    asm volatile("cp.async.commit_group;\n");

    for (int t = 0; t < nt; t++) {
        if (t + 1 < nt) load_tile(t + 1);
        asm volatile("cp.async.commit_group;\n");
        asm volatile("cp.async.wait_group 1;\n");
        __syncthreads();

        const int stO = (t & 1) * STG_H;
        #pragma unroll
        for (int ks = 0; ks < 2; ks++) {
            uint32_t af[4][4], bq[2][4];
            #pragma unroll
            for (int mi = 0; mi < 4; mi++)
                ldsm4(af[mi], sAu + (stO + aoff[mi] + ks * 16) * 2);
            #pragma unroll
            for (int p = 0; p < 2; p++)
                ldsm4(bq[p], sBu + (stO + boff[p] + ks * 16) * 2);
            #pragma unroll
            for (int mi = 0; mi < 4; mi++) {
                #pragma unroll
                for (int ni = 0; ni < 4; ni++) {
                    uint32_t bb[2] = { bq[ni >> 1][ni & 1], bq[ni >> 1][(ni & 1) + 2] };
                    mma16(acc[mi][ni], af[mi], bb);
                }
            }
        }
        __syncthreads();
    }

    // scalar stores (row stride N=50257 is odd: vector stores would misalign)
    #pragma unroll
    for (int mi = 0; mi < 4; mi++) {
        #pragma unroll
        for (int ni = 0; ni < 4; ni++) {
            int m = m0 + wm + mi * 16 + g;
            int n = n0 + wn + ni * 8 + tq * 2;
            #pragma unroll
            for (int half_ = 0; half_ < 2; half_++) {
                int mm = m + half_ * 8;
                #pragma unroll
                for (int e = 0; e < 2; e++) {
                    int nn = n + e;
                    if (nn >= N) continue;
                    C[(size_t)mm * N + nn] = acc[mi][ni][half_ * 2 + e];
                }
            }
        }
    }

    __syncthreads();
    #pragma unroll
    for (int mi = 0; mi < 4; mi++) {
        #pragma unroll
        for (int half_ = 0; half_ < 2; half_++) {
            float lm = -1e30f, lsum = 0.f;
            #pragma unroll
            for (int ni = 0; ni < 4; ni++) {
                #pragma unroll
                for (int e = 0; e < 2; e++) {
                    int nn = n0 + wn + ni * 8 + tq * 2 + e;
                    if (nn < N) lm = fmaxf(lm, acc[mi][ni][half_ * 2 + e]);
                }
            }
            #pragma unroll
            for (int ni = 0; ni < 4; ni++) {
                #pragma unroll
                for (int e = 0; e < 2; e++) {
                    int nn = n0 + wn + ni * 8 + tq * 2 + e;
                    if (nn < N) lsum += __expf(acc[mi][ni][half_ * 2 + e] - lm);
                }
            }
            #pragma unroll
            for (int o = 1; o <= 2; o <<= 1) {
                float m2 = __shfl_xor_sync(0xffffffffu, lm, o);
                float s2 = __shfl_xor_sync(0xffffffffu, lsum, o);
                lse_merge(lm, lsum, m2, s2);
            }
            if (tq == 0) {
                int rl = wm + mi * 16 + half_ * 8 + g;
                sPm[rl * 4 + (wid >> 1)] = lm;
                sPs[rl * 4 + (wid >> 1)] = lsum;
            }
        }
    }
    __syncthreads();
    if (tid < 128) {
        float M_ = sPm[tid * 4], S_ = sPs[tid * 4];
        #pragma unroll
        for (int gi = 1; gi < 4; gi++) lse_merge(M_, S_, sPm[tid * 4 + gi], sPs[tid * 4 + gi]);
        pm[(size_t)(m0 + tid) * NTt + tileY] = M_;
        ps[(size_t)(m0 + tid) * NTt + tileY] = S_;
    }
}

// ---------------- flash attention: register-P + split-K with in-kernel combine ----------------
// grid.x=24, all 576 blocks resident (4 CTAs/SM enforced) -> spin handoff is deadlock-free.
#define FQH 72
#define FTILE (64*FQH)
#define SMEM_FL (5*FTILE*2)
__global__ __launch_bounds__(128, 4)
void flash_h(const __half* __restrict__ qkv, __half* __restrict__ out,
             float* __restrict__ pO, float2* __restrict__ pml,
             int* __restrict__ flags, int gen) {
    extern __shared__ __half smh[];
    __half* Qs = smh;
    const uint32_t sQ = (uint32_t)__cvta_generic_to_shared(Qs);
    const uint32_t sK[2] = { sQ + FTILE * 2,     sQ + 2 * FTILE * 2 };
    const uint32_t sV[2] = { sQ + 3 * FTILE * 2, sQ + 4 * FTILE * 2 };

    const int tid = threadIdx.x;
    const int lane = tid & 31, wid = tid >> 5;
    const int g = lane >> 2, tq = lane & 3;
    const int h = blockIdx.y, b = blockIdx.z;
    const int r0 = wid * 16 + g;

    int qi, kt0, kt1, role;   // 0=full, 1=prefix split (no diag), 2=suffix split (diag, merges)
    const int bx = blockIdx.x;
    if (bx < 16) {
        qi = bx;
        if (qi < 8) { kt0 = 0; kt1 = qi + 1; role = 0; }
        else        { kt0 = 0; kt1 = (qi + 2) >> 1; role = 1; }
    } else {
        qi = bx - 8;
        kt0 = (qi + 2) >> 1; kt1 = qi + 1; role = 2;
    }
    const int q0 = qi * 64;

    auto loadKV = [&](int t, int st) {
        int k0 = t * 64;
        #pragma unroll
        for (int i = 0; i < 4; i++) {
            int idx = tid + i * 128;
            int r = idx >> 3, c8 = (idx & 7) << 3;
            const __half* src = qkv + (size_t)(b * TQ + k0 + r) * (3 * DQ) + h * HD + c8;
            cpa16(sK[st] + (r * FQH + c8) * 2, src + DQ);
            cpa16(sV[st] + (r * FQH + c8) * 2, src + 2 * DQ);
        }
    };

    const int vkrow = (lane & 7) + ((lane >> 3) & 1) * 8;
    const int vdoff = (lane >> 4) * 8;

    const __half2 sc8 = __floats2half2_rn(0.125f, 0.125f);
    #pragma unroll
    for (int i = 0; i < 4; i++) {
        int idx = tid + i * 128;
        int r = idx >> 3, c8 = (idx & 7) << 3;
        uint4 raw = *(const uint4*)(qkv + (size_t)(b * TQ + q0 + r) * (3 * DQ) + h * HD + c8);
        __half2* hp = (__half2*)&raw;
        hp[0] = __hmul2(hp[0], sc8); hp[1] = __hmul2(hp[1], sc8);
        hp[2] = __hmul2(hp[2], sc8); hp[3] = __hmul2(hp[3], sc8);
        *(uint4*)(Qs + r * FQH + c8) = raw;
    }

    loadKV(kt0, 0);
    asm volatile("cp.async.commit_group;\n");
    __syncthreads();

    uint32_t qf[4][4];
    #pragma unroll
    for (int kk = 0; kk < 4; kk++) {
        qf[kk][0] = *(const uint32_t*)(Qs + r0 * FQH + kk * 16 + 2 * tq);
        qf[kk][1] = *(const uint32_t*)(Qs + (r0 + 8) * FQH + kk * 16 + 2 * tq);
        qf[kk][2] = *(const uint32_t*)(Qs + r0 * FQH + kk * 16 + 8 + 2 * tq);
        qf[kk][3] = *(const uint32_t*)(Qs + (r0 + 8) * FQH + kk * 16 + 8 + 2 * tq);
    }

    float m0r = -1e30f, m1r = -1e30f, l0 = 0.f, l1 = 0.f;
    float oc[8][4] = {};

    for (int kt = kt0; kt < kt1; kt++) {
        const int li = kt - kt0;
        const int st = li & 1;
        if (kt + 1 < kt1) {
            loadKV(kt + 1, st ^ 1);
            asm volatile("cp.async.commit_group;\n");
            asm volatile("cp.async.wait_group 1;\n");
        } else {
            asm volatile("cp.async.wait_group 0;\n");
        }
        __syncthreads();

        const __half* Kb = (const __half*)((const char*)smh + (sK[st] - sQ));
        float sc[8][4] = {};
        #pragma unroll
        for (int kk = 0; kk < 4; kk++) {
            #pragma unroll
            for (int ni = 0; ni < 8; ni++) {
                uint32_t bb[2];
                bb[0] = *(const uint32_t*)(Kb + (ni * 8 + g) * FQH + kk * 16 + 2 * tq);
                bb[1] = *(const uint32_t*)(Kb + (ni * 8 + g) * FQH + kk * 16 + 8 + 2 * tq);
                mma16(sc[ni], qf[kk], bb);
            }
        }

        if (role != 1 && kt == kt1 - 1) {
            #pragma unroll
            for (int ni = 0; ni < 8; ni++) {
                int c0 = ni * 8 + 2 * tq, c1 = c0 + 1;
                if (c0 > r0) sc[ni][0] = -1e30f;
                if (c1 > r0) sc[ni][1] = -1e30f;
                if (c0 > r0 + 8) sc[ni][2] = -1e30f;
                if (c1 > r0 + 8) sc[ni][3] = -1e30f;
            }
        }

        float mx0 = -1e30f, mx1 = -1e30f;
        #pragma unroll
        for (int ni = 0; ni < 8; ni++) {
            mx0 = fmaxf(mx0, fmaxf(sc[ni][0], sc[ni][1]));
            mx1 = fmaxf(mx1, fmaxf(sc[ni][2], sc[ni][3]));
        }
        #pragma unroll
        for (int o = 1; o <= 2; o <<= 1) {
            mx0 = fmaxf(mx0, __shfl_xor_sync(0xffffffffu, mx0, o));
            mx1 = fmaxf(mx1, __shfl_xor_sync(0xffffffffu, mx1, o));
        }
        float nm0 = fmaxf(m0r, mx0), nm1 = fmaxf(m1r, mx1);
        float cr0 = __expf(m0r - nm0), cr1 = __expf(m1r - nm1);
        float rs0 = 0.f, rs1 = 0.f;
        #pragma unroll
        for (int ni = 0; ni < 8; ni++) {
            sc[ni][0] = __expf(sc[ni][0] - nm0); rs0 += sc[ni][0];
            sc[ni][1] = __expf(sc[ni][1] - nm0); rs0 += sc[ni][1];
            sc[ni][2] = __expf(sc[ni][2] - nm1); rs1 += sc[ni][2];
            sc[ni][3] = __expf(sc[ni][3] - nm1); rs1 += sc[ni][3];
        }
        #pragma unroll
        for (int o = 1; o <= 2; o <<= 1) {
            rs0 += __shfl_xor_sync(0xffffffffu, rs0, o);
            rs1 += __shfl_xor_sync(0xffffffffu, rs1, o);
        }
        l0 = l0 * cr0 + rs0; l1 = l1 * cr1 + rs1;
        m0r = nm0; m1r = nm1;
        #pragma unroll
        for (int ni = 0; ni < 8; ni++) {
            oc[ni][0] *= cr0; oc[ni][1] *= cr0;
            oc[ni][2] *= cr1; oc[ni][3] *= cr1;
        }

        #pragma unroll
        for (int kk = 0; kk < 4; kk++) {
            uint32_t a[4];
            a[0] = packh2(sc[2 * kk][0],     sc[2 * kk][1]);
            a[1] = packh2(sc[2 * kk][2],     sc[2 * kk][3]);
            a[2] = packh2(sc[2 * kk + 1][0], sc[2 * kk + 1][1]);
            a[3] = packh2(sc[2 * kk + 1][2], sc[2 * kk + 1][3]);
            #pragma unroll
            for (int pr = 0; pr < 4; pr++) {
                uint32_t v4[4];
                ldsm4t(v4, sV[st] + ((kk * 16 + vkrow) * FQH + pr * 16 + vdoff) * 2);
                uint32_t b0[2] = { v4[0], v4[1] };
                uint32_t b1[2] = { v4[2], v4[3] };
                mma16(oc[pr * 2 + 0], a, b0);
                mma16(oc[pr * 2 + 1], a, b1);
            }
        }
        __syncthreads();
    }

    if (role == 0) {
        float i0 = 1.f / l0, i1 = 1.f / l1;
        __half* o0 = out + (size_t)(b * TQ + q0 + r0) * DQ + h * HD;
        __half* o1 = out + (size_t)(b * TQ + q0 + r0 + 8) * DQ + h * HD;
        #pragma unroll
        for (int ni = 0; ni < 8; ni++) {
            *(__half2*)(o0 + ni * 8 + 2 * tq) = __floats2half2_rn(oc[ni][0] * i0, oc[ni][1] * i0);
            *(__half2*)(o1 + ni * 8 + 2 * tq) = __floats2half2_rn(oc[ni][2] * i1, oc[ni][3] * i1);
        }
    } else if (role == 1) {
        // publish partials for the suffix block
        const int sidx = (b * HQ + h) * NSPL + (qi - 8);
        float* Od = pO + (size_t)sidx * 4096;
        #pragma unroll
        for (int ni = 0; ni < 8; ni++) {
            int c = ni * 8 + 2 * tq;
            *(float2*)(Od + r0 * 64 + c)       = make_float2(oc[ni][0], oc[ni][1]);
            *(float2*)(Od + (r0 + 8) * 64 + c) = make_float2(oc[ni][2], oc[ni][3]);
        }
        if (tq == 0) {
            pml[(size_t)sidx * 64 + r0]     = make_float2(m0r, l0);
            pml[(size_t)sidx * 64 + r0 + 8] = make_float2(m1r, l1);
        }
        __threadfence();
        __syncthreads();
        if (tid == 0) atomicExch(&flags[sidx], gen);
    } else {
        // suffix block: wait for prefix partials, merge, write final
        const int sidx = (b * HQ + h) * NSPL + (qi - 8);
        if (tid == 0) {
            int v;
            do {
                asm volatile("ld.global.acquire.gpu.b32 %0, [%1];"
                             : "=r"(v) : "l"(flags + sidx) : "memory");
            } while (v != gen);
        }
        __syncthreads();
        // .cg loads: bypass L1 (lines may be stale from a previous layer in this kernel's L1 image? no —
        // L1 flushes per launch, but partials were written THIS launch by another SM, so L1 never had them;
        // .cg guarantees L2-fresh reads regardless)
        float2 ml0 = __ldcg((const float2*)pml + (size_t)sidx * 64 + r0);
        float2 ml1 = __ldcg((const float2*)pml + (size_t)sidx * 64 + r0 + 8);
        float M0 = fmaxf(ml0.x, m0r), M1 = fmaxf(ml1.x, m1r);
        float w10 = __expf(ml0.x - M0), w20 = __expf(m0r - M0);
        float w11 = __expf(ml1.x - M1), w21 = __expf(m1r - M1);
        float i0 = 1.f / (ml0.y * w10 + l0 * w20);
        float i1 = 1.f / (ml1.y * w11 + l1 * w21);
        const float* Od = pO + (size_t)sidx * 4096;
        __half* o0 = out + (size_t)(b * TQ + q0 + r0) * DQ + h * HD;
        __half* o1 = out + (size_t)(b * TQ + q0 + r0 + 8) * DQ + h * HD;
        #pragma unroll
        for (int ni = 0; ni < 8; ni++) {
            int c = ni * 8 + 2 * tq;
            float2 a0 = __ldcg((const float2*)(Od + r0 * 64 + c));
            float2 a1 = __ldcg((const float2*)(Od + (r0 + 8) * 64 + c));
            *(__half2*)(o0 + c) = __floats2half2_rn((a0.x * w10 + oc[ni][0] * w20) * i0,
                                                    (a0.y * w10 + oc[ni][1] * w20) * i0);
            *(__half2*)(o1 + c) = __floats2half2_rn((a1.x * w11 + oc[ni][2] * w21) * i1,
                                                    (a1.y * w11 + oc[ni][3] * w21) * i1);
        }
    }
}

// ---------------- NLL reduce + loss ----------------
__global__ void nll_reduce(const float* __restrict__ pm, const float* __restrict__ ps,
                           const float* __restrict__ logits, const int* __restrict__ tgt,
                           float* __restrict__ nll) {
    int row = blockIdx.x, t = threadIdx.x;
    float M = -1e30f, S = 0.f;
    for (int j = t; j < NT_LM; j += 128)
        lse_merge(M, S, pm[(size_t)row * NT_LM + j], ps[(size_t)row * NT_LM + j]);
    __shared__ float sm_[128], ss_[128];
    sm_[t] = M; ss_[t] = S; __syncthreads();
    for (int o = 64; o > 0; o >>= 1) {
        if (t < o) {
            float mm = sm_[t], ssv = ss_[t];
            lse_merge(mm, ssv, sm_[t + o], ss_[t + o]);
            sm_[t] = mm; ss_[t] = ssv;
        }
        __syncthreads();
    }
    if (t == 0) {
        float lse = sm_[0] + logf(ss_[0]);
        nll[row] = lse - logits[(size_t)row * VQ + tgt[row]];
    }
}
__global__ void loss_kernel(const float* __restrict__ nll, float* __restrict__ loss) {
    __shared__ float s[1024];
    float v = nll[threadIdx.x] + nll[threadIdx.x + 1024];
    s[threadIdx.x] = v; __syncthreads();
    for (int o = 512; o > 0; o >>= 1) {
        if (threadIdx.x < o) s[threadIdx.x] += s[threadIdx.x + o];
        __syncthreads();
    }
    if (threadIdx.x == 0) *loss = s[0] * (1.f / 2048.f);
}

// ---------------- launch ----------------
extern "C" void kernel_launch(void* const* d_in, const int* in_sizes, int n_in,
                              void* d_out, int out_size) {
    const int*   ids  = (const int*)d_in[0];
    const int*   tgt  = (const int*)d_in[1];
    const float* tok  = (const float*)d_in[2];
    const float* pos  = (const float*)d_in[3];
    const float* ln1w = (const float*)d_in[4];
    const float* ln1b = (const float*)d_in[5];
    const float* qkvw = (const float*)d_in[6];
    const float* qkvb = (const float*)d_in[7];
    const float* apw  = (const float*)d_in[8];
    const float* apb  = (const float*)d_in[9];
    const float* ln2w = (const float*)d_in[10];
    const float* ln2b = (const float*)d_in[11];
    const float* fcw  = (const float*)d_in[12];
    const float* fcb  = (const float*)d_in[13];
    const float* pw   = (const float*)d_in[14];
    const float* pb   = (const float*)d_in[15];
    const float* lnfw = (const float*)d_in[16];
    const float* lnfb = (const float*)d_in[17];

    float *x, *nll, *lfb, *pm, *ps, *pO;
    float2* pml;
    int* flags;
    __half *h, *qkv, *attn, *ffn;
    __half *wqkv, *wap, *wfc, *wpr, *tokt;
    cudaGetSymbolAddress((void**)&x,    g_x);
    cudaGetSymbolAddress((void**)&h,    g_h);
    cudaGetSymbolAddress((void**)&qkv,  g_qkv);
    cudaGetSymbolAddress((void**)&attn, g_attn);
    cudaGetSymbolAddress((void**)&ffn,  g_ffn);
    cudaGetSymbolAddress((void**)&nll,  g_nll);
    cudaGetSymbolAddress((void**)&lfb,  g_logits_fb);
    cudaGetSymbolAddress((void**)&pm,   g_pm);
    cudaGetSymbolAddress((void**)&ps,   g_ps);
    cudaGetSymbolAddress((void**)&pO,   g_pO);
    cudaGetSymbolAddress((void**)&pml,  g_pml);
    cudaGetSymbolAddress((void**)&flags, g_flag);
    cudaGetSymbolAddress((void**)&wqkv, g_wqkv);
    cudaGetSymbolAddress((void**)&wap,  g_wap);
    cudaGetSymbolAddress((void**)&wfc,  g_wfc);
    cudaGetSymbolAddress((void**)&wpr,  g_wpr);
    cudaGetSymbolAddress((void**)&tokt, g_tokt);

    cudaFuncSetAttribute(flash_h,      cudaFuncAttributeMaxDynamicSharedMemorySize, SMEM_FL);
    cudaFuncSetAttribute(gemm_h,       cudaFuncAttributeMaxDynamicSharedMemorySize, SMEM_GEMM);
    cudaFuncSetAttribute(gemm_h64<1>,  cudaFuncAttributeMaxDynamicSharedMemorySize, SMEM_G64);
    cudaFuncSetAttribute(gemm_h64<2>,  cudaFuncAttributeMaxDynamicSharedMemorySize, SMEM_G64);
    cudaFuncSetAttribute(gemm_lm,      cudaFuncAttributeMaxDynamicSharedMemorySize, SMEM_LM);

    const long long LOGN = (long long)BT * VQ;
    float* out    = (float*)d_out;
    float* logits;
    float* lossp  = nullptr;
    if ((long long)out_size > LOGN) {
        lossp  = out;
        logits = out + ((long long)out_size - LOGN);
    } else if ((long long)out_size == LOGN) {
        logits = out;
    } else {
        lossp  = out;
        logits = lfb;
    }

    cvt_all<<<(CVT_TOT + 255) / 256, 256>>>(
        (const float4*)qkvw, (const float4*)apw, (const float4*)fcw,
        (const float4*)pw,   (const float4*)tok,
        (uint4*)wqkv, (uint4*)wap, (uint4*)wfc, (uint4*)wpr, (uint4*)tokt);

    for (int l = 0; l < LQ; l++) {
        if (l == 0)
            embedln_kernel<<<BT/8, 256>>>(ids, tok, pos, ln1w, ln1b, x, h);
        else
            ln_kernel<<<BT/8, 256>>>(x, ln1w + l * DQ, ln1b + l * DQ, h);
        gemm_h<<<dim3((3 * DQ) / 128, BT / 128), 256, SMEM_GEMM>>>(
            h, wqkv + (size_t)l * DQ * 3 * DQ, qkvb + l * 3 * DQ, qkv, BT, 3 * DQ, DQ);
        flash_h<<<dim3(TQ / 64 + NSPL, HQ, BQ), 128, SMEM_FL>>>(qkv, attn, pO, pml, flags, l + 1);
        gemm_h64<1><<<dim3(DQ / 64, BT / 64), 128, SMEM_G64>>>(
            attn, wap + (size_t)l * DQ * DQ, apb + l * DQ, x, x, BT, DQ, DQ);
        ln_kernel<<<BT/8, 256>>>(x, ln2w + l * DQ, ln2b + l * DQ, h);
        gemm_h64<2><<<dim3((4 * DQ) / 64, BT / 64), 128, SMEM_G64>>>(
            h, wfc + (size_t)l * DQ * 4 * DQ, fcb + l * 4 * DQ, nullptr, ffn, BT, 4 * DQ, DQ);
        gemm_h64<1><<<dim3(DQ / 64, BT / 64), 128, SMEM_G64>>>(
            ffn, wpr + (size_t)l * 4 * DQ * DQ, pb + l * DQ, x, x, BT, DQ, 4 * DQ);
    }

    ln_kernel<<<BT/8, 256>>>(x, lnfw, lnfb, h);
    gemm_lm<<<dim3(BT / 128, NT_LM), 256, SMEM_LM>>>(
        h, tokt, logits, pm, ps, BT, VQ, DQ);

    if (lossp) {
        nll_reduce<<<BT, 128>>>(pm, ps, logits, tgt, nll);
        loss_kernel<<<1, 1024>>>(nll, lossp);
    }
}

// round 16
// speedup vs baseline: 1.7768x; 1.0120x over previous
#include <cuda_runtime.h>
#include <cuda_fp16.h>
#include <math.h>
#include <stdint.h>

// ---------------- problem constants ----------------
#define BQ 2
#define TQ 1024
#define DQ 768
#define LQ 4
#define HQ 12
#define VQ 50257
#define BT (BQ*TQ)
#define HD 64
#define NT_LM 393
#define NBH (BQ*HQ)
#define NSPL 8

// ---------------- scratch ----------------
__device__ float  g_x   [BT*DQ];
__device__ __half g_h   [BT*DQ];
__device__ __half g_qkv [BT*3*DQ];
__device__ __half g_attn[BT*DQ];
__device__ __half g_ffn [BT*4*DQ];
__device__ float  g_nll [BT];
__device__ float  g_pm  [BT*NT_LM];
__device__ float  g_ps  [BT*NT_LM];
__device__ float  g_logits_fb[102926336];
__device__ float  g_pO  [NBH*NSPL*64*64];
__device__ float2 g_pml [NBH*NSPL*64];
__device__ int    g_flag[NBH*NSPL];
__device__ __half g_wqkv[LQ*DQ*3*DQ];
__device__ __half g_wap [LQ*DQ*DQ];
__device__ __half g_wfc [LQ*DQ*4*DQ];
__device__ __half g_wpr [LQ*4*DQ*DQ];
__device__ __half g_tokt[(size_t)VQ*DQ];

__device__ __forceinline__ void lse_merge(float& m, float& s, float m2, float s2) {
    float M = fmaxf(m, m2);
    s = s * __expf(m - M) + s2 * __expf(m2 - M);
    m = M;
}

// ---------------- merged fp16 convert ----------------
#define CV0 884736
#define CV1 294912
#define CV2 1179648
#define CV3 1179648
#define CV4 4824672
#define CVT_TOT (CV0+CV1+CV2+CV3+CV4)
__global__ void cvt_all(const float4* __restrict__ s0, const float4* __restrict__ s1,
                        const float4* __restrict__ s2, const float4* __restrict__ s3,
                        const float4* __restrict__ s4,
                        uint4* __restrict__ d0, uint4* __restrict__ d1,
                        uint4* __restrict__ d2, uint4* __restrict__ d3,
                        uint4* __restrict__ d4) {
    int i = blockIdx.x * 256 + threadIdx.x;
    if (i >= CVT_TOT) return;
    const float4* s; uint4* d; int off = i;
    if (off < CV0) { s = s0; d = d0; }
    else if ((off -= CV0) < CV1) { s = s1; d = d1; }
    else if ((off -= CV1) < CV2) { s = s2; d = d2; }
    else if ((off -= CV2) < CV3) { s = s3; d = d3; }
    else { off -= CV3; s = s4; d = d4; }
    float4 a = s[2 * off], b = s[2 * off + 1];
    __half2 h0 = __floats2half2_rn(a.x, a.y);
    __half2 h1 = __floats2half2_rn(a.z, a.w);
    __half2 h2 = __floats2half2_rn(b.x, b.y);
    __half2 h3 = __floats2half2_rn(b.z, b.w);
    d[off] = make_uint4(*(uint32_t*)&h0, *(uint32_t*)&h1, *(uint32_t*)&h2, *(uint32_t*)&h3);
}

// ---------------- fused embedding + layernorm (layer 0) ----------------
__global__ __launch_bounds__(256)
void embedln_kernel(const int* __restrict__ ids, const float* __restrict__ tok,
                    const float* __restrict__ pos, const float* __restrict__ w,
                    const float* __restrict__ b, float* __restrict__ x,
                    __half* __restrict__ y) {
    const int wid = threadIdx.x >> 5, lane = threadIdx.x & 31;
    const int row = blockIdx.x * 8 + wid;
    const float* te = tok + (size_t)ids[row] * DQ;
    const float* pe = pos + (size_t)(row % TQ) * DQ;
    float4 v[6];
    float s = 0.f, q = 0.f;
    #pragma unroll
    for (int i = 0; i < 6; i++) {
        int c = lane * 4 + i * 128;
        float4 t = *(const float4*)(te + c);
        float4 p = *(const float4*)(pe + c);
        v[i] = make_float4(t.x + p.x, t.y + p.y, t.z + p.z, t.w + p.w);
        *(float4*)(x + (size_t)row * DQ + c) = v[i];
        s += v[i].x + v[i].y + v[i].z + v[i].w;
        q += v[i].x * v[i].x + v[i].y * v[i].y + v[i].z * v[i].z + v[i].w * v[i].w;
    }
    #pragma unroll
    for (int o = 16; o > 0; o >>= 1) {
        s += __shfl_xor_sync(0xffffffffu, s, o);
        q += __shfl_xor_sync(0xffffffffu, q, o);
    }
    float mean = s * (1.f / DQ);
    float var  = q * (1.f / DQ) - mean * mean;
    float inv  = rsqrtf(var + 1e-5f);
    __half* yr = y + (size_t)row * DQ;
    #pragma unroll
    for (int i = 0; i < 6; i++) {
        int c = lane * 4 + i * 128;
        float4 wv = *(const float4*)(w + c);
        float4 bv = *(const float4*)(b + c);
        __half2 h0 = __floats2half2_rn((v[i].x - mean) * inv * wv.x + bv.x,
                                       (v[i].y - mean) * inv * wv.y + bv.y);
        __half2 h1 = __floats2half2_rn((v[i].z - mean) * inv * wv.z + bv.z,
                                       (v[i].w - mean) * inv * wv.w + bv.w);
        *(uint2*)(yr + c) = make_uint2(*(uint32_t*)&h0, *(uint32_t*)&h1);
    }
}

// ---------------- layernorm: warp per row ----------------
__global__ __launch_bounds__(256)
void ln_kernel(const float* __restrict__ x, const float* __restrict__ w,
               const float* __restrict__ b, __half* __restrict__ y) {
    const int wid = threadIdx.x >> 5, lane = threadIdx.x & 31;
    const int row = blockIdx.x * 8 + wid;
    const float* xr = x + (size_t)row * DQ;
    float4 v[6];
    float s = 0.f, q = 0.f;
    #pragma unroll
    for (int i = 0; i < 6; i++) {
        v[i] = *(const float4*)(xr + lane * 4 + i * 128);
        s += v[i].x + v[i].y + v[i].z + v[i].w;
        q += v[i].x * v[i].x + v[i].y * v[i].y + v[i].z * v[i].z + v[i].w * v[i].w;
    }
    #pragma unroll
    for (int o = 16; o > 0; o >>= 1) {
        s += __shfl_xor_sync(0xffffffffu, s, o);
        q += __shfl_xor_sync(0xffffffffu, q, o);
    }
    float mean = s * (1.f / DQ);
    float var  = q * (1.f / DQ) - mean * mean;
    float inv  = rsqrtf(var + 1e-5f);
    __half* yr = y + (size_t)row * DQ;
    #pragma unroll
    for (int i = 0; i < 6; i++) {
        int c = lane * 4 + i * 128;
        float4 wv = *(const float4*)(w + c);
        float4 bv = *(const float4*)(b + c);
        __half2 h0 = __floats2half2_rn((v[i].x - mean) * inv * wv.x + bv.x,
                                       (v[i].y - mean) * inv * wv.y + bv.y);
        __half2 h1 = __floats2half2_rn((v[i].z - mean) * inv * wv.z + bv.z,
                                       (v[i].w - mean) * inv * wv.w + bv.w);
        *(uint2*)(yr + c) = make_uint2(*(uint32_t*)&h0, *(uint32_t*)&h1);
    }
}

// ---------------- fp16 mma / cp.async / ldmatrix helpers ----------------
__device__ __forceinline__ void mma16(float* c, const uint32_t* a, const uint32_t* b) {
    asm volatile("mma.sync.aligned.m16n8k16.row.col.f32.f16.f16.f32 "
                 "{%0,%1,%2,%3}, {%4,%5,%6,%7}, {%8,%9}, {%0,%1,%2,%3};\n"
                 : "+f"(c[0]), "+f"(c[1]), "+f"(c[2]), "+f"(c[3])
                 : "r"(a[0]), "r"(a[1]), "r"(a[2]), "r"(a[3]), "r"(b[0]), "r"(b[1]));
}
__device__ __forceinline__ void cpa16(uint32_t dst, const void* src) {
    asm volatile("cp.async.cg.shared.global [%0], [%1], 16;\n" :: "r"(dst), "l"(src));
}
__device__ __forceinline__ void cpa16z(uint32_t dst, const void* src, int bytes) {
    asm volatile("cp.async.cg.shared.global [%0], [%1], 16, %2;\n" :: "r"(dst), "l"(src), "r"(bytes));
}
__device__ __forceinline__ void ldsm4(uint32_t* r, uint32_t addr) {
    asm volatile("ldmatrix.sync.aligned.m8n8.x4.shared.b16 {%0,%1,%2,%3}, [%4];\n"
                 : "=r"(r[0]), "=r"(r[1]), "=r"(r[2]), "=r"(r[3]) : "r"(addr));
}
__device__ __forceinline__ void ldsm4t(uint32_t* r, uint32_t addr) {
    asm volatile("ldmatrix.sync.aligned.m8n8.x4.trans.shared.b16 {%0,%1,%2,%3}, [%4];\n"
                 : "=r"(r[0]), "=r"(r[1]), "=r"(r[2]), "=r"(r[3]) : "r"(addr));
}
__device__ __forceinline__ uint32_t packh2(float a, float b) {
    __half2 h = __floats2half2_rn(a, b);
    return *(uint32_t*)&h;
}

#define SKH 72
#define SNB 136
#define SNB64 72

// ---------------- 128x128 GEMM (qkv): 3-stage cp.async ----------------
#define STGA_H   (128*SKH)
#define STGB_H   (32*SNB)
#define SMEM_GEMM ((3*STGA_H + 3*STGB_H)*2)   // 81408 bytes; 2 CTAs/SM = 159 KB
__global__ __launch_bounds__(256, 2)
void gemm_h(const __half* __restrict__ A, const __half* __restrict__ B,
            const float* __restrict__ bias, __half* __restrict__ C,
            int M, int N, int K) {
    extern __shared__ __half smh[];
    __half* As = smh;
    __half* Bs = smh + 3 * STGA_H;

    const int tid  = threadIdx.x;
    const int lane = tid & 31, wid = tid >> 5;
    const int wm = (wid & 1) * 64, wn = (wid >> 1) * 32;
    const int g = lane >> 2, tq = lane & 3;
    const int m0 = blockIdx.y * 128, n0 = blockIdx.x * 128;

    const uint32_t sAu = (uint32_t)__cvta_generic_to_shared(As);
    const uint32_t sBu = (uint32_t)__cvta_generic_to_shared(Bs);

    const int arow = tid >> 2, acol = (tid & 3) << 3;
    const int brow = tid >> 4, bcol = (tid & 15) << 3;
    const int mrow = lane & 15, khalf = (lane >> 4) << 3;
    const int vkrow = (lane & 7) + ((lane >> 3) & 1) * 8;
    const int vdoff = (lane >> 4) * 8;
    int aoff[4];
    #pragma unroll
    for (int mi = 0; mi < 4; mi++) aoff[mi] = (wm + mi * 16 + mrow) * SKH + khalf;

    auto load_tile = [&](int t) {
        int k0 = t * 32, st = t % 3;
        #pragma unroll
        for (int it = 0; it < 2; it++) {
            int r = arow + it * 64;
            cpa16(sAu + ((st * 128 + r) * SKH + acol) * 2, A + (size_t)(m0 + r) * K + k0 + acol);
            int br = brow + it * 16;
            cpa16(sBu + ((st * 32 + br) * SNB + bcol) * 2, B + (size_t)(k0 + br) * N + n0 + bcol);
        }
    };

    float acc[4][4][4] = {};
    const int nt = K / 32;

    load_tile(0);
    asm volatile("cp.async.commit_group;\n");
    load_tile(1);
    asm volatile("cp.async.commit_group;\n");

    for (int t = 0; t < nt; t++) {
        if (t + 2 < nt) load_tile(t + 2);
        asm volatile("cp.async.commit_group;\n");
        asm volatile("cp.async.wait_group 2;\n");
        __syncthreads();

        const int stA = (t % 3) * STGA_H;
        const int stB = (t % 3) * STGB_H;
        #pragma unroll
        for (int ks = 0; ks < 2; ks++) {
            uint32_t af[4][4], bq[2][4];
            #pragma unroll
            for (int mi = 0; mi < 4; mi++)
                ldsm4(af[mi], sAu + (stA + aoff[mi] + ks * 16) * 2);
            #pragma unroll
            for (int p = 0; p < 2; p++)
                ldsm4t(bq[p], sBu + (stB + (ks * 16 + vkrow) * SNB + wn + p * 16 + vdoff) * 2);
            #pragma unroll
            for (int mi = 0; mi < 4; mi++) {
                #pragma unroll
                for (int ni = 0; ni < 4; ni++) {
                    uint32_t bb[2] = { bq[ni >> 1][(ni & 1) * 2], bq[ni >> 1][(ni & 1) * 2 + 1] };
                    mma16(acc[mi][ni], af[mi], bb);
                }
            }
        }
        __syncthreads();
    }

    #pragma unroll
    for (int mi = 0; mi < 4; mi++) {
        #pragma unroll
        for (int ni = 0; ni < 4; ni++) {
            int m = m0 + wm + mi * 16 + g;
            int n = n0 + wn + ni * 8 + tq * 2;
            #pragma unroll
            for (int half_ = 0; half_ < 2; half_++) {
                int mm = m + half_ * 8;
                float v0 = acc[mi][ni][half_ * 2 + 0] + bias[n + 0];
                float v1 = acc[mi][ni][half_ * 2 + 1] + bias[n + 1];
                *(__half2*)(C + (size_t)mm * N + n) = __floats2half2_rn(v0, v1);
            }
        }
    }
}

// ---------------- 64x64 GEMM, 2-stage (occ 6), templated epilogue ----------------
#define STGA64 (64*SKH)
#define STGB64 (32*SNB64)
#define SMEM_G64 ((2*STGA64 + 2*STGB64)*2)
template<int EPI>   // 1: bias+res -> float, 2: bias+gelu -> half
__global__ __launch_bounds__(128, 6)
void gemm_h64(const __half* __restrict__ A, const __half* __restrict__ B,
              const float* __restrict__ bias, const float* __restrict__ res,
              void* __restrict__ Cv, int M, int N, int K) {
    extern __shared__ __half smh[];
    __half* As = smh;
    __half* Bs = smh + 2 * STGA64;

    const int tid  = threadIdx.x;
    const int lane = tid & 31, wid = tid >> 5;
    const int wm = (wid & 1) * 32, wn = (wid >> 1) * 32;
    const int g = lane >> 2, tq = lane & 3;
    const int m0 = blockIdx.y * 64, n0 = blockIdx.x * 64;

    const uint32_t sAu = (uint32_t)__cvta_generic_to_shared(As);
    const uint32_t sBu = (uint32_t)__cvta_generic_to_shared(Bs);

    const int arow = tid >> 1, acol = (tid & 1) << 4;
    const int brow = tid >> 3, bcol = (tid & 7) << 3;
    const int mrow = lane & 15, khalf = (lane >> 4) << 3;
    const int vkrow = (lane & 7) + ((lane >> 3) & 1) * 8;
    const int vdoff = (lane >> 4) * 8;
    int aoff[2];
    #pragma unroll
    for (int mi = 0; mi < 2; mi++) aoff[mi] = (wm + mi * 16 + mrow) * SKH + khalf;

    auto load_tile = [&](int t) {
        int k0 = t * 32, st = t & 1;
        int r = arow, c8 = acol >> 1;
        cpa16(sAu + ((st * 64 + r) * SKH + c8) * 2, A + (size_t)(m0 + r) * K + k0 + c8);
        cpa16(sAu + ((st * 64 + r) * SKH + c8 + 16) * 2, A + (size_t)(m0 + r) * K + k0 + c8 + 16);
        #pragma unroll
        for (int it = 0; it < 2; it++) {
            int br = brow + it * 16;
            cpa16(sBu + ((st * 32 + br) * SNB64 + bcol) * 2, B + (size_t)(k0 + br) * N + n0 + bcol);
        }
    };

    float acc[2][4][4] = {};
    const int nt = K / 32;

    load_tile(0);
    asm volatile("cp.async.commit_group;\n");

    for (int t = 0; t < nt; t++) {
        if (t + 1 < nt) load_tile(t + 1);
        asm volatile("cp.async.commit_group;\n");
        asm volatile("cp.async.wait_group 1;\n");
        __syncthreads();

        const int stA = (t & 1) * STGA64;
        const int stB = (t & 1) * STGB64;
        #pragma unroll
        for (int ks = 0; ks < 2; ks++) {
            uint32_t af[2][4], bq[2][4];
            #pragma unroll
            for (int mi = 0; mi < 2; mi++)
                ldsm4(af[mi], sAu + (stA + aoff[mi] + ks * 16) * 2);
            #pragma unroll
            for (int p = 0; p < 2; p++)
                ldsm4t(bq[p], sBu + (stB + (ks * 16 + vkrow) * SNB64 + wn + p * 16 + vdoff) * 2);
            #pragma unroll
            for (int mi = 0; mi < 2; mi++) {
                #pragma unroll
                for (int ni = 0; ni < 4; ni++) {
                    uint32_t bb[2] = { bq[ni >> 1][(ni & 1) * 2], bq[ni >> 1][(ni & 1) * 2 + 1] };
                    mma16(acc[mi][ni], af[mi], bb);
                }
            }
        }
        __syncthreads();
    }

    #pragma unroll
    for (int mi = 0; mi < 2; mi++) {
        #pragma unroll
        for (int ni = 0; ni < 4; ni++) {
            int m = m0 + wm + mi * 16 + g;
            int n = n0 + wn + ni * 8 + tq * 2;
            #pragma unroll
            for (int half_ = 0; half_ < 2; half_++) {
                int mm = m + half_ * 8;
                float v0 = acc[mi][ni][half_ * 2 + 0] + bias[n + 0];
                float v1 = acc[mi][ni][half_ * 2 + 1] + bias[n + 1];
                if (EPI == 1) {
                    float2 rr = *(const float2*)((const float*)res + (size_t)mm * N + n);
                    v0 += rr.x; v1 += rr.y;
                    *(float2*)((float*)Cv + (size_t)mm * N + n) = make_float2(v0, v1);
                } else {
                    v0 = 0.5f * v0 * (1.f + erff(v0 * 0.70710678f));
                    v1 = 0.5f * v1 * (1.f + erff(v1 * 0.70710678f));
                    *(__half2*)((__half*)Cv + (size_t)mm * N + n) = __floats2half2_rn(v0, v1);
                }
            }
        }
    }
}

// ---------------- LM-head GEMM: 3-stage cp.async + fused NLL partials ----------------
#define STG_H (128*SKH)
#define SMEM_LM (6*STG_H*2)   // 110592 bytes; 2 CTAs/SM = 216 KB
__global__ __launch_bounds__(256, 2)
void gemm_lm(const __half* __restrict__ A, const __half* __restrict__ B,
             float* __restrict__ C, float* __restrict__ pm, float* __restrict__ ps,
             int M, int N, int K) {
    extern __shared__ __half smh[];
    __half* As = smh;
    __half* Bs = smh + 3 * STG_H;
    float* sPm = (float*)smh;
    float* sPs = (float*)smh + 512;

    const int tid  = threadIdx.x;
    const int lane = tid & 31, wid = tid >> 5;
    const int wm = (wid & 1) * 64, wn = (wid >> 1) * 32;
    const int g = lane >> 2, tq = lane & 3;
    const int m0 = blockIdx.x * 128, n0 = blockIdx.y * 128;
    const int tileY = blockIdx.y, NTt = gridDim.y;

    const uint32_t sAu = (uint32_t)__cvta_generic_to_shared(As);
    const uint32_t sBu = (uint32_t)__cvta_generic_to_shared(Bs);

    const int arow = tid >> 2, acol = (tid & 3) << 3;
    const int mrow = lane & 15, khalf = (lane >> 4) << 3;
    int aoff[4], boff[2];
    #pragma unroll
    for (int mi = 0; mi < 4; mi++) aoff[mi] = (wm + mi * 16 + mrow) * SKH + khalf;
    #pragma unroll
    for (int p = 0; p < 2; p++)    boff[p]  = (wn + p * 16 + mrow) * SKH + khalf;

    auto load_tile = [&](int t) {
        int k0 = t * 32, st = t % 3;
        #pragma unroll
        for (int it = 0; it < 2; it++) {
            int r = arow + it * 64;
            cpa16(sAu + ((st * 128 + r) * SKH + acol) * 2, A + (size_t)(m0 + r) * K + k0 + acol);
            int n = n0 + r;
            int ok = (n < N);
            cpa16z(sBu + ((st * 128 + r) * SKH + acol) * 2,
                   B + (size_t)(ok ? n : (N - 1)) * K + k0 + acol, ok ? 16 : 0);
        }
    };

    float acc[4][4][4] = {};
    const int nt = K / 32;

    load_tile(0);
    asm volatile("cp.async.commit_group;\n");
    load_tile(1);
    asm volatile("cp.async.commit_group;\n");

    for (int t = 0; t < nt; t++) {
        if (t + 2 < nt) load_tile(t + 2);
        asm volatile("cp.async.commit_group;\n");
        asm volatile("cp.async.wait_group 2;\n");
        __syncthreads();

        const int stO = (t % 3) * STG_H;
        #pragma unroll
        for (int ks = 0; ks < 2; ks++) {
            uint32_t af[4][4], bq[2][4];
            #pragma unroll
            for (int mi = 0; mi < 4; mi++)
                ldsm4(af[mi], sAu + (stO + aoff[mi] + ks * 16) * 2);
            #pragma unroll
            for (int p = 0; p < 2; p++)
                ldsm4(bq[p], sBu + (stO + boff[p] + ks * 16) * 2);
            #pragma unroll
            for (int mi = 0; mi < 4; mi++) {
                #pragma unroll
                for (int ni = 0; ni < 4; ni++) {
                    uint32_t bb[2] = { bq[ni >> 1][ni & 1], bq[ni >> 1][(ni & 1) + 2] };
                    mma16(acc[mi][ni], af[mi], bb);
                }
            }
        }
        __syncthreads();
    }

    // scalar stores (row stride N=50257 is odd: vector stores would misalign)
    #pragma unroll
    for (int mi = 0; mi < 4; mi++) {
        #pragma unroll
        for (int ni = 0; ni < 4; ni++) {
            int m = m0 + wm + mi * 16 + g;
            int n = n0 + wn + ni * 8 + tq * 2;
            #pragma unroll
            for (int half_ = 0; half_ < 2; half_++) {
                int mm = m + half_ * 8;
                #pragma unroll
                for (int e = 0; e < 2; e++) {
                    int nn = n + e;
                    if (nn >= N) continue;
                    C[(size_t)mm * N + nn] = acc[mi][ni][half_ * 2 + e];
                }
            }
        }
    }

    __syncthreads();
    #pragma unroll
    for (int mi = 0; mi < 4; mi++) {
        #pragma unroll
        for (int half_ = 0; half_ < 2; half_++) {
            float lm = -1e30f, lsum = 0.f;
            #pragma unroll
            for (int ni = 0; ni < 4; ni++) {
                #pragma unroll
                for (int e = 0; e < 2; e++) {
                    int nn = n0 + wn + ni * 8 + tq * 2 + e;
                    if (nn < N) lm = fmaxf(lm, acc[mi][ni][half_ * 2 + e]);
                }
            }
            #pragma unroll
            for (int ni = 0; ni < 4; ni++) {
                #pragma unroll
                for (int e = 0; e < 2; e++) {
                    int nn = n0 + wn + ni * 8 + tq * 2 + e;
                    if (nn < N) lsum += __expf(acc[mi][ni][half_ * 2 + e] - lm);
                }
            }
            #pragma unroll
            for (int o = 1; o <= 2; o <<= 1) {
                float m2 = __shfl_xor_sync(0xffffffffu, lm, o);
                float s2 = __shfl_xor_sync(0xffffffffu, lsum, o);
                lse_merge(lm, lsum, m2, s2);
            }
            if (tq == 0) {
                int rl = wm + mi * 16 + half_ * 8 + g;
                sPm[rl * 4 + (wid >> 1)] = lm;
                sPs[rl * 4 + (wid >> 1)] = lsum;
            }
        }
    }
    __syncthreads();
    if (tid < 128) {
        float M_ = sPm[tid * 4], S_ = sPs[tid * 4];
        #pragma unroll
        for (int gi = 1; gi < 4; gi++) lse_merge(M_, S_, sPm[tid * 4 + gi], sPs[tid * 4 + gi]);
        pm[(size_t)(m0 + tid) * NTt + tileY] = M_;
        ps[(size_t)(m0 + tid) * NTt + tileY] = S_;
    }
}

// ---------------- flash attention: register-P + split-K with in-kernel combine ----------------
#define FQH 72
#define FTILE (64*FQH)
#define SMEM_FL (5*FTILE*2)
__global__ __launch_bounds__(128, 4)
void flash_h(const __half* __restrict__ qkv, __half* __restrict__ out,
             float* __restrict__ pO, float2* __restrict__ pml,
             int* __restrict__ flags, int gen) {
    extern __shared__ __half smh[];
    __half* Qs = smh;
    const uint32_t sQ = (uint32_t)__cvta_generic_to_shared(Qs);
    const uint32_t sK[2] = { sQ + FTILE * 2,     sQ + 2 * FTILE * 2 };
    const uint32_t sV[2] = { sQ + 3 * FTILE * 2, sQ + 4 * FTILE * 2 };

    const int tid = threadIdx.x;
    const int lane = tid & 31, wid = tid >> 5;
    const int g = lane >> 2, tq = lane & 3;
    const int h = blockIdx.y, b = blockIdx.z;
    const int r0 = wid * 16 + g;

    int qi, kt0, kt1, role;
    const int bx = blockIdx.x;
    if (bx < 16) {
        qi = bx;
        if (qi < 8) { kt0 = 0; kt1 = qi + 1; role = 0; }
        else        { kt0 = 0; kt1 = (qi + 2) >> 1; role = 1; }
    } else {
        qi = bx - 8;
        kt0 = (qi + 2) >> 1; kt1 = qi + 1; role = 2;
    }
    const int q0 = qi * 64;

    auto loadKV = [&](int t, int st) {
        int k0 = t * 64;
        #pragma unroll
        for (int i = 0; i < 4; i++) {
            int idx = tid + i * 128;
            int r = idx >> 3, c8 = (idx & 7) << 3;
            const __half* src = qkv + (size_t)(b * TQ + k0 + r) * (3 * DQ) + h * HD + c8;
            cpa16(sK[st] + (r * FQH + c8) * 2, src + DQ);
            cpa16(sV[st] + (r * FQH + c8) * 2, src + 2 * DQ);
        }
    };

    const int vkrow = (lane & 7) + ((lane >> 3) & 1) * 8;
    const int vdoff = (lane >> 4) * 8;

    const __half2 sc8 = __floats2half2_rn(0.125f, 0.125f);
    #pragma unroll
    for (int i = 0; i < 4; i++) {
        int idx = tid + i * 128;
        int r = idx >> 3, c8 = (idx & 7) << 3;
        uint4 raw = *(const uint4*)(qkv + (size_t)(b * TQ + q0 + r) * (3 * DQ) + h * HD + c8);
        __half2* hp = (__half2*)&raw;
        hp[0] = __hmul2(hp[0], sc8); hp[1] = __hmul2(hp[1], sc8);
        hp[2] = __hmul2(hp[2], sc8); hp[3] = __hmul2(hp[3], sc8);
        *(uint4*)(Qs + r * FQH + c8) = raw;
    }

    loadKV(kt0, 0);
    asm volatile("cp.async.commit_group;\n");
    __syncthreads();

    uint32_t qf[4][4];
    #pragma unroll
    for (int kk = 0; kk < 4; kk++) {
        qf[kk][0] = *(const uint32_t*)(Qs + r0 * FQH + kk * 16 + 2 * tq);
        qf[kk][1] = *(const uint32_t*)(Qs + (r0 + 8) * FQH + kk * 16 + 2 * tq);
        qf[kk][2] = *(const uint32_t*)(Qs + r0 * FQH + kk * 16 + 8 + 2 * tq);
        qf[kk][3] = *(const uint32_t*)(Qs + (r0 + 8) * FQH + kk * 16 + 8 + 2 * tq);
    }

    float m0r = -1e30f, m1r = -1e30f, l0 = 0.f, l1 = 0.f;
    float oc[8][4] = {};

    for (int kt = kt0; kt < kt1; kt++) {
        const int li = kt - kt0;
        const int st = li & 1;
        if (kt + 1 < kt1) {
            loadKV(kt + 1, st ^ 1);
            asm volatile("cp.async.commit_group;\n");
            asm volatile("cp.async.wait_group 1;\n");
        } else {
            asm volatile("cp.async.wait_group 0;\n");
        }
        __syncthreads();

        const __half* Kb = (const __half*)((const char*)smh + (sK[st] - sQ));
        float sc[8][4] = {};
        #pragma unroll
        for (int kk = 0; kk < 4; kk++) {
            #pragma unroll
            for (int ni = 0; ni < 8; ni++) {
                uint32_t bb[2];
                bb[0] = *(const uint32_t*)(Kb + (ni * 8 + g) * FQH + kk * 16 + 2 * tq);
                bb[1] = *(const uint32_t*)(Kb + (ni * 8 + g) * FQH + kk * 16 + 8 + 2 * tq);
                mma16(sc[ni], qf[kk], bb);
            }
        }

        if (role != 1 && kt == kt1 - 1) {
            #pragma unroll
            for (int ni = 0; ni < 8; ni++) {
                int c0 = ni * 8 + 2 * tq, c1 = c0 + 1;
                if (c0 > r0) sc[ni][0] = -1e30f;
                if (c1 > r0) sc[ni][1] = -1e30f;
                if (c0 > r0 + 8) sc[ni][2] = -1e30f;
                if (c1 > r0 + 8) sc[ni][3] = -1e30f;
            }
        }

        float mx0 = -1e30f, mx1 = -1e30f;
        #pragma unroll
        for (int ni = 0; ni < 8; ni++) {
            mx0 = fmaxf(mx0, fmaxf(sc[ni][0], sc[ni][1]));
            mx1 = fmaxf(mx1, fmaxf(sc[ni][2], sc[ni][3]));
        }
        #pragma unroll
        for (int o = 1; o <= 2; o <<= 1) {
            mx0 = fmaxf(mx0, __shfl_xor_sync(0xffffffffu, mx0, o));
            mx1 = fmaxf(mx1, __shfl_xor_sync(0xffffffffu, mx1, o));
        }
        float nm0 = fmaxf(m0r, mx0), nm1 = fmaxf(m1r, mx1);
        float cr0 = __expf(m0r - nm0), cr1 = __expf(m1r - nm1);
        float rs0 = 0.f, rs1 = 0.f;
        #pragma unroll
        for (int ni = 0; ni < 8; ni++) {
            sc[ni][0] = __expf(sc[ni][0] - nm0); rs0 += sc[ni][0];
            sc[ni][1] = __expf(sc[ni][1] - nm0); rs0 += sc[ni][1];
            sc[ni][2] = __expf(sc[ni][2] - nm1); rs1 += sc[ni][2];
            sc[ni][3] = __expf(sc[ni][3] - nm1); rs1 += sc[ni][3];
        }
        #pragma unroll
        for (int o = 1; o <= 2; o <<= 1) {
            rs0 += __shfl_xor_sync(0xffffffffu, rs0, o);
            rs1 += __shfl_xor_sync(0xffffffffu, rs1, o);
        }
        l0 = l0 * cr0 + rs0; l1 = l1 * cr1 + rs1;
        m0r = nm0; m1r = nm1;
        #pragma unroll
        for (int ni = 0; ni < 8; ni++) {
            oc[ni][0] *= cr0; oc[ni][1] *= cr0;
            oc[ni][2] *= cr1; oc[ni][3] *= cr1;
        }

        #pragma unroll
        for (int kk = 0; kk < 4; kk++) {
            uint32_t a[4];
            a[0] = packh2(sc[2 * kk][0],     sc[2 * kk][1]);
            a[1] = packh2(sc[2 * kk][2],     sc[2 * kk][3]);
            a[2] = packh2(sc[2 * kk + 1][0], sc[2 * kk + 1][1]);
            a[3] = packh2(sc[2 * kk + 1][2], sc[2 * kk + 1][3]);
            #pragma unroll
            for (int pr = 0; pr < 4; pr++) {
                uint32_t v4[4];
                ldsm4t(v4, sV[st] + ((kk * 16 + vkrow) * FQH + pr * 16 + vdoff) * 2);
                uint32_t b0[2] = { v4[0], v4[1] };
                uint32_t b1[2] = { v4[2], v4[3] };
                mma16(oc[pr * 2 + 0], a, b0);
                mma16(oc[pr * 2 + 1], a, b1);
            }
        }
        __syncthreads();
    }

    if (role == 0) {
        float i0 = 1.f / l0, i1 = 1.f / l1;
        __half* o0 = out + (size_t)(b * TQ + q0 + r0) * DQ + h * HD;
        __half* o1 = out + (size_t)(b * TQ + q0 + r0 + 8) * DQ + h * HD;
        #pragma unroll
        for (int ni = 0; ni < 8; ni++) {
            *(__half2*)(o0 + ni * 8 + 2 * tq) = __floats2half2_rn(oc[ni][0] * i0, oc[ni][1] * i0);
            *(__half2*)(o1 + ni * 8 + 2 * tq) = __floats2half2_rn(oc[ni][2] * i1, oc[ni][3] * i1);
        }
    } else if (role == 1) {
        const int sidx = (b * HQ + h) * NSPL + (qi - 8);
        float* Od = pO + (size_t)sidx * 4096;
        #pragma unroll
        for (int ni = 0; ni < 8; ni++) {
            int c = ni * 8 + 2 * tq;
            *(float2*)(Od + r0 * 64 + c)       = make_float2(oc[ni][0], oc[ni][1]);
            *(float2*)(Od + (r0 + 8) * 64 + c) = make_float2(oc[ni][2], oc[ni][3]);
        }
        if (tq == 0) {
            pml[(size_t)sidx * 64 + r0]     = make_float2(m0r, l0);
            pml[(size_t)sidx * 64 + r0 + 8] = make_float2(m1r, l1);
        }
        __threadfence();
        __syncthreads();
        if (tid == 0) atomicExch(&flags[sidx], gen);
    } else {
        const int sidx = (b * HQ + h) * NSPL + (qi - 8);
        if (tid == 0) {
            int v;
            do {
                asm volatile("ld.global.acquire.gpu.b32 %0, [%1];"
                             : "=r"(v) : "l"(flags + sidx) : "memory");
            } while (v != gen);
        }
        __syncthreads();
        float2 ml0 = __ldcg((const float2*)pml + (size_t)sidx * 64 + r0);
        float2 ml1 = __ldcg((const float2*)pml + (size_t)sidx * 64 + r0 + 8);
        float M0 = fmaxf(ml0.x, m0r), M1 = fmaxf(ml1.x, m1r);
        float w10 = __expf(ml0.x - M0), w20 = __expf(m0r - M0);
        float w11 = __expf(ml1.x - M1), w21 = __expf(m1r - M1);
        float i0 = 1.f / (ml0.y * w10 + l0 * w20);
        float i1 = 1.f / (ml1.y * w11 + l1 * w21);
        const float* Od = pO + (size_t)sidx * 4096;
        __half* o0 = out + (size_t)(b * TQ + q0 + r0) * DQ + h * HD;
        __half* o1 = out + (size_t)(b * TQ + q0 + r0 + 8) * DQ + h * HD;
        #pragma unroll
        for (int ni = 0; ni < 8; ni++) {
            int c = ni * 8 + 2 * tq;
            float2 a0 = __ldcg((const float2*)(Od + r0 * 64 + c));
            float2 a1 = __ldcg((const float2*)(Od + (r0 + 8) * 64 + c));
            *(__half2*)(o0 + c) = __floats2half2_rn((a0.x * w10 + oc[ni][0] * w20) * i0,
                                                    (a0.y * w10 + oc[ni][1] * w20) * i0);
            *(__half2*)(o1 + c) = __floats2half2_rn((a1.x * w11 + oc[ni][2] * w21) * i1,
                                                    (a1.y * w11 + oc[ni][3] * w21) * i1);
        }
    }
}

// ---------------- NLL reduce + loss ----------------
__global__ void nll_reduce(const float* __restrict__ pm, const float* __restrict__ ps,
                           const float* __restrict__ logits, const int* __restrict__ tgt,
                           float* __restrict__ nll) {
    int row = blockIdx.x, t = threadIdx.x;
    float M = -1e30f, S = 0.f;
    for (int j = t; j < NT_LM; j += 128)
        lse_merge(M, S, pm[(size_t)row * NT_LM + j], ps[(size_t)row * NT_LM + j]);
    __shared__ float sm_[128], ss_[128];
    sm_[t] = M; ss_[t] = S; __syncthreads();
    for (int o = 64; o > 0; o >>= 1) {
        if (t < o) {
            float mm = sm_[t], ssv = ss_[t];
            lse_merge(mm, ssv, sm_[t + o], ss_[t + o]);
            sm_[t] = mm; ss_[t] = ssv;
        }
        __syncthreads();
    }
    if (t == 0) {
        float lse = sm_[0] + logf(ss_[0]);
        nll[row] = lse - logits[(size_t)row * VQ + tgt[row]];
    }
}
__global__ void loss_kernel(const float* __restrict__ nll, float* __restrict__ loss) {
    __shared__ float s[1024];
    float v = nll[threadIdx.x] + nll[threadIdx.x + 1024];
    s[threadIdx.x] = v; __syncthreads();
    for (int o = 512; o > 0; o >>= 1) {
        if (threadIdx.x < o) s[threadIdx.x] += s[threadIdx.x + o];
        __syncthreads();
    }
    if (threadIdx.x == 0) *loss = s[0] * (1.f / 2048.f);
}

// ---------------- launch ----------------
extern "C" void kernel_launch(void* const* d_in, const int* in_sizes, int n_in,
                              void* d_out, int out_size) {
    const int*   ids  = (const int*)d_in[0];
    const int*   tgt  = (const int*)d_in[1];
    const float* tok  = (const float*)d_in[2];
    const float* pos  = (const float*)d_in[3];
    const float* ln1w = (const float*)d_in[4];
    const float* ln1b = (const float*)d_in[5];
    const float* qkvw = (const float*)d_in[6];
    const float* qkvb = (const float*)d_in[7];
    const float* apw  = (const float*)d_in[8];
    const float* apb  = (const float*)d_in[9];
    const float* ln2w = (const float*)d_in[10];
    const float* ln2b = (const float*)d_in[11];
    const float* fcw  = (const float*)d_in[12];
    const float* fcb  = (const float*)d_in[13];
    const float* pw   = (const float*)d_in[14];
    const float* pb   = (const float*)d_in[15];
    const float* lnfw = (const float*)d_in[16];
    const float* lnfb = (const float*)d_in[17];

    float *x, *nll, *lfb, *pm, *ps, *pO;
    float2* pml;
    int* flags;
    __half *h, *qkv, *attn, *ffn;
    __half *wqkv, *wap, *wfc, *wpr, *tokt;
    cudaGetSymbolAddress((void**)&x,    g_x);
    cudaGetSymbolAddress((void**)&h,    g_h);
    cudaGetSymbolAddress((void**)&qkv,  g_qkv);
    cudaGetSymbolAddress((void**)&attn, g_attn);
    cudaGetSymbolAddress((void**)&ffn,  g_ffn);
    cudaGetSymbolAddress((void**)&nll,  g_nll);
    cudaGetSymbolAddress((void**)&lfb,  g_logits_fb);
    cudaGetSymbolAddress((void**)&pm,   g_pm);
    cudaGetSymbolAddress((void**)&ps,   g_ps);
    cudaGetSymbolAddress((void**)&pO,   g_pO);
    cudaGetSymbolAddress((void**)&pml,  g_pml);
    cudaGetSymbolAddress((void**)&flags, g_flag);
    cudaGetSymbolAddress((void**)&wqkv, g_wqkv);
    cudaGetSymbolAddress((void**)&wap,  g_wap);
    cudaGetSymbolAddress((void**)&wfc,  g_wfc);
    cudaGetSymbolAddress((void**)&wpr,  g_wpr);
    cudaGetSymbolAddress((void**)&tokt, g_tokt);

    cudaFuncSetAttribute(flash_h,      cudaFuncAttributeMaxDynamicSharedMemorySize, SMEM_FL);
    cudaFuncSetAttribute(gemm_h,       cudaFuncAttributeMaxDynamicSharedMemorySize, SMEM_GEMM);
    cudaFuncSetAttribute(gemm_h64<1>,  cudaFuncAttributeMaxDynamicSharedMemorySize, SMEM_G64);
    cudaFuncSetAttribute(gemm_h64<2>,  cudaFuncAttributeMaxDynamicSharedMemorySize, SMEM_G64);
    cudaFuncSetAttribute(gemm_lm,      cudaFuncAttributeMaxDynamicSharedMemorySize, SMEM_LM);

    const long long LOGN = (long long)BT * VQ;
    float* out    = (float*)d_out;
    float* logits;
    float* lossp  = nullptr;
    if ((long long)out_size > LOGN) {
        lossp  = out;
        logits = out + ((long long)out_size - LOGN);
    } else if ((long long)out_size == LOGN) {
        logits = out;
    } else {
        lossp  = out;
        logits = lfb;
    }

    cvt_all<<<(CVT_TOT + 255) / 256, 256>>>(
        (const float4*)qkvw, (const float4*)apw, (const float4*)fcw,
        (const float4*)pw,   (const float4*)tok,
        (uint4*)wqkv, (uint4*)wap, (uint4*)wfc, (uint4*)wpr, (uint4*)tokt);

    for (int l = 0; l < LQ; l++) {
        if (l == 0)
            embedln_kernel<<<BT/8, 256>>>(ids, tok, pos, ln1w, ln1b, x, h);
        else
            ln_kernel<<<BT/8, 256>>>(x, ln1w + l * DQ, ln1b + l * DQ, h);
        gemm_h<<<dim3((3 * DQ) / 128, BT / 128), 256, SMEM_GEMM>>>(
            h, wqkv + (size_t)l * DQ * 3 * DQ, qkvb + l * 3 * DQ, qkv, BT, 3 * DQ, DQ);
        flash_h<<<dim3(TQ / 64 + NSPL, HQ, BQ), 128, SMEM_FL>>>(qkv, attn, pO, pml, flags, l + 1);
        gemm_h64<1><<<dim3(DQ / 64, BT / 64), 128, SMEM_G64>>>(
            attn, wap + (size_t)l * DQ * DQ, apb + l * DQ, x, x, BT, DQ, DQ);
        ln_kernel<<<BT/8, 256>>>(x, ln2w + l * DQ, ln2b + l * DQ, h);
        gemm_h64<2><<<dim3((4 * DQ) / 64, BT / 64), 128, SMEM_G64>>>(
            h, wfc + (size_t)l * DQ * 4 * DQ, fcb + l * 4 * DQ, nullptr, ffn, BT, 4 * DQ, DQ);
        gemm_h64<1><<<dim3(DQ / 64, BT / 64), 128, SMEM_G64>>>(
            ffn, wpr + (size_t)l * 4 * DQ * DQ, pb + l * DQ, x, x, BT, DQ, 4 * DQ);
    }

    ln_kernel<<<BT/8, 256>>>(x, lnfw, lnfb, h);
    gemm_lm<<<dim3(BT / 128, NT_LM), 256, SMEM_LM>>>(
        h, tokt, logits, pm, ps, BT, VQ, DQ);

    if (lossp) {
        nll_reduce<<<BT, 128>>>(pm, ps, logits, tgt, nll);
        loss_kernel<<<1, 1024>>>(nll, lossp);
    }
}

// round 17
// speedup vs baseline: 2.0578x; 1.1582x over previous
#include <cuda_runtime.h>
#include <cuda_fp16.h>
#include <math.h>
#include <stdint.h>

// ---------------- problem constants ----------------
#define BQ 2
#define TQ 1024
#define DQ 768
#define LQ 4
#define HQ 12
#define VQ 50257
#define BT (BQ*TQ)
#define HD 64
#define NT_LM 393
#define NBH (BQ*HQ)
#define NSPL 8

// ---------------- scratch ----------------
__device__ float  g_x   [BT*DQ];
__device__ __half g_h   [BT*DQ];
__device__ __half g_qkv [BT*3*DQ];
__device__ __half g_attn[BT*DQ];
__device__ __half g_ffn [BT*4*DQ];
__device__ float  g_nll [BT];
__device__ float  g_pm  [BT*NT_LM];
__device__ float  g_ps  [BT*NT_LM];
__device__ float  g_logits_fb[102926336];
__device__ float  g_pO  [NBH*NSPL*64*64];
__device__ float2 g_pml [NBH*NSPL*64];
__device__ int    g_flag[NBH*NSPL];
__device__ __half g_wqkv[LQ*DQ*3*DQ];
__device__ __half g_wap [LQ*DQ*DQ];
__device__ __half g_wfc [LQ*DQ*4*DQ];
__device__ __half g_wpr [LQ*4*DQ*DQ];
__device__ __half g_tokt[(size_t)VQ*DQ];

__device__ __forceinline__ void lse_merge(float& m, float& s, float m2, float s2) {
    float M = fmaxf(m, m2);
    s = s * __expf(m - M) + s2 * __expf(m2 - M);
    m = M;
}

// ---------------- merged fp16 convert ----------------
#define CV0 884736
#define CV1 294912
#define CV2 1179648
#define CV3 1179648
#define CV4 4824672
#define CVT_TOT (CV0+CV1+CV2+CV3+CV4)
__global__ void cvt_all(const float4* __restrict__ s0, const float4* __restrict__ s1,
                        const float4* __restrict__ s2, const float4* __restrict__ s3,
                        const float4* __restrict__ s4,
                        uint4* __restrict__ d0, uint4* __restrict__ d1,
                        uint4* __restrict__ d2, uint4* __restrict__ d3,
                        uint4* __restrict__ d4) {
    int i = blockIdx.x * 256 + threadIdx.x;
    if (i >= CVT_TOT) return;
    const float4* s; uint4* d; int off = i;
    if (off < CV0) { s = s0; d = d0; }
    else if ((off -= CV0) < CV1) { s = s1; d = d1; }
    else if ((off -= CV1) < CV2) { s = s2; d = d2; }
    else if ((off -= CV2) < CV3) { s = s3; d = d3; }
    else { off -= CV3; s = s4; d = d4; }
    float4 a = s[2 * off], b = s[2 * off + 1];
    __half2 h0 = __floats2half2_rn(a.x, a.y);
    __half2 h1 = __floats2half2_rn(a.z, a.w);
    __half2 h2 = __floats2half2_rn(b.x, b.y);
    __half2 h3 = __floats2half2_rn(b.z, b.w);
    d[off] = make_uint4(*(uint32_t*)&h0, *(uint32_t*)&h1, *(uint32_t*)&h2, *(uint32_t*)&h3);
}

// ---------------- fused embedding + layernorm (layer 0) ----------------
__global__ __launch_bounds__(256)
void embedln_kernel(const int* __restrict__ ids, const float* __restrict__ tok,
                    const float* __restrict__ pos, const float* __restrict__ w,
                    const float* __restrict__ b, float* __restrict__ x,
                    __half* __restrict__ y) {
    const int wid = threadIdx.x >> 5, lane = threadIdx.x & 31;
    const int row = blockIdx.x * 8 + wid;
    const float* te = tok + (size_t)ids[row] * DQ;
    const float* pe = pos + (size_t)(row % TQ) * DQ;
    float4 v[6];
    float s = 0.f, q = 0.f;
    #pragma unroll
    for (int i = 0; i < 6; i++) {
        int c = lane * 4 + i * 128;
        float4 t = *(const float4*)(te + c);
        float4 p = *(const float4*)(pe + c);
        v[i] = make_float4(t.x + p.x, t.y + p.y, t.z + p.z, t.w + p.w);
        *(float4*)(x + (size_t)row * DQ + c) = v[i];
        s += v[i].x + v[i].y + v[i].z + v[i].w;
        q += v[i].x * v[i].x + v[i].y * v[i].y + v[i].z * v[i].z + v[i].w * v[i].w;
    }
    #pragma unroll
    for (int o = 16; o > 0; o >>= 1) {
        s += __shfl_xor_sync(0xffffffffu, s, o);
        q += __shfl_xor_sync(0xffffffffu, q, o);
    }
    float mean = s * (1.f / DQ);
    float var  = q * (1.f / DQ) - mean * mean;
    float inv  = rsqrtf(var + 1e-5f);
    __half* yr = y + (size_t)row * DQ;
    #pragma unroll
    for (int i = 0; i < 6; i++) {
        int c = lane * 4 + i * 128;
        float4 wv = *(const float4*)(w + c);
        float4 bv = *(const float4*)(b + c);
        __half2 h0 = __floats2half2_rn((v[i].x - mean) * inv * wv.x + bv.x,
                                       (v[i].y - mean) * inv * wv.y + bv.y);
        __half2 h1 = __floats2half2_rn((v[i].z - mean) * inv * wv.z + bv.z,
                                       (v[i].w - mean) * inv * wv.w + bv.w);
        *(uint2*)(yr + c) = make_uint2(*(uint32_t*)&h0, *(uint32_t*)&h1);
    }
}

// ---------------- layernorm: warp per row ----------------
__global__ __launch_bounds__(256)
void ln_kernel(const float* __restrict__ x, const float* __restrict__ w,
               const float* __restrict__ b, __half* __restrict__ y) {
    const int wid = threadIdx.x >> 5, lane = threadIdx.x & 31;
    const int row = blockIdx.x * 8 + wid;
    const float* xr = x + (size_t)row * DQ;
    float4 v[6];
    float s = 0.f, q = 0.f;
    #pragma unroll
    for (int i = 0; i < 6; i++) {
        v[i] = *(const float4*)(xr + lane * 4 + i * 128);
        s += v[i].x + v[i].y + v[i].z + v[i].w;
        q += v[i].x * v[i].x + v[i].y * v[i].y + v[i].z * v[i].z + v[i].w * v[i].w;
    }
    #pragma unroll
    for (int o = 16; o > 0; o >>= 1) {
        s += __shfl_xor_sync(0xffffffffu, s, o);
        q += __shfl_xor_sync(0xffffffffu, q, o);
    }
    float mean = s * (1.f / DQ);
    float var  = q * (1.f / DQ) - mean * mean;
    float inv  = rsqrtf(var + 1e-5f);
    __half* yr = y + (size_t)row * DQ;
    #pragma unroll
    for (int i = 0; i < 6; i++) {
        int c = lane * 4 + i * 128;
        float4 wv = *(const float4*)(w + c);
        float4 bv = *(const float4*)(b + c);
        __half2 h0 = __floats2half2_rn((v[i].x - mean) * inv * wv.x + bv.x,
                                       (v[i].y - mean) * inv * wv.y + bv.y);
        __half2 h1 = __floats2half2_rn((v[i].z - mean) * inv * wv.z + bv.z,
                                       (v[i].w - mean) * inv * wv.w + bv.w);
        *(uint2*)(yr + c) = make_uint2(*(uint32_t*)&h0, *(uint32_t*)&h1);
    }
}

// ---------------- fp16 mma / cp.async / ldmatrix helpers ----------------
__device__ __forceinline__ void mma16(float* c, const uint32_t* a, const uint32_t* b) {
    asm volatile("mma.sync.aligned.m16n8k16.row.col.f32.f16.f16.f32 "
                 "{%0,%1,%2,%3}, {%4,%5,%6,%7}, {%8,%9}, {%0,%1,%2,%3};\n"
                 : "+f"(c[0]), "+f"(c[1]), "+f"(c[2]), "+f"(c[3])
                 : "r"(a[0]), "r"(a[1]), "r"(a[2]), "r"(a[3]), "r"(b[0]), "r"(b[1]));
}
__device__ __forceinline__ void cpa16(uint32_t dst, const void* src) {
    asm volatile("cp.async.cg.shared.global [%0], [%1], 16;\n" :: "r"(dst), "l"(src));
}
__device__ __forceinline__ void cpa16z(uint32_t dst, const void* src, int bytes) {
    asm volatile("cp.async.cg.shared.global [%0], [%1], 16, %2;\n" :: "r"(dst), "l"(src), "r"(bytes));
}
__device__ __forceinline__ void ldsm4(uint32_t* r, uint32_t addr) {
    asm volatile("ldmatrix.sync.aligned.m8n8.x4.shared.b16 {%0,%1,%2,%3}, [%4];\n"
                 : "=r"(r[0]), "=r"(r[1]), "=r"(r[2]), "=r"(r[3]) : "r"(addr));
}
__device__ __forceinline__ void ldsm4t(uint32_t* r, uint32_t addr) {
    asm volatile("ldmatrix.sync.aligned.m8n8.x4.trans.shared.b16 {%0,%1,%2,%3}, [%4];\n"
                 : "=r"(r[0]), "=r"(r[1]), "=r"(r[2]), "=r"(r[3]) : "r"(addr));
}
__device__ __forceinline__ uint32_t packh2(float a, float b) {
    __half2 h = __floats2half2_rn(a, b);
    return *(uint32_t*)&h;
}

#define SKH 72
#define SNB 136
#define SNB64 72

// ---------------- 128x128 GEMM (qkv): BK=64, 2-stage ----------------
#define STGA_H   (128*SKH)          // 9216 halves
#define STGB_H   (64*SNB)           // 8704 halves
#define SMEM_GEMM ((2*(STGA_H + STGB_H))*2)   // 71680 B; 2 CTAs/SM
__global__ __launch_bounds__(256, 2)
void gemm_h(const __half* __restrict__ A, const __half* __restrict__ B,
            const float* __restrict__ bias, __half* __restrict__ C,
            int M, int N, int K) {
    extern __shared__ __half smh[];
    __half* As = smh;
    __half* Bs = smh + 2 * STGA_H;

    const int tid  = threadIdx.x;
    const int lane = tid & 31, wid = tid >> 5;
    const int wm = (wid & 1) * 64, wn = (wid >> 1) * 32;
    const int g = lane >> 2, tq = lane & 3;
    const int m0 = blockIdx.y * 128, n0 = blockIdx.x * 128;

    const uint32_t sAu = (uint32_t)__cvta_generic_to_shared(As);
    const uint32_t sBu = (uint32_t)__cvta_generic_to_shared(Bs);

    const int mrow = lane & 15, khalf = (lane >> 4) << 3;
    const int vkrow = (lane & 7) + ((lane >> 3) & 1) * 8;
    const int vdoff = (lane >> 4) * 8;
    int aoff[4];
    #pragma unroll
    for (int mi = 0; mi < 4; mi++) aoff[mi] = (wm + mi * 16 + mrow) * SKH + khalf;

    auto load_tile = [&](int t) {
        int k0 = t * 64, st = t & 1;
        #pragma unroll
        for (int it = 0; it < 4; it++) {
            int idx = tid + it * 256;
            int r = idx >> 3, c8 = (idx & 7) << 3;        // A: 128 rows x 64 halves
            cpa16(sAu + ((st * 128 + r) * SKH + c8) * 2, A + (size_t)(m0 + r) * K + k0 + c8);
            int kr = idx >> 4, cb = (idx & 15) << 3;      // B: 64 krows x 128 n
            cpa16(sBu + ((st * 64 + kr) * SNB + cb) * 2, B + (size_t)(k0 + kr) * N + n0 + cb);
        }
    };

    float acc[4][4][4] = {};
    const int nt = K / 64;

    load_tile(0);
    asm volatile("cp.async.commit_group;\n");

    for (int t = 0; t < nt; t++) {
        if (t + 1 < nt) load_tile(t + 1);
        asm volatile("cp.async.commit_group;\n");
        asm volatile("cp.async.wait_group 1;\n");
        __syncthreads();

        const int stA = (t & 1) * STGA_H;
        const int stB = (t & 1) * STGB_H;
        #pragma unroll
        for (int ks = 0; ks < 4; ks++) {
            uint32_t af[4][4], bq[2][4];
            #pragma unroll
            for (int mi = 0; mi < 4; mi++)
                ldsm4(af[mi], sAu + (stA + aoff[mi] + ks * 16) * 2);
            #pragma unroll
            for (int p = 0; p < 2; p++)
                ldsm4t(bq[p], sBu + (stB + (ks * 16 + vkrow) * SNB + wn + p * 16 + vdoff) * 2);
            #pragma unroll
            for (int mi = 0; mi < 4; mi++) {
                #pragma unroll
                for (int ni = 0; ni < 4; ni++) {
                    uint32_t bb[2] = { bq[ni >> 1][(ni & 1) * 2], bq[ni >> 1][(ni & 1) * 2 + 1] };
                    mma16(acc[mi][ni], af[mi], bb);
                }
            }
        }
        __syncthreads();
    }

    #pragma unroll
    for (int mi = 0; mi < 4; mi++) {
        #pragma unroll
        for (int ni = 0; ni < 4; ni++) {
            int m = m0 + wm + mi * 16 + g;
            int n = n0 + wn + ni * 8 + tq * 2;
            #pragma unroll
            for (int half_ = 0; half_ < 2; half_++) {
                int mm = m + half_ * 8;
                float v0 = acc[mi][ni][half_ * 2 + 0] + bias[n + 0];
                float v1 = acc[mi][ni][half_ * 2 + 1] + bias[n + 1];
                *(__half2*)(C + (size_t)mm * N + n) = __floats2half2_rn(v0, v1);
            }
        }
    }
}

// ---------------- 64x64 GEMM: BK=64, 2-stage, occ 6, templated epilogue ----------------
#define STGA64 (64*SKH)
#define STGB64 (64*SNB64)
#define SMEM_G64 ((2*(STGA64 + STGB64))*2)   // 36864 B; occ 6 = 221 KB
template<int EPI>   // 1: bias+res -> float, 2: bias+gelu -> half
__global__ __launch_bounds__(128, 6)
void gemm_h64(const __half* __restrict__ A, const __half* __restrict__ B,
              const float* __restrict__ bias, const float* __restrict__ res,
              void* __restrict__ Cv, int M, int N, int K) {
    extern __shared__ __half smh[];
    __half* As = smh;
    __half* Bs = smh + 2 * STGA64;

    const int tid  = threadIdx.x;
    const int lane = tid & 31, wid = tid >> 5;
    const int wm = (wid & 1) * 32, wn = (wid >> 1) * 32;
    const int g = lane >> 2, tq = lane & 3;
    const int m0 = blockIdx.y * 64, n0 = blockIdx.x * 64;

    const uint32_t sAu = (uint32_t)__cvta_generic_to_shared(As);
    const uint32_t sBu = (uint32_t)__cvta_generic_to_shared(Bs);

    const int mrow = lane & 15, khalf = (lane >> 4) << 3;
    const int vkrow = (lane & 7) + ((lane >> 3) & 1) * 8;
    const int vdoff = (lane >> 4) * 8;
    int aoff[2];
    #pragma unroll
    for (int mi = 0; mi < 2; mi++) aoff[mi] = (wm + mi * 16 + mrow) * SKH + khalf;

    auto load_tile = [&](int t) {
        int k0 = t * 64, st = t & 1;
        #pragma unroll
        for (int it = 0; it < 4; it++) {
            int idx = tid + it * 128;
            int r = idx >> 3, c8 = (idx & 7) << 3;   // 64 rows x 64 halves
            cpa16(sAu + ((st * 64 + r) * SKH + c8) * 2, A + (size_t)(m0 + r) * K + k0 + c8);
            cpa16(sBu + ((st * 64 + r) * SNB64 + c8) * 2, B + (size_t)(k0 + r) * N + n0 + c8);
        }
    };

    float acc[2][4][4] = {};
    const int nt = K / 64;

    load_tile(0);
    asm volatile("cp.async.commit_group;\n");

    for (int t = 0; t < nt; t++) {
        if (t + 1 < nt) load_tile(t + 1);
        asm volatile("cp.async.commit_group;\n");
        asm volatile("cp.async.wait_group 1;\n");
        __syncthreads();

        const int stA = (t & 1) * STGA64;
        const int stB = (t & 1) * STGB64;
        #pragma unroll
        for (int ks = 0; ks < 4; ks++) {
            uint32_t af[2][4], bq[2][4];
            #pragma unroll
            for (int mi = 0; mi < 2; mi++)
                ldsm4(af[mi], sAu + (stA + aoff[mi] + ks * 16) * 2);
            #pragma unroll
            for (int p = 0; p < 2; p++)
                ldsm4t(bq[p], sBu + (stB + (ks * 16 + vkrow) * SNB64 + wn + p * 16 + vdoff) * 2);
            #pragma unroll
            for (int mi = 0; mi < 2; mi++) {
                #pragma unroll
                for (int ni = 0; ni < 4; ni++) {
                    uint32_t bb[2] = { bq[ni >> 1][(ni & 1) * 2], bq[ni >> 1][(ni & 1) * 2 + 1] };
                    mma16(acc[mi][ni], af[mi], bb);
                }
            }
        }
        __syncthreads();
    }

    #pragma unroll
    for (int mi = 0; mi < 2; mi++) {
        #pragma unroll
        for (int ni = 0; ni < 4; ni++) {
            int m = m0 + wm + mi * 16 + g;
            int n = n0 + wn + ni * 8 + tq * 2;
            #pragma unroll
            for (int half_ = 0; half_ < 2; half_++) {
                int mm = m + half_ * 8;
                float v0 = acc[mi][ni][half_ * 2 + 0] + bias[n + 0];
                float v1 = acc[mi][ni][half_ * 2 + 1] + bias[n + 1];
                if (EPI == 1) {
                    float2 rr = *(const float2*)((const float*)res + (size_t)mm * N + n);
                    v0 += rr.x; v1 += rr.y;
                    *(float2*)((float*)Cv + (size_t)mm * N + n) = make_float2(v0, v1);
                } else {
                    v0 = 0.5f * v0 * (1.f + erff(v0 * 0.70710678f));
                    v1 = 0.5f * v1 * (1.f + erff(v1 * 0.70710678f));
                    *(__half2*)((__half*)Cv + (size_t)mm * N + n) = __floats2half2_rn(v0, v1);
                }
            }
        }
    }
}

// ---------------- LM-head GEMM: BK=64, 2-stage + fused NLL partials ----------------
#define STG_H (128*SKH)
#define SMEM_LM ((2*(STG_H + STG_H))*2)   // 73728 B; 2 CTAs/SM
__global__ __launch_bounds__(256, 2)
void gemm_lm(const __half* __restrict__ A, const __half* __restrict__ B,
             float* __restrict__ C, float* __restrict__ pm, float* __restrict__ ps,
             int M, int N, int K) {
    extern __shared__ __half smh[];
    __half* As = smh;
    __half* Bs = smh + 2 * STG_H;
    float* sPm = (float*)smh;
    float* sPs = (float*)smh + 512;

    const int tid  = threadIdx.x;
    const int lane = tid & 31, wid = tid >> 5;
    const int wm = (wid & 1) * 64, wn = (wid >> 1) * 32;
    const int g = lane >> 2, tq = lane & 3;
    const int m0 = blockIdx.x * 128, n0 = blockIdx.y * 128;
    const int tileY = blockIdx.y, NTt = gridDim.y;

    const uint32_t sAu = (uint32_t)__cvta_generic_to_shared(As);
    const uint32_t sBu = (uint32_t)__cvta_generic_to_shared(Bs);

    const int mrow = lane & 15, khalf = (lane >> 4) << 3;
    int aoff[4], boff[2];
    #pragma unroll
    for (int mi = 0; mi < 4; mi++) aoff[mi] = (wm + mi * 16 + mrow) * SKH + khalf;
    #pragma unroll
    for (int p = 0; p < 2; p++)    boff[p]  = (wn + p * 16 + mrow) * SKH + khalf;

    auto load_tile = [&](int t) {
        int k0 = t * 64, st = t & 1;
        #pragma unroll
        for (int it = 0; it < 4; it++) {
            int idx = tid + it * 256;
            int r = idx >> 3, c8 = (idx & 7) << 3;   // 128 rows x 64 halves
            cpa16(sAu + ((st * 128 + r) * SKH + c8) * 2, A + (size_t)(m0 + r) * K + k0 + c8);
            int n = n0 + r;
            int ok = (n < N);
            cpa16z(sBu + ((st * 128 + r) * SKH + c8) * 2,
                   B + (size_t)(ok ? n : (N - 1)) * K + k0 + c8, ok ? 16 : 0);
        }
    };

    float acc[4][4][4] = {};
    const int nt = K / 64;

    load_tile(0);
    asm volatile("cp.async.commit_group;\n");

    for (int t = 0; t < nt; t++) {
        if (t + 1 < nt) load_tile(t + 1);
        asm volatile("cp.async.commit_group;\n");
        asm volatile("cp.async.wait_group 1;\n");
        __syncthreads();

        const int stO = (t & 1) * STG_H;
        #pragma unroll
        for (int ks = 0; ks < 4; ks++) {
            uint32_t af[4][4], bq[2][4];
            #pragma unroll
            for (int mi = 0; mi < 4; mi++)
                ldsm4(af[mi], sAu + (stO + aoff[mi] + ks * 16) * 2);
            #pragma unroll
            for (int p = 0; p < 2; p++)
                ldsm4(bq[p], sBu + (stO + boff[p] + ks * 16) * 2);
            #pragma unroll
            for (int mi = 0; mi < 4; mi++) {
                #pragma unroll
                for (int ni = 0; ni < 4; ni++) {
                    uint32_t bb[2] = { bq[ni >> 1][ni & 1], bq[ni >> 1][(ni & 1) + 2] };
                    mma16(acc[mi][ni], af[mi], bb);
                }
            }
        }
        __syncthreads();
    }

    // scalar stores (row stride N=50257 is odd: vector stores would misalign)
    #pragma unroll
    for (int mi = 0; mi < 4; mi++) {
        #pragma unroll
        for (int ni = 0; ni < 4; ni++) {
            int m = m0 + wm + mi * 16 + g;
            int n = n0 + wn + ni * 8 + tq * 2;
            #pragma unroll
            for (int half_ = 0; half_ < 2; half_++) {
                int mm = m + half_ * 8;
                #pragma unroll
                for (int e = 0; e < 2; e++) {
                    int nn = n + e;
                    if (nn >= N) continue;
                    C[(size_t)mm * N + nn] = acc[mi][ni][half_ * 2 + e];
                }
            }
        }
    }

    __syncthreads();
    #pragma unroll
    for (int mi = 0; mi < 4; mi++) {
        #pragma unroll
        for (int half_ = 0; half_ < 2; half_++) {
            float lm = -1e30f, lsum = 0.f;
            #pragma unroll
            for (int ni = 0; ni < 4; ni++) {
                #pragma unroll
                for (int e = 0; e < 2; e++) {
                    int nn = n0 + wn + ni * 8 + tq * 2 + e;
                    if (nn < N) lm = fmaxf(lm, acc[mi][ni][half_ * 2 + e]);
                }
            }
            #pragma unroll
            for (int ni = 0; ni < 4; ni++) {
                #pragma unroll
                for (int e = 0; e < 2; e++) {
                    int nn = n0 + wn + ni * 8 + tq * 2 + e;
                    if (nn < N) lsum += __expf(acc[mi][ni][half_ * 2 + e] - lm);
                }
            }
            #pragma unroll
            for (int o = 1; o <= 2; o <<= 1) {
                float m2 = __shfl_xor_sync(0xffffffffu, lm, o);
                float s2 = __shfl_xor_sync(0xffffffffu, lsum, o);
                lse_merge(lm, lsum, m2, s2);
            }
            if (tq == 0) {
                int rl = wm + mi * 16 + half_ * 8 + g;
                sPm[rl * 4 + (wid >> 1)] = lm;
                sPs[rl * 4 + (wid >> 1)] = lsum;
            }
        }
    }
    __syncthreads();
    if (tid < 128) {
        float M_ = sPm[tid * 4], S_ = sPs[tid * 4];
        #pragma unroll
        for (int gi = 1; gi < 4; gi++) lse_merge(M_, S_, sPm[tid * 4 + gi], sPs[tid * 4 + gi]);
        pm[(size_t)(m0 + tid) * NTt + tileY] = M_;
        ps[(size_t)(m0 + tid) * NTt + tileY] = S_;
    }
}

// ---------------- flash attention: register-P + split-K with in-kernel combine ----------------
#define FQH 72
#define FTILE (64*FQH)
#define SMEM_FL (5*FTILE*2)
__global__ __launch_bounds__(128, 4)
void flash_h(const __half* __restrict__ qkv, __half* __restrict__ out,
             float* __restrict__ pO, float2* __restrict__ pml,
             int* __restrict__ flags, int gen) {
    extern __shared__ __half smh[];
    __half* Qs = smh;
    const uint32_t sQ = (uint32_t)__cvta_generic_to_shared(Qs);
    const uint32_t sK[2] = { sQ + FTILE * 2,     sQ + 2 * FTILE * 2 };
    const uint32_t sV[2] = { sQ + 3 * FTILE * 2, sQ + 4 * FTILE * 2 };

    const int tid = threadIdx.x;
    const int lane = tid & 31, wid = tid >> 5;
    const int g = lane >> 2, tq = lane & 3;
    const int h = blockIdx.y, b = blockIdx.z;
    const int r0 = wid * 16 + g;

    int qi, kt0, kt1, role;
    const int bx = blockIdx.x;
    if (bx < 16) {
        qi = bx;
        if (qi < 8) { kt0 = 0; kt1 = qi + 1; role = 0; }
        else        { kt0 = 0; kt1 = (qi + 2) >> 1; role = 1; }
    } else {
        qi = bx - 8;
        kt0 = (qi + 2) >> 1; kt1 = qi + 1; role = 2;
    }
    const int q0 = qi * 64;

    auto loadKV = [&](int t, int st) {
        int k0 = t * 64;
        #pragma unroll
        for (int i = 0; i < 4; i++) {
            int idx = tid + i * 128;
            int r = idx >> 3, c8 = (idx & 7) << 3;
            const __half* src = qkv + (size_t)(b * TQ + k0 + r) * (3 * DQ) + h * HD + c8;
            cpa16(sK[st] + (r * FQH + c8) * 2, src + DQ);
            cpa16(sV[st] + (r * FQH + c8) * 2, src + 2 * DQ);
        }
    };

    const int vkrow = (lane & 7) + ((lane >> 3) & 1) * 8;
    const int vdoff = (lane >> 4) * 8;

    // Q via cp.async (unscaled; 1/8 folded into S post-mma)
    #pragma unroll
    for (int i = 0; i < 4; i++) {
        int idx = tid + i * 128;
        int r = idx >> 3, c8 = (idx & 7) << 3;
        cpa16(sQ + (r * FQH + c8) * 2,
              qkv + (size_t)(b * TQ + q0 + r) * (3 * DQ) + h * HD + c8);
    }
    loadKV(kt0, 0);
    asm volatile("cp.async.commit_group;\n");

    uint32_t qf[4][4];
    float m0r = -1e30f, m1r = -1e30f, l0 = 0.f, l1 = 0.f;
    float oc[8][4] = {};

    for (int kt = kt0; kt < kt1; kt++) {
        const int li = kt - kt0;
        const int st = li & 1;
        if (kt + 1 < kt1) {
            loadKV(kt + 1, st ^ 1);
            asm volatile("cp.async.commit_group;\n");
            asm volatile("cp.async.wait_group 1;\n");
        } else {
            asm volatile("cp.async.wait_group 0;\n");
        }
        __syncthreads();

        if (li == 0) {
            #pragma unroll
            for (int kk = 0; kk < 4; kk++) {
                qf[kk][0] = *(const uint32_t*)(Qs + r0 * FQH + kk * 16 + 2 * tq);
                qf[kk][1] = *(const uint32_t*)(Qs + (r0 + 8) * FQH + kk * 16 + 2 * tq);
                qf[kk][2] = *(const uint32_t*)(Qs + r0 * FQH + kk * 16 + 8 + 2 * tq);
                qf[kk][3] = *(const uint32_t*)(Qs + (r0 + 8) * FQH + kk * 16 + 8 + 2 * tq);
            }
        }

        const __half* Kb = (const __half*)((const char*)smh + (sK[st] - sQ));
        float sc[8][4] = {};
        #pragma unroll
        for (int kk = 0; kk < 4; kk++) {
            #pragma unroll
            for (int ni = 0; ni < 8; ni++) {
                uint32_t bb[2];
                bb[0] = *(const uint32_t*)(Kb + (ni * 8 + g) * FQH + kk * 16 + 2 * tq);
                bb[1] = *(const uint32_t*)(Kb + (ni * 8 + g) * FQH + kk * 16 + 8 + 2 * tq);
                mma16(sc[ni], qf[kk], bb);
            }
        }
        // fold 1/sqrt(64) here (fp32, exact scaling by power of 2)
        #pragma unroll
        for (int ni = 0; ni < 8; ni++) {
            sc[ni][0] *= 0.125f; sc[ni][1] *= 0.125f;
            sc[ni][2] *= 0.125f; sc[ni][3] *= 0.125f;
        }

        if (role != 1 && kt == kt1 - 1) {
            #pragma unroll
            for (int ni = 0; ni < 8; ni++) {
                int c0 = ni * 8 + 2 * tq, c1 = c0 + 1;
                if (c0 > r0) sc[ni][0] = -1e30f;
                if (c1 > r0) sc[ni][1] = -1e30f;
                if (c0 > r0 + 8) sc[ni][2] = -1e30f;
                if (c1 > r0 + 8) sc[ni][3] = -1e30f;
            }
        }

        float mx0 = -1e30f, mx1 = -1e30f;
        #pragma unroll
        for (int ni = 0; ni < 8; ni++) {
            mx0 = fmaxf(mx0, fmaxf(sc[ni][0], sc[ni][1]));
            mx1 = fmaxf(mx1, fmaxf(sc[ni][2], sc[ni][3]));
        }
        #pragma unroll
        for (int o = 1; o <= 2; o <<= 1) {
            mx0 = fmaxf(mx0, __shfl_xor_sync(0xffffffffu, mx0, o));
            mx1 = fmaxf(mx1, __shfl_xor_sync(0xffffffffu, mx1, o));
        }
        float nm0 = fmaxf(m0r, mx0), nm1 = fmaxf(m1r, mx1);
        float cr0 = __expf(m0r - nm0), cr1 = __expf(m1r - nm1);
        float rs0 = 0.f, rs1 = 0.f;
        #pragma unroll
        for (int ni = 0; ni < 8; ni++) {
            sc[ni][0] = __expf(sc[ni][0] - nm0); rs0 += sc[ni][0];
            sc[ni][1] = __expf(sc[ni][1] - nm0); rs0 += sc[ni][1];
            sc[ni][2] = __expf(sc[ni][2] - nm1); rs1 += sc[ni][2];
            sc[ni][3] = __expf(sc[ni][3] - nm1); rs1 += sc[ni][3];
        }
        #pragma unroll
        for (int o = 1; o <= 2; o <<= 1) {
            rs0 += __shfl_xor_sync(0xffffffffu, rs0, o);
            rs1 += __shfl_xor_sync(0xffffffffu, rs1, o);
        }
        l0 = l0 * cr0 + rs0; l1 = l1 * cr1 + rs1;
        m0r = nm0; m1r = nm1;
        #pragma unroll
        for (int ni = 0; ni < 8; ni++) {
            oc[ni][0] *= cr0; oc[ni][1] *= cr0;
            oc[ni][2] *= cr1; oc[ni][3] *= cr1;
        }

        #pragma unroll
        for (int kk = 0; kk < 4; kk++) {
            uint32_t a[4];
            a[0] = packh2(sc[2 * kk][0],     sc[2 * kk][1]);
            a[1] = packh2(sc[2 * kk][2],     sc[2 * kk][3]);
            a[2] = packh2(sc[2 * kk + 1][0], sc[2 * kk + 1][1]);
            a[3] = packh2(sc[2 * kk + 1][2], sc[2 * kk + 1][3]);
            #pragma unroll
            for (int pr = 0; pr < 4; pr++) {
                uint32_t v4[4];
                ldsm4t(v4, sV[st] + ((kk * 16 + vkrow) * FQH + pr * 16 + vdoff) * 2);
                uint32_t b0[2] = { v4[0], v4[1] };
                uint32_t b1[2] = { v4[2], v4[3] };
                mma16(oc[pr * 2 + 0], a, b0);
                mma16(oc[pr * 2 + 1], a, b1);
            }
        }
        __syncthreads();
    }

    if (role == 0) {
        float i0 = 1.f / l0, i1 = 1.f / l1;
        __half* o0 = out + (size_t)(b * TQ + q0 + r0) * DQ + h * HD;
        __half* o1 = out + (size_t)(b * TQ + q0 + r0 + 8) * DQ + h * HD;
        #pragma unroll
        for (int ni = 0; ni < 8; ni++) {
            *(__half2*)(o0 + ni * 8 + 2 * tq) = __floats2half2_rn(oc[ni][0] * i0, oc[ni][1] * i0);
            *(__half2*)(o1 + ni * 8 + 2 * tq) = __floats2half2_rn(oc[ni][2] * i1, oc[ni][3] * i1);
        }
    } else if (role == 1) {
        const int sidx = (b * HQ + h) * NSPL + (qi - 8);
        float* Od = pO + (size_t)sidx * 4096;
        #pragma unroll
        for (int ni = 0; ni < 8; ni++) {
            int c = ni * 8 + 2 * tq;
            *(float2*)(Od + r0 * 64 + c)       = make_float2(oc[ni][0], oc[ni][1]);
            *(float2*)(Od + (r0 + 8) * 64 + c) = make_float2(oc[ni][2], oc[ni][3]);
        }
        if (tq == 0) {
            pml[(size_t)sidx * 64 + r0]     = make_float2(m0r, l0);
            pml[(size_t)sidx * 64 + r0 + 8] = make_float2(m1r, l1);
        }
        __threadfence();
        __syncthreads();
        if (tid == 0) atomicExch(&flags[sidx], gen);
    } else {
        const int sidx = (b * HQ + h) * NSPL + (qi - 8);
        if (tid == 0) {
            int v;
            do {
                asm volatile("ld.global.acquire.gpu.b32 %0, [%1];"
                             : "=r"(v) : "l"(flags + sidx) : "memory");
            } while (v != gen);
        }
        __syncthreads();
        float2 ml0 = __ldcg((const float2*)pml + (size_t)sidx * 64 + r0);
        float2 ml1 = __ldcg((const float2*)pml + (size_t)sidx * 64 + r0 + 8);
        float M0 = fmaxf(ml0.x, m0r), M1 = fmaxf(ml1.x, m1r);
        float w10 = __expf(ml0.x - M0), w20 = __expf(m0r - M0);
        float w11 = __expf(ml1.x - M1), w21 = __expf(m1r - M1);
        float i0 = 1.f / (ml0.y * w10 + l0 * w20);
        float i1 = 1.f / (ml1.y * w11 + l1 * w21);
        const float* Od = pO + (size_t)sidx * 4096;
        __half* o0 = out + (size_t)(b * TQ + q0 + r0) * DQ + h * HD;
        __half* o1 = out + (size_t)(b * TQ + q0 + r0 + 8) * DQ + h * HD;
        #pragma unroll
        for (int ni = 0; ni < 8; ni++) {
            int c = ni * 8 + 2 * tq;
            float2 a0 = __ldcg((const float2*)(Od + r0 * 64 + c));
            float2 a1 = __ldcg((const float2*)(Od + (r0 + 8) * 64 + c));
            *(__half2*)(o0 + c) = __floats2half2_rn((a0.x * w10 + oc[ni][0] * w20) * i0,
                                                    (a0.y * w10 + oc[ni][1] * w20) * i0);
            *(__half2*)(o1 + c) = __floats2half2_rn((a1.x * w11 + oc[ni][2] * w21) * i1,
                                                    (a1.y * w11 + oc[ni][3] * w21) * i1);
        }
    }
}

// ---------------- NLL reduce + loss ----------------
__global__ void nll_reduce(const float* __restrict__ pm, const float* __restrict__ ps,
                           const float* __restrict__ logits, const int* __restrict__ tgt,
                           float* __restrict__ nll) {
    int row = blockIdx.x, t = threadIdx.x;
    float M = -1e30f, S = 0.f;
    for (int j = t; j < NT_LM; j += 128)
        lse_merge(M, S, pm[(size_t)row * NT_LM + j], ps[(size_t)row * NT_LM + j]);
    __shared__ float sm_[128], ss_[128];
    sm_[t] = M; ss_[t] = S; __syncthreads();
    for (int o = 64; o > 0; o >>= 1) {
        if (t < o) {
            float mm = sm_[t], ssv = ss_[t];
            lse_merge(mm, ssv, sm_[t + o], ss_[t + o]);
            sm_[t] = mm; ss_[t] = ssv;
        }
        __syncthreads();
    }
    if (t == 0) {
        float lse = sm_[0] + logf(ss_[0]);
        nll[row] = lse - logits[(size_t)row * VQ + tgt[row]];
    }
}
__global__ void loss_kernel(const float* __restrict__ nll, float* __restrict__ loss) {
    __shared__ float s[1024];
    float v = nll[threadIdx.x] + nll[threadIdx.x + 1024];
    s[threadIdx.x] = v; __syncthreads();
    for (int o = 512; o > 0; o >>= 1) {
        if (threadIdx.x < o) s[threadIdx.x] += s[threadIdx.x + o];
        __syncthreads();
    }
    if (threadIdx.x == 0) *loss = s[0] * (1.f / 2048.f);
}

// ---------------- launch ----------------
extern "C" void kernel_launch(void* const* d_in, const int* in_sizes, int n_in,
                              void* d_out, int out_size) {
    const int*   ids  = (const int*)d_in[0];
    const int*   tgt  = (const int*)d_in[1];
    const float* tok  = (const float*)d_in[2];
    const float* pos  = (const float*)d_in[3];
    const float* ln1w = (const float*)d_in[4];
    const float* ln1b = (const float*)d_in[5];
    const float* qkvw = (const float*)d_in[6];
    const float* qkvb = (const float*)d_in[7];
    const float* apw  = (const float*)d_in[8];
    const float* apb  = (const float*)d_in[9];
    const float* ln2w = (const float*)d_in[10];
    const float* ln2b = (const float*)d_in[11];
    const float* fcw  = (const float*)d_in[12];
    const float* fcb  = (const float*)d_in[13];
    const float* pw   = (const float*)d_in[14];
    const float* pb   = (const float*)d_in[15];
    const float* lnfw = (const float*)d_in[16];
    const float* lnfb = (const float*)d_in[17];

    float *x, *nll, *lfb, *pm, *ps, *pO;
    float2* pml;
    int* flags;
    __half *h, *qkv, *attn, *ffn;
    __half *wqkv, *wap, *wfc, *wpr, *tokt;
    cudaGetSymbolAddress((void**)&x,    g_x);
    cudaGetSymbolAddress((void**)&h,    g_h);
    cudaGetSymbolAddress((void**)&qkv,  g_qkv);
    cudaGetSymbolAddress((void**)&attn, g_attn);
    cudaGetSymbolAddress((void**)&ffn,  g_ffn);
    cudaGetSymbolAddress((void**)&nll,  g_nll);
    cudaGetSymbolAddress((void**)&lfb,  g_logits_fb);
    cudaGetSymbolAddress((void**)&pm,   g_pm);
    cudaGetSymbolAddress((void**)&ps,   g_ps);
    cudaGetSymbolAddress((void**)&pO,   g_pO);
    cudaGetSymbolAddress((void**)&pml,  g_pml);
    cudaGetSymbolAddress((void**)&flags, g_flag);
    cudaGetSymbolAddress((void**)&wqkv, g_wqkv);
    cudaGetSymbolAddress((void**)&wap,  g_wap);
    cudaGetSymbolAddress((void**)&wfc,  g_wfc);
    cudaGetSymbolAddress((void**)&wpr,  g_wpr);
    cudaGetSymbolAddress((void**)&tokt, g_tokt);

    cudaFuncSetAttribute(flash_h,      cudaFuncAttributeMaxDynamicSharedMemorySize, SMEM_FL);
    cudaFuncSetAttribute(gemm_h,       cudaFuncAttributeMaxDynamicSharedMemorySize, SMEM_GEMM);
    cudaFuncSetAttribute(gemm_h64<1>,  cudaFuncAttributeMaxDynamicSharedMemorySize, SMEM_G64);
    cudaFuncSetAttribute(gemm_h64<2>,  cudaFuncAttributeMaxDynamicSharedMemorySize, SMEM_G64);
    cudaFuncSetAttribute(gemm_lm,      cudaFuncAttributeMaxDynamicSharedMemorySize, SMEM_LM);

    const long long LOGN = (long long)BT * VQ;
    float* out    = (float*)d_out;
    float* logits;
    float* lossp  = nullptr;
    if ((long long)out_size > LOGN) {
        lossp  = out;
        logits = out + ((long long)out_size - LOGN);
    } else if ((long long)out_size == LOGN) {
        logits = out;
    } else {
        lossp  = out;
        logits = lfb;
    }

    cvt_all<<<(CVT_TOT + 255) / 256, 256>>>(
        (const float4*)qkvw, (const float4*)apw, (const float4*)fcw,
        (const float4*)pw,   (const float4*)tok,
        (uint4*)wqkv, (uint4*)wap, (uint4*)wfc, (uint4*)wpr, (uint4*)tokt);

    for (int l = 0; l < LQ; l++) {
        if (l == 0)
            embedln_kernel<<<BT/8, 256>>>(ids, tok, pos, ln1w, ln1b, x, h);
        else
            ln_kernel<<<BT/8, 256>>>(x, ln1w + l * DQ, ln1b + l * DQ, h);
        gemm_h<<<dim3((3 * DQ) / 128, BT / 128), 256, SMEM_GEMM>>>(
            h, wqkv + (size_t)l * DQ * 3 * DQ, qkvb + l * 3 * DQ, qkv, BT, 3 * DQ, DQ);
        flash_h<<<dim3(TQ / 64 + NSPL, HQ, BQ), 128, SMEM_FL>>>(qkv, attn, pO, pml, flags, l + 1);
        gemm_h64<1><<<dim3(DQ / 64, BT / 64), 128, SMEM_G64>>>(
            attn, wap + (size_t)l * DQ * DQ, apb + l * DQ, x, x, BT, DQ, DQ);
        ln_kernel<<<BT/8, 256>>>(x, ln2w + l * DQ, ln2b + l * DQ, h);
        gemm_h64<2><<<dim3((4 * DQ) / 64, BT / 64), 128, SMEM_G64>>>(
            h, wfc + (size_t)l * DQ * 4 * DQ, fcb + l * 4 * DQ, nullptr, ffn, BT, 4 * DQ, DQ);
        gemm_h64<1><<<dim3(DQ / 64, BT / 64), 128, SMEM_G64>>>(
            ffn, wpr + (size_t)l * 4 * DQ * DQ, pb + l * DQ, x, x, BT, DQ, 4 * DQ);
    }

    ln_kernel<<<BT/8, 256>>>(x, lnfw, lnfb, h);
    gemm_lm<<<dim3(BT / 128, NT_LM), 256, SMEM_LM>>>(
        h, tokt, logits, pm, ps, BT, VQ, DQ);

    if (lossp) {
        nll_reduce<<<BT, 128>>>(pm, ps, logits, tgt, nll);
        loss_kernel<<<1, 1024>>>(nll, lossp);
    }
}